// round 4
// baseline (speedup 1.0000x reference)
#include <cuda_runtime.h>

#define BB 8
#define CC 256
#define NPOS 4096   // 64*64
#define MPOS 1024   // 32*32
#define CF 32       // C/8
#define CHD 128     // C/2

// ---- scratch (static device globals; no allocation) ----
__device__ float g_f[(size_t)BB * CF * NPOS];       // f = Wf@x
__device__ float g_gp[(size_t)BB * CF * MPOS];      // pooled g
__device__ float g_hp[(size_t)BB * CHD * MPOS];     // pooled h
__device__ float g_o[(size_t)BB * CHD * NPOS];      // attention output
__device__ float g_wta[256 * 192];                  // [k][oc] cat(Wf,Wg,Wh)^T
__device__ float g_wtd[128 * 256];                  // [k][oc] Wo^T

// ---- cp.async helpers ----
__device__ __forceinline__ void cpa16(float* s, const float* g) {
    unsigned sa = (unsigned)__cvta_generic_to_shared(s);
    asm volatile("cp.async.ca.shared.global [%0], [%1], 16;\n" :: "r"(sa), "l"(g));
}
__device__ __forceinline__ void cpcommit() { asm volatile("cp.async.commit_group;\n" ::); }
__device__ __forceinline__ void cpwait0()  { asm volatile("cp.async.wait_group 0;\n" ::); }

// ============================================================
// Kernel T: transpose weights to [k][oc] layouts
// ============================================================
__global__ __launch_bounds__(256) void kT(const float* __restrict__ Wf,
                                          const float* __restrict__ Wg,
                                          const float* __restrict__ Wh,
                                          const float* __restrict__ Wo) {
    int idx = blockIdx.x * 256 + threadIdx.x;
    if (idx < 192 * 256) {
        int oc = idx >> 8, k = idx & 255;
        const float* src = (oc < 32) ? Wf + (size_t)oc * 256
                         : (oc < 64) ? Wg + (size_t)(oc - 32) * 256
                                     : Wh + (size_t)(oc - 64) * 256;
        g_wta[(size_t)k * 192 + oc] = src[k];
    }
    int idx2 = idx - 192 * 256;
    if (idx2 >= 0 && idx2 < 256 * 128) {
        int oc = idx2 >> 7, k = idx2 & 127;
        g_wtd[(size_t)k * 256 + oc] = Wo[(size_t)oc * 128 + k];
    }
}

// ============================================================
// Kernel A: [f;g;h] = Wcat @ x, pooled epilogue for g,h rows.
// grid (32 n-tiles of 128, 3 oc-tiles of 64, 8 b), 256 threads
// ============================================================
__global__ __launch_bounds__(256, 3) void kA(const float* __restrict__ x) {
    __shared__ __align__(16) float Ws[2][32 * 64];
    __shared__ __align__(16) float xs[2][32 * 128];
    const int b = blockIdx.z, ocb = blockIdx.y;
    const int n0 = blockIdx.x * 128;
    const int tid = threadIdx.x;
    const int tx = tid & 15, ty = tid >> 4;
    const float* xb = x + (size_t)b * CC * NPOS;

    float acc[4][8];
#pragma unroll
    for (int i = 0; i < 4; i++)
#pragma unroll
        for (int j = 0; j < 8; j++) acc[i][j] = 0.f;

    {
#pragma unroll
        for (int p = 0; p < 2; p++) {
            int idx = tid + p * 256; int kk = idx >> 4, c = idx & 15;
            cpa16(&Ws[0][kk * 64 + c * 4], &g_wta[(size_t)kk * 192 + ocb * 64 + c * 4]);
        }
#pragma unroll
        for (int p = 0; p < 4; p++) {
            int idx = tid + p * 256; int kk = idx >> 5, c = idx & 31;
            cpa16(&xs[0][kk * 128 + c * 4], &xb[(size_t)kk * NPOS + n0 + c * 4]);
        }
        cpcommit();
    }
    cpwait0(); __syncthreads();

    for (int it = 0; it < 8; it++) {
        const int cur = it & 1;
        if (it + 1 < 8) {
            const int nxt = cur ^ 1, k0 = (it + 1) * 32;
#pragma unroll
            for (int p = 0; p < 2; p++) {
                int idx = tid + p * 256; int kk = idx >> 4, c = idx & 15;
                cpa16(&Ws[nxt][kk * 64 + c * 4], &g_wta[(size_t)(k0 + kk) * 192 + ocb * 64 + c * 4]);
            }
#pragma unroll
            for (int p = 0; p < 4; p++) {
                int idx = tid + p * 256; int kk = idx >> 5, c = idx & 31;
                cpa16(&xs[nxt][kk * 128 + c * 4], &xb[(size_t)(k0 + kk) * NPOS + n0 + c * 4]);
            }
        }
        cpcommit();
#pragma unroll
        for (int kk = 0; kk < 32; kk++) {
            float4 a4 = *(const float4*)&Ws[cur][kk * 64 + ty * 4];
            float4 b0 = *(const float4*)&xs[cur][kk * 128 + tx * 4];
            float4 b1 = *(const float4*)&xs[cur][kk * 128 + 64 + tx * 4];
            float a[4] = {a4.x, a4.y, a4.z, a4.w};
            float bv[8] = {b0.x, b0.y, b0.z, b0.w, b1.x, b1.y, b1.z, b1.w};
#pragma unroll
            for (int i = 0; i < 4; i++)
#pragma unroll
                for (int j = 0; j < 8; j++) acc[i][j] = fmaf(a[i], bv[j], acc[i][j]);
        }
        cpwait0(); __syncthreads();
    }

    const int pm = blockIdx.x * 32 + tx * 2;
#pragma unroll
    for (int i = 0; i < 4; i++) {
        int oc = ocb * 64 + ty * 4 + i;
        if (oc < 32) {
            float* fb = g_f + (size_t)b * CF * NPOS + (size_t)oc * NPOS + n0;
            *(float4*)&fb[tx * 4]      = make_float4(acc[i][0], acc[i][1], acc[i][2], acc[i][3]);
            *(float4*)&fb[64 + tx * 4] = make_float4(acc[i][4], acc[i][5], acc[i][6], acc[i][7]);
        } else {
            float v0 = fmaxf(fmaxf(acc[i][0], acc[i][1]), fmaxf(acc[i][4], acc[i][5]));
            float v1 = fmaxf(fmaxf(acc[i][2], acc[i][3]), fmaxf(acc[i][6], acc[i][7]));
            float* dst = (oc < 64) ? g_gp + ((size_t)b * CF + (oc - 32)) * MPOS
                                   : g_hp + ((size_t)b * CHD + (oc - 64)) * MPOS;
            *(float2*)&dst[pm] = make_float2(v0, v1);
        }
    }
}

// ============================================================
// Kernel C: streaming attention, 64-query tiles.
// grid (64 q-tiles, 8 b), 256 threads, Mt=64, 16 m-tiles.
// smem: fs[32][68], gs[32][68] (single buf), hs[2][128][68],
//       ps[64][68], rsum[64]  = 104.7 KB -> 2 blocks/SM
// ============================================================
#define GST 68
#define KC_FS 0
#define KC_GS (32 * GST)
#define KC_HS (KC_GS + 32 * GST)
#define KC_PS (KC_HS + 2 * 128 * GST)
#define KC_RS (KC_PS + 64 * GST)
#define SMEM_C_FLOATS (KC_RS + 64)
#define SMEM_C_BYTES (SMEM_C_FLOATS * 4)

extern __shared__ float smc[];

__global__ __launch_bounds__(256, 2) void kC() {
    float* fs   = smc + KC_FS;    // 32 x 68
    float* gs   = smc + KC_GS;    // 32 x 68
    float* hs   = smc + KC_HS;    // 2 x 128 x 68
    float* ps   = smc + KC_PS;    // 64 x 68
    float* rsum = smc + KC_RS;    // 64

    const int b = blockIdx.y;
    const int n0 = blockIdx.x * 64;
    const int tid = threadIdx.x;
    const int hi = tid >> 4;      // 0..15  (score: tn  | o: cg)
    const int lo = tid & 15;      // 0..15  (score: tm  | o: ng)
    const float* gp = g_gp + (size_t)b * CF * MPOS;
    const float* hp = g_hp + (size_t)b * CHD * MPOS;
    const float* fp = g_f + (size_t)b * CF * NPOS + n0;

    // issue tile 0 + f-tile loads
#pragma unroll
    for (int p = 0; p < 2; p++) {
        int idx = tid + p * 256; int r = idx >> 4, c = idx & 15;
        cpa16(&fs[r * GST + c * 4], &fp[(size_t)r * NPOS + c * 4]);
        cpa16(&gs[r * GST + c * 4], &gp[(size_t)r * MPOS + c * 4]);
    }
#pragma unroll
    for (int p = 0; p < 8; p++) {
        int idx = tid + p * 256; int r = idx >> 4, c = idx & 15;
        cpa16(&hs[r * GST + c * 4], &hp[(size_t)r * MPOS + c * 4]);
    }
    cpcommit();
    cpwait0(); __syncthreads();

    float rs[4] = {0.f, 0.f, 0.f, 0.f};
    float acc[8][4];
#pragma unroll
    for (int i = 0; i < 8; i++)
#pragma unroll
        for (int j = 0; j < 4; j++) acc[i][j] = 0.f;

    for (int t16 = 0; t16 < 16; t16++) {
        const int cur = t16 & 1;
        const float* hsc = hs + cur * 128 * GST;

        // ---- score: 4n x 4m per thread, n = hi*4.., m = lo*4.. ----
        float4 s0 = make_float4(0.f, 0.f, 0.f, 0.f);
        float4 s1 = make_float4(0.f, 0.f, 0.f, 0.f);
        float4 s2 = make_float4(0.f, 0.f, 0.f, 0.f);
        float4 s3 = make_float4(0.f, 0.f, 0.f, 0.f);
#pragma unroll
        for (int k = 0; k < 32; k++) {
            float4 fv = *(const float4*)&fs[k * GST + hi * 4];
            float4 gv = *(const float4*)&gs[k * GST + lo * 4];
            s0.x = fmaf(fv.x, gv.x, s0.x); s0.y = fmaf(fv.x, gv.y, s0.y);
            s0.z = fmaf(fv.x, gv.z, s0.z); s0.w = fmaf(fv.x, gv.w, s0.w);
            s1.x = fmaf(fv.y, gv.x, s1.x); s1.y = fmaf(fv.y, gv.y, s1.y);
            s1.z = fmaf(fv.y, gv.z, s1.z); s1.w = fmaf(fv.y, gv.w, s1.w);
            s2.x = fmaf(fv.z, gv.x, s2.x); s2.y = fmaf(fv.z, gv.y, s2.y);
            s2.z = fmaf(fv.z, gv.z, s2.z); s2.w = fmaf(fv.z, gv.w, s2.w);
            s3.x = fmaf(fv.w, gv.x, s3.x); s3.y = fmaf(fv.w, gv.y, s3.y);
            s3.z = fmaf(fv.w, gv.z, s3.z); s3.w = fmaf(fv.w, gv.w, s3.w);
        }
        float4 e0 = make_float4(__expf(s0.x), __expf(s0.y), __expf(s0.z), __expf(s0.w));
        float4 e1 = make_float4(__expf(s1.x), __expf(s1.y), __expf(s1.z), __expf(s1.w));
        float4 e2 = make_float4(__expf(s2.x), __expf(s2.y), __expf(s2.z), __expf(s2.w));
        float4 e3 = make_float4(__expf(s3.x), __expf(s3.y), __expf(s3.z), __expf(s3.w));
        *(float4*)&ps[(hi * 4 + 0) * GST + lo * 4] = e0;
        *(float4*)&ps[(hi * 4 + 1) * GST + lo * 4] = e1;
        *(float4*)&ps[(hi * 4 + 2) * GST + lo * 4] = e2;
        *(float4*)&ps[(hi * 4 + 3) * GST + lo * 4] = e3;
        rs[0] += (e0.x + e0.y) + (e0.z + e0.w);
        rs[1] += (e1.x + e1.y) + (e1.z + e1.w);
        rs[2] += (e2.x + e2.y) + (e2.z + e2.w);
        rs[3] += (e3.x + e3.y) + (e3.z + e3.w);
        __syncthreads();   // ps visible; gs free

        // prefetch tile t16+1 (gs into same buffer, hs into alternate)
        if (t16 + 1 < 16) {
            const int m1 = (t16 + 1) * 64;
            float* hsd = hs + (cur ^ 1) * 128 * GST;
#pragma unroll
            for (int p = 0; p < 2; p++) {
                int idx = tid + p * 256; int r = idx >> 4, c = idx & 15;
                cpa16(&gs[r * GST + c * 4], &gp[(size_t)r * MPOS + m1 + c * 4]);
            }
#pragma unroll
            for (int p = 0; p < 8; p++) {
                int idx = tid + p * 256; int r = idx >> 4, c = idx & 15;
                cpa16(&hsd[r * GST + c * 4], &hp[(size_t)r * MPOS + m1 + c * 4]);
            }
        }
        cpcommit();

        // ---- o accumulate: ch = hi*8+i, n = lo*4+j, full m ----
#pragma unroll
        for (int m = 0; m < 64; m += 4) {
            float4 sv[4];
#pragma unroll
            for (int j = 0; j < 4; j++)
                sv[j] = *(const float4*)&ps[(lo * 4 + j) * GST + m];
#pragma unroll
            for (int i = 0; i < 8; i++) {
                float4 hv = *(const float4*)&hsc[(hi * 8 + i) * GST + m];
#pragma unroll
                for (int j = 0; j < 4; j++) {
                    float r = acc[i][j];
                    r = fmaf(hv.x, sv[j].x, r);
                    r = fmaf(hv.y, sv[j].y, r);
                    r = fmaf(hv.z, sv[j].z, r);
                    r = fmaf(hv.w, sv[j].w, r);
                    acc[i][j] = r;
                }
            }
        }
        cpwait0();
        __syncthreads();   // next tiles ready; ps free
    }

    // ---- rowsums: reduce over the 16 tm lanes (shfl within 16-lane group) ----
#pragma unroll
    for (int off = 1; off < 16; off <<= 1) {
#pragma unroll
        for (int r = 0; r < 4; r++) rs[r] += __shfl_xor_sync(0xffffffffu, rs[r], off);
    }
    if (lo == 0) {
#pragma unroll
        for (int r = 0; r < 4; r++) rsum[hi * 4 + r] = rs[r];
    }
    __syncthreads();

    // ---- normalize + store ----
    {
        float inv[4];
#pragma unroll
        for (int j = 0; j < 4; j++) inv[j] = 1.f / rsum[lo * 4 + j];
        float* ob = g_o + (size_t)b * CHD * NPOS + n0 + lo * 4;
#pragma unroll
        for (int i = 0; i < 8; i++) {
            float4 v = make_float4(acc[i][0] * inv[0], acc[i][1] * inv[1],
                                   acc[i][2] * inv[2], acc[i][3] * inv[3]);
            *(float4*)&ob[(size_t)(hi * 8 + i) * NPOS] = v;
        }
    }
}

// ============================================================
// Kernel D: out = gamma * (Wo @ o) + x, double-buffered cp.async
// ============================================================
__global__ __launch_bounds__(256, 3) void kD(const float* __restrict__ x,
                                             const float* __restrict__ gptr,
                                             float* __restrict__ out) {
    __shared__ __align__(16) float Ws[2][32 * 64];
    __shared__ __align__(16) float os[2][32 * 128];
    const int b = blockIdx.z, ocb = blockIdx.y;
    const int n0 = blockIdx.x * 128;
    const int tid = threadIdx.x;
    const int tx = tid & 15, ty = tid >> 4;
    const float gamma = *gptr;
    const float* ob = g_o + (size_t)b * CHD * NPOS;

    float acc[4][8];
#pragma unroll
    for (int i = 0; i < 4; i++)
#pragma unroll
        for (int j = 0; j < 8; j++) acc[i][j] = 0.f;

    {
#pragma unroll
        for (int p = 0; p < 2; p++) {
            int idx = tid + p * 256; int kk = idx >> 4, c = idx & 15;
            cpa16(&Ws[0][kk * 64 + c * 4], &g_wtd[(size_t)kk * 256 + ocb * 64 + c * 4]);
        }
#pragma unroll
        for (int p = 0; p < 4; p++) {
            int idx = tid + p * 256; int kk = idx >> 5, c = idx & 31;
            cpa16(&os[0][kk * 128 + c * 4], &ob[(size_t)kk * NPOS + n0 + c * 4]);
        }
        cpcommit();
    }
    cpwait0(); __syncthreads();

    for (int it = 0; it < 4; it++) {
        const int cur = it & 1;
        if (it + 1 < 4) {
            const int nxt = cur ^ 1, k0 = (it + 1) * 32;
#pragma unroll
            for (int p = 0; p < 2; p++) {
                int idx = tid + p * 256; int kk = idx >> 4, c = idx & 15;
                cpa16(&Ws[nxt][kk * 64 + c * 4], &g_wtd[(size_t)(k0 + kk) * 256 + ocb * 64 + c * 4]);
            }
#pragma unroll
            for (int p = 0; p < 4; p++) {
                int idx = tid + p * 256; int kk = idx >> 5, c = idx & 31;
                cpa16(&os[nxt][kk * 128 + c * 4], &ob[(size_t)(k0 + kk) * NPOS + n0 + c * 4]);
            }
        }
        cpcommit();
#pragma unroll
        for (int kk = 0; kk < 32; kk++) {
            float4 a4 = *(const float4*)&Ws[cur][kk * 64 + ty * 4];
            float4 b0 = *(const float4*)&os[cur][kk * 128 + tx * 4];
            float4 b1 = *(const float4*)&os[cur][kk * 128 + 64 + tx * 4];
            float a[4] = {a4.x, a4.y, a4.z, a4.w};
            float bv[8] = {b0.x, b0.y, b0.z, b0.w, b1.x, b1.y, b1.z, b1.w};
#pragma unroll
            for (int i = 0; i < 4; i++)
#pragma unroll
                for (int j = 0; j < 8; j++) acc[i][j] = fmaf(a[i], bv[j], acc[i][j]);
        }
        cpwait0(); __syncthreads();
    }

    const float* xb = x + (size_t)b * CC * NPOS;
    float* outb = out + (size_t)b * CC * NPOS;
#pragma unroll
    for (int i = 0; i < 4; i++) {
        int oc = ocb * 64 + ty * 4 + i;
        size_t o0 = (size_t)oc * NPOS + n0 + tx * 4;
        size_t o1 = o0 + 64;
        float4 x0 = *(const float4*)&xb[o0];
        float4 x1 = *(const float4*)&xb[o1];
        *(float4*)&outb[o0] = make_float4(fmaf(gamma, acc[i][0], x0.x), fmaf(gamma, acc[i][1], x0.y),
                                          fmaf(gamma, acc[i][2], x0.z), fmaf(gamma, acc[i][3], x0.w));
        *(float4*)&outb[o1] = make_float4(fmaf(gamma, acc[i][4], x1.x), fmaf(gamma, acc[i][5], x1.y),
                                          fmaf(gamma, acc[i][6], x1.z), fmaf(gamma, acc[i][7], x1.w));
    }
}

// ============================================================
extern "C" void kernel_launch(void* const* d_in, const int* in_sizes, int n_in,
                              void* d_out, int out_size) {
    const float* x     = (const float*)d_in[0];
    const float* Wf    = (const float*)d_in[1];
    const float* Wg    = (const float*)d_in[2];
    const float* Wh    = (const float*)d_in[3];
    const float* Wo    = (const float*)d_in[4];
    const float* gamma = (const float*)d_in[5];
    float* out = (float*)d_out;

    cudaFuncSetAttribute(kC, cudaFuncAttributeMaxDynamicSharedMemorySize, SMEM_C_BYTES);

    kT<<<320, 256>>>(Wf, Wg, Wh, Wo);
    kA<<<dim3(32, 3, 8), 256>>>(x);
    kC<<<dim3(64, 8), 256, SMEM_C_BYTES>>>();
    kD<<<dim3(32, 4, 8), 256>>>(x, gamma, out);
}

// round 5
// speedup vs baseline: 1.3157x; 1.3157x over previous
#include <cuda_runtime.h>

#define BB 8
#define CC 256
#define NPOS 4096   // 64*64
#define MPOS 1024   // 32*32
#define CF 32       // C/8
#define CHD 128     // C/2

// ---- scratch (static device globals; no allocation) ----
__device__ float g_f[(size_t)BB * CF * NPOS];       // f = Wf@x
__device__ float g_gp[(size_t)BB * CF * MPOS];      // pooled g
__device__ float g_hp[(size_t)BB * CHD * MPOS];     // pooled h
__device__ float g_o[(size_t)BB * CHD * NPOS];      // attention output
__device__ float g_wta[256 * 192];                  // [k][oc] cat(Wf,Wg,Wh)^T
__device__ float g_wtd[128 * 256];                  // [k][oc] Wo^T

// ---- cp.async helpers ----
__device__ __forceinline__ void cpa16(float* s, const float* g) {
    unsigned sa = (unsigned)__cvta_generic_to_shared(s);
    asm volatile("cp.async.ca.shared.global [%0], [%1], 16;\n" :: "r"(sa), "l"(g));
}
__device__ __forceinline__ void cpcommit() { asm volatile("cp.async.commit_group;\n" ::); }
__device__ __forceinline__ void cpwait0()  { asm volatile("cp.async.wait_group 0;\n" ::); }

// ============================================================
// Kernel T: transpose weights to [k][oc] layouts
// ============================================================
__global__ __launch_bounds__(256) void kT(const float* __restrict__ Wf,
                                          const float* __restrict__ Wg,
                                          const float* __restrict__ Wh,
                                          const float* __restrict__ Wo) {
    int idx = blockIdx.x * 256 + threadIdx.x;
    if (idx < 192 * 256) {
        int oc = idx >> 8, k = idx & 255;
        const float* src = (oc < 32) ? Wf + (size_t)oc * 256
                         : (oc < 64) ? Wg + (size_t)(oc - 32) * 256
                                     : Wh + (size_t)(oc - 64) * 256;
        g_wta[(size_t)k * 192 + oc] = src[k];
    }
    int idx2 = idx - 192 * 256;
    if (idx2 >= 0 && idx2 < 256 * 128) {
        int oc = idx2 >> 7, k = idx2 & 127;
        g_wtd[(size_t)k * 256 + oc] = Wo[(size_t)oc * 128 + k];
    }
}

// ============================================================
// Kernel A: [f;g;h] = Wcat @ x, pooled epilogue for g,h rows.
// grid (32 n-tiles of 128, 3 oc-tiles of 64, 8 b), 256 threads
// ============================================================
__global__ __launch_bounds__(256, 3) void kA(const float* __restrict__ x) {
    __shared__ __align__(16) float Ws[2][32 * 64];
    __shared__ __align__(16) float xs[2][32 * 128];
    const int b = blockIdx.z, ocb = blockIdx.y;
    const int n0 = blockIdx.x * 128;
    const int tid = threadIdx.x;
    const int tx = tid & 15, ty = tid >> 4;
    const float* xb = x + (size_t)b * CC * NPOS;

    float acc[4][8];
#pragma unroll
    for (int i = 0; i < 4; i++)
#pragma unroll
        for (int j = 0; j < 8; j++) acc[i][j] = 0.f;

    {
#pragma unroll
        for (int p = 0; p < 2; p++) {
            int idx = tid + p * 256; int kk = idx >> 4, c = idx & 15;
            cpa16(&Ws[0][kk * 64 + c * 4], &g_wta[(size_t)kk * 192 + ocb * 64 + c * 4]);
        }
#pragma unroll
        for (int p = 0; p < 4; p++) {
            int idx = tid + p * 256; int kk = idx >> 5, c = idx & 31;
            cpa16(&xs[0][kk * 128 + c * 4], &xb[(size_t)kk * NPOS + n0 + c * 4]);
        }
        cpcommit();
    }
    cpwait0(); __syncthreads();

    for (int it = 0; it < 8; it++) {
        const int cur = it & 1;
        if (it + 1 < 8) {
            const int nxt = cur ^ 1, k0 = (it + 1) * 32;
#pragma unroll
            for (int p = 0; p < 2; p++) {
                int idx = tid + p * 256; int kk = idx >> 4, c = idx & 15;
                cpa16(&Ws[nxt][kk * 64 + c * 4], &g_wta[(size_t)(k0 + kk) * 192 + ocb * 64 + c * 4]);
            }
#pragma unroll
            for (int p = 0; p < 4; p++) {
                int idx = tid + p * 256; int kk = idx >> 5, c = idx & 31;
                cpa16(&xs[nxt][kk * 128 + c * 4], &xb[(size_t)(k0 + kk) * NPOS + n0 + c * 4]);
            }
        }
        cpcommit();
#pragma unroll
        for (int kk = 0; kk < 32; kk++) {
            float4 a4 = *(const float4*)&Ws[cur][kk * 64 + ty * 4];
            float4 b0 = *(const float4*)&xs[cur][kk * 128 + tx * 4];
            float4 b1 = *(const float4*)&xs[cur][kk * 128 + 64 + tx * 4];
            float a[4] = {a4.x, a4.y, a4.z, a4.w};
            float bv[8] = {b0.x, b0.y, b0.z, b0.w, b1.x, b1.y, b1.z, b1.w};
#pragma unroll
            for (int i = 0; i < 4; i++)
#pragma unroll
                for (int j = 0; j < 8; j++) acc[i][j] = fmaf(a[i], bv[j], acc[i][j]);
        }
        cpwait0(); __syncthreads();
    }

    const int pm = blockIdx.x * 32 + tx * 2;
#pragma unroll
    for (int i = 0; i < 4; i++) {
        int oc = ocb * 64 + ty * 4 + i;
        if (oc < 32) {
            float* fb = g_f + (size_t)b * CF * NPOS + (size_t)oc * NPOS + n0;
            *(float4*)&fb[tx * 4]      = make_float4(acc[i][0], acc[i][1], acc[i][2], acc[i][3]);
            *(float4*)&fb[64 + tx * 4] = make_float4(acc[i][4], acc[i][5], acc[i][6], acc[i][7]);
        } else {
            float v0 = fmaxf(fmaxf(acc[i][0], acc[i][1]), fmaxf(acc[i][4], acc[i][5]));
            float v1 = fmaxf(fmaxf(acc[i][2], acc[i][3]), fmaxf(acc[i][6], acc[i][7]));
            float* dst = (oc < 64) ? g_gp + ((size_t)b * CF + (oc - 32)) * MPOS
                                   : g_hp + ((size_t)b * CHD + (oc - 64)) * MPOS;
            *(float2*)&dst[pm] = make_float2(v0, v1);
        }
    }
}

// ============================================================
// Kernel C: streaming attention, 64-query tiles, conflict-free maps.
// grid (64 q-tiles, 8 b), 256 threads, Mt=64, 16 m-tiles.
// score: thread (hi,lo) -> n = hi*4+r (r<4), m = lo*4..lo*4+3
// o    : thread (hi,lo) -> ch = hi*8+i,    n = j*16+lo (j<4)
// ============================================================
#define GST 68
#define KC_FS 0
#define KC_GS (32 * GST)
#define KC_HS (KC_GS + 32 * GST)
#define KC_PS (KC_HS + 2 * 128 * GST)
#define KC_RS (KC_PS + 64 * GST)
#define SMEM_C_FLOATS (KC_RS + 64)
#define SMEM_C_BYTES (SMEM_C_FLOATS * 4)

extern __shared__ float smc[];

__global__ __launch_bounds__(256, 2) void kC() {
    float* fs   = smc + KC_FS;    // 32 x 68
    float* gs   = smc + KC_GS;    // 32 x 68 (single buffer)
    float* hs   = smc + KC_HS;    // 2 x 128 x 68
    float* ps   = smc + KC_PS;    // 64 x 68
    float* rsum = smc + KC_RS;    // 64

    const int b = blockIdx.y;
    const int n0 = blockIdx.x * 64;
    const int tid = threadIdx.x;
    const int hi = tid >> 4;      // 0..15
    const int lo = tid & 15;      // 0..15
    const float* gp = g_gp + (size_t)b * CF * MPOS;
    const float* hp = g_hp + (size_t)b * CHD * MPOS;
    const float* fp = g_f + (size_t)b * CF * NPOS + n0;

    // issue tile 0 + f-tile loads
#pragma unroll
    for (int p = 0; p < 2; p++) {
        int idx = tid + p * 256; int r = idx >> 4, c = idx & 15;
        cpa16(&fs[r * GST + c * 4], &fp[(size_t)r * NPOS + c * 4]);
        cpa16(&gs[r * GST + c * 4], &gp[(size_t)r * MPOS + c * 4]);
    }
#pragma unroll
    for (int p = 0; p < 8; p++) {
        int idx = tid + p * 256; int r = idx >> 4, c = idx & 15;
        cpa16(&hs[r * GST + c * 4], &hp[(size_t)r * MPOS + c * 4]);
    }
    cpcommit();
    cpwait0(); __syncthreads();

    float rs[4] = {0.f, 0.f, 0.f, 0.f};
    float acc[8][4];
#pragma unroll
    for (int i = 0; i < 8; i++)
#pragma unroll
        for (int j = 0; j < 4; j++) acc[i][j] = 0.f;

    for (int t16 = 0; t16 < 16; t16++) {
        const int cur = t16 & 1;
        const float* hsc = hs + cur * 128 * GST;

        // prefetch hs for t16+1 into the freed alternate buffer (own group)
        if (t16 + 1 < 16) {
            const int m1 = (t16 + 1) * 64;
            float* hsd = hs + (cur ^ 1) * 128 * GST;
#pragma unroll
            for (int p = 0; p < 8; p++) {
                int idx = tid + p * 256; int r = idx >> 4, c = idx & 15;
                cpa16(&hsd[r * GST + c * 4], &hp[(size_t)r * MPOS + m1 + c * 4]);
            }
        }
        cpcommit();

        // ---- score: 4n x 4m per thread, n = hi*4+r, m = lo*4.. ----
        float4 s0 = make_float4(0.f, 0.f, 0.f, 0.f);
        float4 s1 = make_float4(0.f, 0.f, 0.f, 0.f);
        float4 s2 = make_float4(0.f, 0.f, 0.f, 0.f);
        float4 s3 = make_float4(0.f, 0.f, 0.f, 0.f);
#pragma unroll
        for (int k = 0; k < 32; k++) {
            float4 fv = *(const float4*)&fs[k * GST + hi * 4];
            float4 gv = *(const float4*)&gs[k * GST + lo * 4];
            s0.x = fmaf(fv.x, gv.x, s0.x); s0.y = fmaf(fv.x, gv.y, s0.y);
            s0.z = fmaf(fv.x, gv.z, s0.z); s0.w = fmaf(fv.x, gv.w, s0.w);
            s1.x = fmaf(fv.y, gv.x, s1.x); s1.y = fmaf(fv.y, gv.y, s1.y);
            s1.z = fmaf(fv.y, gv.z, s1.z); s1.w = fmaf(fv.y, gv.w, s1.w);
            s2.x = fmaf(fv.z, gv.x, s2.x); s2.y = fmaf(fv.z, gv.y, s2.y);
            s2.z = fmaf(fv.z, gv.z, s2.z); s2.w = fmaf(fv.z, gv.w, s2.w);
            s3.x = fmaf(fv.w, gv.x, s3.x); s3.y = fmaf(fv.w, gv.y, s3.y);
            s3.z = fmaf(fv.w, gv.z, s3.z); s3.w = fmaf(fv.w, gv.w, s3.w);
        }
        float4 e0 = make_float4(__expf(s0.x), __expf(s0.y), __expf(s0.z), __expf(s0.w));
        float4 e1 = make_float4(__expf(s1.x), __expf(s1.y), __expf(s1.z), __expf(s1.w));
        float4 e2 = make_float4(__expf(s2.x), __expf(s2.y), __expf(s2.z), __expf(s2.w));
        float4 e3 = make_float4(__expf(s3.x), __expf(s3.y), __expf(s3.z), __expf(s3.w));
        *(float4*)&ps[(hi * 4 + 0) * GST + lo * 4] = e0;
        *(float4*)&ps[(hi * 4 + 1) * GST + lo * 4] = e1;
        *(float4*)&ps[(hi * 4 + 2) * GST + lo * 4] = e2;
        *(float4*)&ps[(hi * 4 + 3) * GST + lo * 4] = e3;
        rs[0] += (e0.x + e0.y) + (e0.z + e0.w);
        rs[1] += (e1.x + e1.y) + (e1.z + e1.w);
        rs[2] += (e2.x + e2.y) + (e2.z + e2.w);
        rs[3] += (e3.x + e3.y) + (e3.z + e3.w);
        __syncthreads();   // ps visible; gs free

        // prefetch gs for t16+1 (single buffer, safe now)
        if (t16 + 1 < 16) {
            const int m1 = (t16 + 1) * 64;
#pragma unroll
            for (int p = 0; p < 2; p++) {
                int idx = tid + p * 256; int r = idx >> 4, c = idx & 15;
                cpa16(&gs[r * GST + c * 4], &gp[(size_t)r * MPOS + m1 + c * 4]);
            }
        }
        cpcommit();

        // ---- o accumulate: ch = hi*8+i, n = j*16+lo (conflict-free sv) ----
#pragma unroll
        for (int m = 0; m < 64; m += 4) {
            float4 sv[4];
#pragma unroll
            for (int j = 0; j < 4; j++)
                sv[j] = *(const float4*)&ps[(j * 16 + lo) * GST + m];
#pragma unroll
            for (int i = 0; i < 8; i++) {
                float4 hv = *(const float4*)&hsc[(hi * 8 + i) * GST + m];
#pragma unroll
                for (int j = 0; j < 4; j++) {
                    float r = acc[i][j];
                    r = fmaf(hv.x, sv[j].x, r);
                    r = fmaf(hv.y, sv[j].y, r);
                    r = fmaf(hv.z, sv[j].z, r);
                    r = fmaf(hv.w, sv[j].w, r);
                    acc[i][j] = r;
                }
            }
        }
        cpwait0();
        __syncthreads();   // next tiles resident; ps free
    }

    // ---- rowsums: reduce over the 16 m-lanes ----
#pragma unroll
    for (int off = 1; off < 16; off <<= 1) {
#pragma unroll
        for (int r = 0; r < 4; r++) rs[r] += __shfl_xor_sync(0xffffffffu, rs[r], off);
    }
    if (lo == 0) {
#pragma unroll
        for (int r = 0; r < 4; r++) rsum[hi * 4 + r] = rs[r];
    }
    __syncthreads();

    // ---- normalize + store: n = j*16+lo ----
    {
        float inv[4];
#pragma unroll
        for (int j = 0; j < 4; j++) inv[j] = 1.f / rsum[j * 16 + lo];
        float* ob = g_o + (size_t)b * CHD * NPOS + n0 + lo;
#pragma unroll
        for (int i = 0; i < 8; i++) {
            float* orow = ob + (size_t)(hi * 8 + i) * NPOS;
#pragma unroll
            for (int j = 0; j < 4; j++)
                orow[j * 16] = acc[i][j] * inv[j];
        }
    }
}

// ============================================================
// Kernel D: out = gamma * (Wo @ o) + x, double-buffered cp.async
// ============================================================
__global__ __launch_bounds__(256, 3) void kD(const float* __restrict__ x,
                                             const float* __restrict__ gptr,
                                             float* __restrict__ out) {
    __shared__ __align__(16) float Ws[2][32 * 64];
    __shared__ __align__(16) float os[2][32 * 128];
    const int b = blockIdx.z, ocb = blockIdx.y;
    const int n0 = blockIdx.x * 128;
    const int tid = threadIdx.x;
    const int tx = tid & 15, ty = tid >> 4;
    const float gamma = *gptr;
    const float* ob = g_o + (size_t)b * CHD * NPOS;

    float acc[4][8];
#pragma unroll
    for (int i = 0; i < 4; i++)
#pragma unroll
        for (int j = 0; j < 8; j++) acc[i][j] = 0.f;

    {
#pragma unroll
        for (int p = 0; p < 2; p++) {
            int idx = tid + p * 256; int kk = idx >> 4, c = idx & 15;
            cpa16(&Ws[0][kk * 64 + c * 4], &g_wtd[(size_t)kk * 256 + ocb * 64 + c * 4]);
        }
#pragma unroll
        for (int p = 0; p < 4; p++) {
            int idx = tid + p * 256; int kk = idx >> 5, c = idx & 31;
            cpa16(&os[0][kk * 128 + c * 4], &ob[(size_t)kk * NPOS + n0 + c * 4]);
        }
        cpcommit();
    }
    cpwait0(); __syncthreads();

    for (int it = 0; it < 4; it++) {
        const int cur = it & 1;
        if (it + 1 < 4) {
            const int nxt = cur ^ 1, k0 = (it + 1) * 32;
#pragma unroll
            for (int p = 0; p < 2; p++) {
                int idx = tid + p * 256; int kk = idx >> 4, c = idx & 15;
                cpa16(&Ws[nxt][kk * 64 + c * 4], &g_wtd[(size_t)(k0 + kk) * 256 + ocb * 64 + c * 4]);
            }
#pragma unroll
            for (int p = 0; p < 4; p++) {
                int idx = tid + p * 256; int kk = idx >> 5, c = idx & 31;
                cpa16(&os[nxt][kk * 128 + c * 4], &ob[(size_t)(k0 + kk) * NPOS + n0 + c * 4]);
            }
        }
        cpcommit();
#pragma unroll
        for (int kk = 0; kk < 32; kk++) {
            float4 a4 = *(const float4*)&Ws[cur][kk * 64 + ty * 4];
            float4 b0 = *(const float4*)&os[cur][kk * 128 + tx * 4];
            float4 b1 = *(const float4*)&os[cur][kk * 128 + 64 + tx * 4];
            float a[4] = {a4.x, a4.y, a4.z, a4.w};
            float bv[8] = {b0.x, b0.y, b0.z, b0.w, b1.x, b1.y, b1.z, b1.w};
#pragma unroll
            for (int i = 0; i < 4; i++)
#pragma unroll
                for (int j = 0; j < 8; j++) acc[i][j] = fmaf(a[i], bv[j], acc[i][j]);
        }
        cpwait0(); __syncthreads();
    }

    const float* xb = x + (size_t)b * CC * NPOS;
    float* outb = out + (size_t)b * CC * NPOS;
#pragma unroll
    for (int i = 0; i < 4; i++) {
        int oc = ocb * 64 + ty * 4 + i;
        size_t o0 = (size_t)oc * NPOS + n0 + tx * 4;
        size_t o1 = o0 + 64;
        float4 x0 = *(const float4*)&xb[o0];
        float4 x1 = *(const float4*)&xb[o1];
        *(float4*)&outb[o0] = make_float4(fmaf(gamma, acc[i][0], x0.x), fmaf(gamma, acc[i][1], x0.y),
                                          fmaf(gamma, acc[i][2], x0.z), fmaf(gamma, acc[i][3], x0.w));
        *(float4*)&outb[o1] = make_float4(fmaf(gamma, acc[i][4], x1.x), fmaf(gamma, acc[i][5], x1.y),
                                          fmaf(gamma, acc[i][6], x1.z), fmaf(gamma, acc[i][7], x1.w));
    }
}

// ============================================================
extern "C" void kernel_launch(void* const* d_in, const int* in_sizes, int n_in,
                              void* d_out, int out_size) {
    const float* x     = (const float*)d_in[0];
    const float* Wf    = (const float*)d_in[1];
    const float* Wg    = (const float*)d_in[2];
    const float* Wh    = (const float*)d_in[3];
    const float* Wo    = (const float*)d_in[4];
    const float* gamma = (const float*)d_in[5];
    float* out = (float*)d_out;

    cudaFuncSetAttribute(kC, cudaFuncAttributeMaxDynamicSharedMemorySize, SMEM_C_BYTES);

    kT<<<320, 256>>>(Wf, Wg, Wh, Wo);
    kA<<<dim3(32, 3, 8), 256>>>(x);
    kC<<<dim3(64, 8), 256, SMEM_C_BYTES>>>();
    kD<<<dim3(32, 4, 8), 256>>>(x, gamma, out);
}

// round 6
// speedup vs baseline: 2.2059x; 1.6766x over previous
#include <cuda_runtime.h>
#include <cstdint>

#define BB 8
#define CC 256
#define NPOS 4096   // 64*64
#define MPOS 1024   // 32*32
#define CF 32       // C/8
#define CHD 128     // C/2

// ---- scratch (static device globals; no allocation) ----
__device__ float g_f[(size_t)BB * CF * NPOS];       // f = Wf@x   (tf32-rounded)
__device__ float g_gp[(size_t)BB * CF * MPOS];      // pooled g   (tf32-rounded)
__device__ float g_hp[(size_t)BB * CHD * MPOS];     // pooled h   (tf32-rounded)
__device__ float g_o[(size_t)BB * CHD * NPOS];      // attention output (fp32)
__device__ float g_wta[256 * 192];                  // [k][oc] cat(Wf,Wg,Wh)^T
__device__ float g_wtd[128 * 256];                  // [k][oc] Wo^T

// ---- helpers ----
__device__ __forceinline__ void cpa16(float* s, const float* g) {
    unsigned sa = (unsigned)__cvta_generic_to_shared(s);
    asm volatile("cp.async.ca.shared.global [%0], [%1], 16;\n" :: "r"(sa), "l"(g));
}
__device__ __forceinline__ void cpcommit() { asm volatile("cp.async.commit_group;\n" ::); }
__device__ __forceinline__ void cpwait0()  { asm volatile("cp.async.wait_group 0;\n" ::); }

__device__ __forceinline__ float tf32r(float x) {
    uint32_t u;
    asm("cvt.rna.tf32.f32 %0, %1;" : "=r"(u) : "f"(x));
    return __uint_as_float(u);
}

__device__ __forceinline__ void mma8(float& c0, float& c1, float& c2, float& c3,
                                     uint32_t a0, uint32_t a1, uint32_t a2, uint32_t a3,
                                     uint32_t b0, uint32_t b1) {
    asm volatile("mma.sync.aligned.m16n8k8.row.col.f32.tf32.tf32.f32 "
                 "{%0,%1,%2,%3}, {%4,%5,%6,%7}, {%8,%9}, {%0,%1,%2,%3};"
                 : "+f"(c0), "+f"(c1), "+f"(c2), "+f"(c3)
                 : "r"(a0), "r"(a1), "r"(a2), "r"(a3), "r"(b0), "r"(b1));
}

// ============================================================
// Kernel T: transpose weights to [k][oc] layouts
// ============================================================
__global__ __launch_bounds__(256) void kT(const float* __restrict__ Wf,
                                          const float* __restrict__ Wg,
                                          const float* __restrict__ Wh,
                                          const float* __restrict__ Wo) {
    int idx = blockIdx.x * 256 + threadIdx.x;
    if (idx < 192 * 256) {
        int oc = idx >> 8, k = idx & 255;
        const float* src = (oc < 32) ? Wf + (size_t)oc * 256
                         : (oc < 64) ? Wg + (size_t)(oc - 32) * 256
                                     : Wh + (size_t)(oc - 64) * 256;
        g_wta[(size_t)k * 192 + oc] = src[k];
    }
    int idx2 = idx - 192 * 256;
    if (idx2 >= 0 && idx2 < 256 * 128) {
        int oc = idx2 >> 7, k = idx2 & 127;
        g_wtd[(size_t)k * 256 + oc] = Wo[(size_t)oc * 128 + k];
    }
}

// ============================================================
// Kernel A: [f;g;h] = Wcat @ x, pooled + tf32-rounded epilogue.
// grid (32 n-tiles of 128, 3 oc-tiles of 64, 8 b), 256 threads
// ============================================================
__global__ __launch_bounds__(256, 3) void kA(const float* __restrict__ x) {
    __shared__ __align__(16) float Ws[2][32 * 64];
    __shared__ __align__(16) float xs[2][32 * 128];
    const int b = blockIdx.z, ocb = blockIdx.y;
    const int n0 = blockIdx.x * 128;
    const int tid = threadIdx.x;
    const int tx = tid & 15, ty = tid >> 4;
    const float* xb = x + (size_t)b * CC * NPOS;

    float acc[4][8];
#pragma unroll
    for (int i = 0; i < 4; i++)
#pragma unroll
        for (int j = 0; j < 8; j++) acc[i][j] = 0.f;

    {
#pragma unroll
        for (int p = 0; p < 2; p++) {
            int idx = tid + p * 256; int kk = idx >> 4, c = idx & 15;
            cpa16(&Ws[0][kk * 64 + c * 4], &g_wta[(size_t)kk * 192 + ocb * 64 + c * 4]);
        }
#pragma unroll
        for (int p = 0; p < 4; p++) {
            int idx = tid + p * 256; int kk = idx >> 5, c = idx & 31;
            cpa16(&xs[0][kk * 128 + c * 4], &xb[(size_t)kk * NPOS + n0 + c * 4]);
        }
        cpcommit();
    }
    cpwait0(); __syncthreads();

    for (int it = 0; it < 8; it++) {
        const int cur = it & 1;
        if (it + 1 < 8) {
            const int nxt = cur ^ 1, k0 = (it + 1) * 32;
#pragma unroll
            for (int p = 0; p < 2; p++) {
                int idx = tid + p * 256; int kk = idx >> 4, c = idx & 15;
                cpa16(&Ws[nxt][kk * 64 + c * 4], &g_wta[(size_t)(k0 + kk) * 192 + ocb * 64 + c * 4]);
            }
#pragma unroll
            for (int p = 0; p < 4; p++) {
                int idx = tid + p * 256; int kk = idx >> 5, c = idx & 31;
                cpa16(&xs[nxt][kk * 128 + c * 4], &xb[(size_t)(k0 + kk) * NPOS + n0 + c * 4]);
            }
        }
        cpcommit();
#pragma unroll
        for (int kk = 0; kk < 32; kk++) {
            float4 a4 = *(const float4*)&Ws[cur][kk * 64 + ty * 4];
            float4 b0 = *(const float4*)&xs[cur][kk * 128 + tx * 4];
            float4 b1 = *(const float4*)&xs[cur][kk * 128 + 64 + tx * 4];
            float a[4] = {a4.x, a4.y, a4.z, a4.w};
            float bv[8] = {b0.x, b0.y, b0.z, b0.w, b1.x, b1.y, b1.z, b1.w};
#pragma unroll
            for (int i = 0; i < 4; i++)
#pragma unroll
                for (int j = 0; j < 8; j++) acc[i][j] = fmaf(a[i], bv[j], acc[i][j]);
        }
        cpwait0(); __syncthreads();
    }

    const int pm = blockIdx.x * 32 + tx * 2;
#pragma unroll
    for (int i = 0; i < 4; i++) {
        int oc = ocb * 64 + ty * 4 + i;
        if (oc < 32) {
            float* fb = g_f + (size_t)b * CF * NPOS + (size_t)oc * NPOS + n0;
            *(float4*)&fb[tx * 4]      = make_float4(tf32r(acc[i][0]), tf32r(acc[i][1]),
                                                     tf32r(acc[i][2]), tf32r(acc[i][3]));
            *(float4*)&fb[64 + tx * 4] = make_float4(tf32r(acc[i][4]), tf32r(acc[i][5]),
                                                     tf32r(acc[i][6]), tf32r(acc[i][7]));
        } else {
            float v0 = fmaxf(fmaxf(acc[i][0], acc[i][1]), fmaxf(acc[i][4], acc[i][5]));
            float v1 = fmaxf(fmaxf(acc[i][2], acc[i][3]), fmaxf(acc[i][6], acc[i][7]));
            float* dst = (oc < 64) ? g_gp + ((size_t)b * CF + (oc - 32)) * MPOS
                                   : g_hp + ((size_t)b * CHD + (oc - 64)) * MPOS;
            *(float2*)&dst[pm] = make_float2(tf32r(v0), tf32r(v1));
        }
    }
}

// ============================================================
// Kernel C: attention via tf32 mma.sync (m16n8k8).
// grid (64 q-tiles, 8 b), 256 threads = 8 warps, Mt=64, 16 m-tiles.
// score: warp w -> m-strip (w&3)*16, n-half (w>>2)*32 : 16 mmas/tile
// o    : warp w -> channels w*16..w*16+15, all 64 n   : 64 mmas/tile
// strides: fs/gs/ps = 72 (==8 mod 32, k-row access conflict-free)
//          hs = 68 (==4 mod 32, c-row access conflict-free)
// ============================================================
#define FST 72
#define GST2 72
#define HST 68
#define PST 72
#define KC_FS 0
#define KC_GS (32 * FST)
#define KC_HS (KC_GS + 32 * GST2)
#define KC_PS (KC_HS + 2 * 128 * HST)
#define KC_R4 (KC_PS + 64 * PST)
#define KC_RS (KC_R4 + 4 * 64)
#define SMEM_C_FLOATS (KC_RS + 64)
#define SMEM_C_BYTES (SMEM_C_FLOATS * 4)

extern __shared__ float smc[];

__global__ __launch_bounds__(256, 2) void kC() {
    float* fs   = smc + KC_FS;    // [k=32][72] f tile (n cols)
    float* gs   = smc + KC_GS;    // [k=32][72] g tile (m cols), single buffer
    float* hs   = smc + KC_HS;    // 2 x [c=128][68] h tiles (m cols)
    float* ps   = smc + KC_PS;    // [m=64][72] P tile (n cols)
    float* r4   = smc + KC_R4;    // [4][64] rowsum partials
    float* rsum = smc + KC_RS;    // [64] 1/rowsum

    const int b = blockIdx.y;
    const int n0 = blockIdx.x * 64;
    const int tid = threadIdx.x;
    const int w = tid >> 5, lane = tid & 31;
    const int r = lane >> 2, c = lane & 3;
    const float* gp = g_gp + (size_t)b * CF * MPOS;
    const float* hp = g_hp + (size_t)b * CHD * MPOS;
    const float* fp = g_f + (size_t)b * CF * NPOS + n0;

    // initial loads: fs + gs(t0) + hs(t0)
#pragma unroll
    for (int p = 0; p < 2; p++) {
        int idx = tid + p * 256; int rr = idx >> 4, cc = idx & 15;
        cpa16(&fs[rr * FST + cc * 4], &fp[(size_t)rr * NPOS + cc * 4]);
        cpa16(&gs[rr * GST2 + cc * 4], &gp[(size_t)rr * MPOS + cc * 4]);
    }
#pragma unroll
    for (int p = 0; p < 8; p++) {
        int idx = tid + p * 256; int rr = idx >> 4, cc = idx & 15;
        cpa16(&hs[rr * HST + cc * 4], &hp[(size_t)rr * MPOS + cc * 4]);
    }
    cpcommit();
    cpwait0(); __syncthreads();

    const int ms = (w & 3) * 16;    // score m-strip
    const int nb = (w >> 2) * 32;   // score n-half
    const int cb = w * 16;          // o-phase channel base

    float rs8[8];
#pragma unroll
    for (int i = 0; i < 8; i++) rs8[i] = 0.f;
    float oc[8][4];
#pragma unroll
    for (int i = 0; i < 8; i++)
#pragma unroll
        for (int j = 0; j < 4; j++) oc[i][j] = 0.f;

    for (int t = 0; t < 16; t++) {
        const int cur = t & 1;
        const float* hsc = hs + cur * 128 * HST;

        // prefetch hs(t+1) into alternate buffer (own group)
        if (t + 1 < 16) {
            const int m1 = (t + 1) * 64;
            float* hsd = hs + (cur ^ 1) * 128 * HST;
#pragma unroll
            for (int p = 0; p < 8; p++) {
                int idx = tid + p * 256; int rr = idx >> 4, cc = idx & 15;
                cpa16(&hsd[rr * HST + cc * 4], &hp[(size_t)rr * MPOS + m1 + cc * 4]);
            }
        }
        cpcommit();

        // ---- score mma: S'[m64][n64] = g^T f, warp does m16 x n32 ----
        float sc[4][4];
#pragma unroll
        for (int j = 0; j < 4; j++)
#pragma unroll
            for (int q = 0; q < 4; q++) sc[j][q] = 0.f;
#pragma unroll
        for (int ks = 0; ks < 4; ks++) {
            const int k0 = ks * 8;
            uint32_t a0 = __float_as_uint(gs[(k0 + c) * GST2 + ms + r]);
            uint32_t a1 = __float_as_uint(gs[(k0 + c) * GST2 + ms + r + 8]);
            uint32_t a2 = __float_as_uint(gs[(k0 + c + 4) * GST2 + ms + r]);
            uint32_t a3 = __float_as_uint(gs[(k0 + c + 4) * GST2 + ms + r + 8]);
#pragma unroll
            for (int j = 0; j < 4; j++) {
                uint32_t b0 = __float_as_uint(fs[(k0 + c) * FST + nb + j * 8 + r]);
                uint32_t b1 = __float_as_uint(fs[(k0 + c + 4) * FST + nb + j * 8 + r]);
                mma8(sc[j][0], sc[j][1], sc[j][2], sc[j][3], a0, a1, a2, a3, b0, b1);
            }
        }

        // ---- exp, store P (tf32), rowsum partials ----
#pragma unroll
        for (int j = 0; j < 4; j++) {
            float e0 = __expf(sc[j][0]);
            float e1 = __expf(sc[j][1]);
            float e2 = __expf(sc[j][2]);
            float e3 = __expf(sc[j][3]);
            const int n = nb + j * 8 + 2 * c;
            ps[(ms + r) * PST + n]         = tf32r(e0);
            ps[(ms + r) * PST + n + 1]     = tf32r(e1);
            ps[(ms + r + 8) * PST + n]     = tf32r(e2);
            ps[(ms + r + 8) * PST + n + 1] = tf32r(e3);
            float p0 = e0 + e2, p1 = e1 + e3;
#pragma unroll
            for (int off = 4; off < 32; off <<= 1) {
                p0 += __shfl_xor_sync(0xffffffffu, p0, off);
                p1 += __shfl_xor_sync(0xffffffffu, p1, off);
            }
            rs8[2 * j]     += p0;
            rs8[2 * j + 1] += p1;
        }
        __syncthreads();   // ps visible to all warps; gs free

        // prefetch gs(t+1) (single buffer, safe now)
        if (t + 1 < 16) {
            const int m1 = (t + 1) * 64;
#pragma unroll
            for (int p = 0; p < 2; p++) {
                int idx = tid + p * 256; int rr = idx >> 4, cc = idx & 15;
                cpa16(&gs[rr * GST2 + cc * 4], &gp[(size_t)rr * MPOS + m1 + cc * 4]);
            }
        }
        cpcommit();

        // ---- o mma: O[c128][n64] += h P, warp does c16 x n64 ----
#pragma unroll
        for (int km = 0; km < 8; km++) {
            const int m = km * 8;
            uint32_t a0 = __float_as_uint(hsc[(cb + r) * HST + m + c]);
            uint32_t a1 = __float_as_uint(hsc[(cb + r + 8) * HST + m + c]);
            uint32_t a2 = __float_as_uint(hsc[(cb + r) * HST + m + c + 4]);
            uint32_t a3 = __float_as_uint(hsc[(cb + r + 8) * HST + m + c + 4]);
#pragma unroll
            for (int j = 0; j < 8; j++) {
                uint32_t b0 = __float_as_uint(ps[(m + c) * PST + j * 8 + r]);
                uint32_t b1 = __float_as_uint(ps[(m + c + 4) * PST + j * 8 + r]);
                mma8(oc[j][0], oc[j][1], oc[j][2], oc[j][3], a0, a1, a2, a3, b0, b1);
            }
        }
        cpwait0();
        __syncthreads();   // next tiles resident; ps free
    }

    // ---- rowsum combine across the 4 m-strip warps ----
    if (r == 0) {
#pragma unroll
        for (int j = 0; j < 4; j++) {
            r4[(w & 3) * 64 + nb + j * 8 + 2 * c]     = rs8[2 * j];
            r4[(w & 3) * 64 + nb + j * 8 + 2 * c + 1] = rs8[2 * j + 1];
        }
    }
    __syncthreads();
    if (tid < 64)
        rsum[tid] = 1.f / (r4[tid] + r4[64 + tid] + r4[128 + tid] + r4[192 + tid]);
    __syncthreads();

    // ---- normalize + store O ----
    float* ob = g_o + (size_t)b * CHD * NPOS + n0;
#pragma unroll
    for (int j = 0; j < 8; j++) {
        const int n = j * 8 + 2 * c;
        float i0 = rsum[n], i1 = rsum[n + 1];
        *(float2*)&ob[(size_t)(cb + r) * NPOS + n]     = make_float2(oc[j][0] * i0, oc[j][1] * i1);
        *(float2*)&ob[(size_t)(cb + r + 8) * NPOS + n] = make_float2(oc[j][2] * i0, oc[j][3] * i1);
    }
}

// ============================================================
// Kernel D: out = gamma * (Wo @ o) + x, double-buffered cp.async
// ============================================================
__global__ __launch_bounds__(256, 3) void kD(const float* __restrict__ x,
                                             const float* __restrict__ gptr,
                                             float* __restrict__ out) {
    __shared__ __align__(16) float Ws[2][32 * 64];
    __shared__ __align__(16) float os[2][32 * 128];
    const int b = blockIdx.z, ocb = blockIdx.y;
    const int n0 = blockIdx.x * 128;
    const int tid = threadIdx.x;
    const int tx = tid & 15, ty = tid >> 4;
    const float gamma = *gptr;
    const float* ob = g_o + (size_t)b * CHD * NPOS;

    float acc[4][8];
#pragma unroll
    for (int i = 0; i < 4; i++)
#pragma unroll
        for (int j = 0; j < 8; j++) acc[i][j] = 0.f;

    {
#pragma unroll
        for (int p = 0; p < 2; p++) {
            int idx = tid + p * 256; int kk = idx >> 4, c = idx & 15;
            cpa16(&Ws[0][kk * 64 + c * 4], &g_wtd[(size_t)kk * 256 + ocb * 64 + c * 4]);
        }
#pragma unroll
        for (int p = 0; p < 4; p++) {
            int idx = tid + p * 256; int kk = idx >> 5, c = idx & 31;
            cpa16(&os[0][kk * 128 + c * 4], &ob[(size_t)kk * NPOS + n0 + c * 4]);
        }
        cpcommit();
    }
    cpwait0(); __syncthreads();

    for (int it = 0; it < 4; it++) {
        const int cur = it & 1;
        if (it + 1 < 4) {
            const int nxt = cur ^ 1, k0 = (it + 1) * 32;
#pragma unroll
            for (int p = 0; p < 2; p++) {
                int idx = tid + p * 256; int kk = idx >> 4, c = idx & 15;
                cpa16(&Ws[nxt][kk * 64 + c * 4], &g_wtd[(size_t)(k0 + kk) * 256 + ocb * 64 + c * 4]);
            }
#pragma unroll
            for (int p = 0; p < 4; p++) {
                int idx = tid + p * 256; int kk = idx >> 5, c = idx & 31;
                cpa16(&os[nxt][kk * 128 + c * 4], &ob[(size_t)(k0 + kk) * NPOS + n0 + c * 4]);
            }
        }
        cpcommit();
#pragma unroll
        for (int kk = 0; kk < 32; kk++) {
            float4 a4 = *(const float4*)&Ws[cur][kk * 64 + ty * 4];
            float4 b0 = *(const float4*)&os[cur][kk * 128 + tx * 4];
            float4 b1 = *(const float4*)&os[cur][kk * 128 + 64 + tx * 4];
            float a[4] = {a4.x, a4.y, a4.z, a4.w};
            float bv[8] = {b0.x, b0.y, b0.z, b0.w, b1.x, b1.y, b1.z, b1.w};
#pragma unroll
            for (int i = 0; i < 4; i++)
#pragma unroll
                for (int j = 0; j < 8; j++) acc[i][j] = fmaf(a[i], bv[j], acc[i][j]);
        }
        cpwait0(); __syncthreads();
    }

    const float* xb = x + (size_t)b * CC * NPOS;
    float* outb = out + (size_t)b * CC * NPOS;
#pragma unroll
    for (int i = 0; i < 4; i++) {
        int oc = ocb * 64 + ty * 4 + i;
        size_t o0 = (size_t)oc * NPOS + n0 + tx * 4;
        size_t o1 = o0 + 64;
        float4 x0 = *(const float4*)&xb[o0];
        float4 x1 = *(const float4*)&xb[o1];
        *(float4*)&outb[o0] = make_float4(fmaf(gamma, acc[i][0], x0.x), fmaf(gamma, acc[i][1], x0.y),
                                          fmaf(gamma, acc[i][2], x0.z), fmaf(gamma, acc[i][3], x0.w));
        *(float4*)&outb[o1] = make_float4(fmaf(gamma, acc[i][4], x1.x), fmaf(gamma, acc[i][5], x1.y),
                                          fmaf(gamma, acc[i][6], x1.z), fmaf(gamma, acc[i][7], x1.w));
    }
}

// ============================================================
extern "C" void kernel_launch(void* const* d_in, const int* in_sizes, int n_in,
                              void* d_out, int out_size) {
    const float* x     = (const float*)d_in[0];
    const float* Wf    = (const float*)d_in[1];
    const float* Wg    = (const float*)d_in[2];
    const float* Wh    = (const float*)d_in[3];
    const float* Wo    = (const float*)d_in[4];
    const float* gamma = (const float*)d_in[5];
    float* out = (float*)d_out;

    cudaFuncSetAttribute(kC, cudaFuncAttributeMaxDynamicSharedMemorySize, SMEM_C_BYTES);

    kT<<<320, 256>>>(Wf, Wg, Wh, Wo);
    kA<<<dim3(32, 3, 8), 256>>>(x);
    kC<<<dim3(64, 8), 256, SMEM_C_BYTES>>>();
    kD<<<dim3(32, 4, 8), 256>>>(x, gamma, out);
}

// round 7
// speedup vs baseline: 3.0116x; 1.3653x over previous
#include <cuda_runtime.h>
#include <cstdint>

#define BB 8
#define CC 256
#define NPOS 4096   // 64*64
#define MPOS 1024   // 32*32
#define CF 32       // C/8
#define CHD 128     // C/2

// ---- scratch (static device globals; no allocation) ----
__device__ float g_f[(size_t)BB * CF * NPOS];       // f = Wf@x   (tf32-rounded)
__device__ float g_gp[(size_t)BB * CF * MPOS];      // pooled g   (tf32-rounded)
__device__ float g_hp[(size_t)BB * CHD * MPOS];     // pooled h   (tf32-rounded)
__device__ float g_o[(size_t)BB * CHD * NPOS];      // attention output (tf32-rounded)
__device__ float g_wta[256 * 192];                  // [k][oc] cat(Wf,Wg,Wh)^T, tf32
__device__ float g_wtd[128 * 256];                  // [k][oc] Wo^T, tf32

// ---- helpers ----
__device__ __forceinline__ void cpa16(float* s, const float* g) {
    unsigned sa = (unsigned)__cvta_generic_to_shared(s);
    asm volatile("cp.async.ca.shared.global [%0], [%1], 16;\n" :: "r"(sa), "l"(g));
}
__device__ __forceinline__ void cpcommit() { asm volatile("cp.async.commit_group;\n" ::); }
__device__ __forceinline__ void cpwait0()  { asm volatile("cp.async.wait_group 0;\n" ::); }

__device__ __forceinline__ float tf32r(float x) {
    uint32_t u;
    asm("cvt.rna.tf32.f32 %0, %1;" : "=r"(u) : "f"(x));
    return __uint_as_float(u);
}

__device__ __forceinline__ void mma8(float& c0, float& c1, float& c2, float& c3,
                                     uint32_t a0, uint32_t a1, uint32_t a2, uint32_t a3,
                                     uint32_t b0, uint32_t b1) {
    asm volatile("mma.sync.aligned.m16n8k8.row.col.f32.tf32.tf32.f32 "
                 "{%0,%1,%2,%3}, {%4,%5,%6,%7}, {%8,%9}, {%0,%1,%2,%3};"
                 : "+f"(c0), "+f"(c1), "+f"(c2), "+f"(c3)
                 : "r"(a0), "r"(a1), "r"(a2), "r"(a3), "r"(b0), "r"(b1));
}

extern __shared__ float smc[];

// ============================================================
// Kernel T: transpose weights to [k][oc] layouts (tf32-rounded)
// ============================================================
__global__ __launch_bounds__(256) void kT(const float* __restrict__ Wf,
                                          const float* __restrict__ Wg,
                                          const float* __restrict__ Wh,
                                          const float* __restrict__ Wo) {
    int idx = blockIdx.x * 256 + threadIdx.x;
    if (idx < 192 * 256) {
        int oc = idx >> 8, k = idx & 255;
        const float* src = (oc < 32) ? Wf + (size_t)oc * 256
                         : (oc < 64) ? Wg + (size_t)(oc - 32) * 256
                                     : Wh + (size_t)(oc - 64) * 256;
        g_wta[(size_t)k * 192 + oc] = tf32r(src[k]);
    }
    int idx2 = idx - 192 * 256;
    if (idx2 >= 0 && idx2 < 256 * 128) {
        int oc = idx2 >> 7, k = idx2 & 127;
        g_wtd[(size_t)k * 256 + oc] = tf32r(Wo[(size_t)oc * 128 + k]);
    }
}

// ============================================================
// Kernel A: [f;g;h] = Wcat @ x via tf32 mma, pooled epilogue.
// grid (32 n-tiles of 128, 3 oc-tiles of 64, 8 b), 256 thr = 8 warps.
// warp w: oc strip ms=(w&3)*16, n-mmas j: nn = (w>>2)*32 + (j&3)*8 + (j>>2)*64
// smem: Ws[2][32*72] (W tile [k][oc]), xs[2][32*136] (x tile [k][n]).
// ============================================================
#define AWST 72
#define AXST 136
#define KA_WS 0
#define KA_XS (2 * 32 * AWST)
#define SMEM_A_BYTES ((KA_XS + 2 * 32 * AXST) * 4)

__global__ __launch_bounds__(256, 3) void kA(const float* __restrict__ x) {
    float* Ws = smc + KA_WS;   // 2 x [32][72]
    float* xs = smc + KA_XS;   // 2 x [32][136]
    const int b = blockIdx.z, ocb = blockIdx.y;
    const int n0 = blockIdx.x * 128;
    const int tid = threadIdx.x;
    const int w = tid >> 5, lane = tid & 31;
    const int r = lane >> 2, c = lane & 3;
    const int ms = (w & 3) * 16, nh = w >> 2;
    const float* xb = x + (size_t)b * CC * NPOS;

    float acc[8][4];
#pragma unroll
    for (int j = 0; j < 8; j++)
#pragma unroll
        for (int q = 0; q < 4; q++) acc[j][q] = 0.f;

    // preload chunk 0
#pragma unroll
    for (int p = 0; p < 2; p++) {
        int idx = tid + p * 256; int kk = idx >> 4, cc = idx & 15;
        cpa16(&Ws[kk * AWST + cc * 4], &g_wta[(size_t)kk * 192 + ocb * 64 + cc * 4]);
    }
#pragma unroll
    for (int p = 0; p < 4; p++) {
        int idx = tid + p * 256; int kk = idx >> 5, cc = idx & 31;
        cpa16(&xs[kk * AXST + cc * 4], &xb[(size_t)kk * NPOS + n0 + cc * 4]);
    }
    cpcommit();
    cpwait0(); __syncthreads();

    for (int it = 0; it < 8; it++) {
        const int cur = it & 1;
        if (it + 1 < 8) {
            const int nxt = cur ^ 1, k0g = (it + 1) * 32;
            float* Wd = Ws + nxt * 32 * AWST;
            float* xd = xs + nxt * 32 * AXST;
#pragma unroll
            for (int p = 0; p < 2; p++) {
                int idx = tid + p * 256; int kk = idx >> 4, cc = idx & 15;
                cpa16(&Wd[kk * AWST + cc * 4], &g_wta[(size_t)(k0g + kk) * 192 + ocb * 64 + cc * 4]);
            }
#pragma unroll
            for (int p = 0; p < 4; p++) {
                int idx = tid + p * 256; int kk = idx >> 5, cc = idx & 31;
                cpa16(&xd[kk * AXST + cc * 4], &xb[(size_t)(k0g + kk) * NPOS + n0 + cc * 4]);
            }
        }
        cpcommit();

        const float* Wc = Ws + cur * 32 * AWST;
        const float* xc = xs + cur * 32 * AXST;
#pragma unroll
        for (int ks = 0; ks < 4; ks++) {
            const int k0 = ks * 8;
            uint32_t a0 = __float_as_uint(Wc[(k0 + c) * AWST + ms + r]);
            uint32_t a1 = __float_as_uint(Wc[(k0 + c) * AWST + ms + r + 8]);
            uint32_t a2 = __float_as_uint(Wc[(k0 + c + 4) * AWST + ms + r]);
            uint32_t a3 = __float_as_uint(Wc[(k0 + c + 4) * AWST + ms + r + 8]);
#pragma unroll
            for (int j = 0; j < 8; j++) {
                const int nn = nh * 32 + (j & 3) * 8 + (j >> 2) * 64;
                uint32_t b0 = __float_as_uint(xc[(k0 + c) * AXST + nn + r]);
                uint32_t b1 = __float_as_uint(xc[(k0 + c + 4) * AXST + nn + r]);
                mma8(acc[j][0], acc[j][1], acc[j][2], acc[j][3], a0, a1, a2, a3, b0, b1);
            }
        }
        cpwait0(); __syncthreads();
    }

    // epilogue
    if (ocb == 0 && ms < 32) {
        // f rows: store fp32 (tf32-rounded), no pooling
        float* fb = g_f + (size_t)b * CF * NPOS;
#pragma unroll
        for (int j = 0; j < 8; j++) {
            const int nn = nh * 32 + (j & 3) * 8 + (j >> 2) * 64;
            const int n = n0 + nn + 2 * c;
            *(float2*)&fb[(size_t)(ms + r) * NPOS + n] =
                make_float2(tf32r(acc[j][0]), tf32r(acc[j][1]));
            *(float2*)&fb[(size_t)(ms + r + 8) * NPOS + n] =
                make_float2(tf32r(acc[j][2]), tf32r(acc[j][3]));
        }
    } else {
        // g/h rows: 2x2 pool (col pair = 2c/2c+1, row pair = j / j+4)
        const int oc0 = ocb * 64 + ms + r;
        float* dst = (ocb == 0) ? g_gp + ((size_t)b * CF + (oc0 - 32)) * MPOS
                                : g_hp + ((size_t)b * CHD + (oc0 - 64)) * MPOS;
#pragma unroll
        for (int j = 0; j < 4; j++) {
            float vlo = fmaxf(fmaxf(acc[j][0], acc[j][1]), fmaxf(acc[j + 4][0], acc[j + 4][1]));
            float vhi = fmaxf(fmaxf(acc[j][2], acc[j][3]), fmaxf(acc[j + 4][2], acc[j + 4][3]));
            const int pm = blockIdx.x * 32 + nh * 16 + j * 4 + c;
            dst[pm] = tf32r(vlo);
            dst[8 * MPOS + pm] = tf32r(vhi);
        }
    }
}

// ============================================================
// Kernel C: attention via tf32 mma.sync (m16n8k8). (unchanged from R6,
// except o stored tf32-rounded for kD's mma)
// ============================================================
#define FST 72
#define GST2 72
#define HST 68
#define PST 72
#define KC_FS 0
#define KC_GS (32 * FST)
#define KC_HS (KC_GS + 32 * GST2)
#define KC_PS (KC_HS + 2 * 128 * HST)
#define KC_R4 (KC_PS + 64 * PST)
#define KC_RS (KC_R4 + 4 * 64)
#define SMEM_C_FLOATS (KC_RS + 64)
#define SMEM_C_BYTES (SMEM_C_FLOATS * 4)

__global__ __launch_bounds__(256, 2) void kC() {
    float* fs   = smc + KC_FS;
    float* gs   = smc + KC_GS;
    float* hs   = smc + KC_HS;
    float* ps   = smc + KC_PS;
    float* r4   = smc + KC_R4;
    float* rsum = smc + KC_RS;

    const int b = blockIdx.y;
    const int n0 = blockIdx.x * 64;
    const int tid = threadIdx.x;
    const int w = tid >> 5, lane = tid & 31;
    const int r = lane >> 2, c = lane & 3;
    const float* gp = g_gp + (size_t)b * CF * MPOS;
    const float* hp = g_hp + (size_t)b * CHD * MPOS;
    const float* fp = g_f + (size_t)b * CF * NPOS + n0;

#pragma unroll
    for (int p = 0; p < 2; p++) {
        int idx = tid + p * 256; int rr = idx >> 4, cc = idx & 15;
        cpa16(&fs[rr * FST + cc * 4], &fp[(size_t)rr * NPOS + cc * 4]);
        cpa16(&gs[rr * GST2 + cc * 4], &gp[(size_t)rr * MPOS + cc * 4]);
    }
#pragma unroll
    for (int p = 0; p < 8; p++) {
        int idx = tid + p * 256; int rr = idx >> 4, cc = idx & 15;
        cpa16(&hs[rr * HST + cc * 4], &hp[(size_t)rr * MPOS + cc * 4]);
    }
    cpcommit();
    cpwait0(); __syncthreads();

    const int ms = (w & 3) * 16;
    const int nb = (w >> 2) * 32;
    const int cb = w * 16;

    float rs8[8];
#pragma unroll
    for (int i = 0; i < 8; i++) rs8[i] = 0.f;
    float oc[8][4];
#pragma unroll
    for (int i = 0; i < 8; i++)
#pragma unroll
        for (int j = 0; j < 4; j++) oc[i][j] = 0.f;

    for (int t = 0; t < 16; t++) {
        const int cur = t & 1;
        const float* hsc = hs + cur * 128 * HST;

        if (t + 1 < 16) {
            const int m1 = (t + 1) * 64;
            float* hsd = hs + (cur ^ 1) * 128 * HST;
#pragma unroll
            for (int p = 0; p < 8; p++) {
                int idx = tid + p * 256; int rr = idx >> 4, cc = idx & 15;
                cpa16(&hsd[rr * HST + cc * 4], &hp[(size_t)rr * MPOS + m1 + cc * 4]);
            }
        }
        cpcommit();

        float sc[4][4];
#pragma unroll
        for (int j = 0; j < 4; j++)
#pragma unroll
            for (int q = 0; q < 4; q++) sc[j][q] = 0.f;
#pragma unroll
        for (int ks = 0; ks < 4; ks++) {
            const int k0 = ks * 8;
            uint32_t a0 = __float_as_uint(gs[(k0 + c) * GST2 + ms + r]);
            uint32_t a1 = __float_as_uint(gs[(k0 + c) * GST2 + ms + r + 8]);
            uint32_t a2 = __float_as_uint(gs[(k0 + c + 4) * GST2 + ms + r]);
            uint32_t a3 = __float_as_uint(gs[(k0 + c + 4) * GST2 + ms + r + 8]);
#pragma unroll
            for (int j = 0; j < 4; j++) {
                uint32_t b0 = __float_as_uint(fs[(k0 + c) * FST + nb + j * 8 + r]);
                uint32_t b1 = __float_as_uint(fs[(k0 + c + 4) * FST + nb + j * 8 + r]);
                mma8(sc[j][0], sc[j][1], sc[j][2], sc[j][3], a0, a1, a2, a3, b0, b1);
            }
        }

#pragma unroll
        for (int j = 0; j < 4; j++) {
            float e0 = __expf(sc[j][0]);
            float e1 = __expf(sc[j][1]);
            float e2 = __expf(sc[j][2]);
            float e3 = __expf(sc[j][3]);
            const int n = nb + j * 8 + 2 * c;
            ps[(ms + r) * PST + n]         = tf32r(e0);
            ps[(ms + r) * PST + n + 1]     = tf32r(e1);
            ps[(ms + r + 8) * PST + n]     = tf32r(e2);
            ps[(ms + r + 8) * PST + n + 1] = tf32r(e3);
            float p0 = e0 + e2, p1 = e1 + e3;
#pragma unroll
            for (int off = 4; off < 32; off <<= 1) {
                p0 += __shfl_xor_sync(0xffffffffu, p0, off);
                p1 += __shfl_xor_sync(0xffffffffu, p1, off);
            }
            rs8[2 * j]     += p0;
            rs8[2 * j + 1] += p1;
        }
        __syncthreads();

        if (t + 1 < 16) {
            const int m1 = (t + 1) * 64;
#pragma unroll
            for (int p = 0; p < 2; p++) {
                int idx = tid + p * 256; int rr = idx >> 4, cc = idx & 15;
                cpa16(&gs[rr * GST2 + cc * 4], &gp[(size_t)rr * MPOS + m1 + cc * 4]);
            }
        }
        cpcommit();

#pragma unroll
        for (int km = 0; km < 8; km++) {
            const int m = km * 8;
            uint32_t a0 = __float_as_uint(hsc[(cb + r) * HST + m + c]);
            uint32_t a1 = __float_as_uint(hsc[(cb + r + 8) * HST + m + c]);
            uint32_t a2 = __float_as_uint(hsc[(cb + r) * HST + m + c + 4]);
            uint32_t a3 = __float_as_uint(hsc[(cb + r + 8) * HST + m + c + 4]);
#pragma unroll
            for (int j = 0; j < 8; j++) {
                uint32_t b0 = __float_as_uint(ps[(m + c) * PST + j * 8 + r]);
                uint32_t b1 = __float_as_uint(ps[(m + c + 4) * PST + j * 8 + r]);
                mma8(oc[j][0], oc[j][1], oc[j][2], oc[j][3], a0, a1, a2, a3, b0, b1);
            }
        }
        cpwait0();
        __syncthreads();
    }

    if (r == 0) {
#pragma unroll
        for (int j = 0; j < 4; j++) {
            r4[(w & 3) * 64 + nb + j * 8 + 2 * c]     = rs8[2 * j];
            r4[(w & 3) * 64 + nb + j * 8 + 2 * c + 1] = rs8[2 * j + 1];
        }
    }
    __syncthreads();
    if (tid < 64)
        rsum[tid] = 1.f / (r4[tid] + r4[64 + tid] + r4[128 + tid] + r4[192 + tid]);
    __syncthreads();

    float* ob = g_o + (size_t)b * CHD * NPOS + n0;
#pragma unroll
    for (int j = 0; j < 8; j++) {
        const int n = j * 8 + 2 * c;
        float i0 = rsum[n], i1 = rsum[n + 1];
        *(float2*)&ob[(size_t)(cb + r) * NPOS + n] =
            make_float2(tf32r(oc[j][0] * i0), tf32r(oc[j][1] * i1));
        *(float2*)&ob[(size_t)(cb + r + 8) * NPOS + n] =
            make_float2(tf32r(oc[j][2] * i0), tf32r(oc[j][3] * i1));
    }
}

// ============================================================
// Kernel D: out = gamma * (Wo @ o) + x via tf32 mma.
// grid (32 n-tiles of 128, 4 oc-tiles of 64, 8 b), 256 thr = 8 warps.
// ============================================================
#define KD_WS 0
#define KD_XS (2 * 32 * AWST)
#define SMEM_D_BYTES ((KD_XS + 2 * 32 * AXST) * 4)

__global__ __launch_bounds__(256, 3) void kD(const float* __restrict__ x,
                                             const float* __restrict__ gptr,
                                             float* __restrict__ out) {
    float* Ws = smc + KD_WS;
    float* os = smc + KD_XS;
    const int b = blockIdx.z, ocb = blockIdx.y;
    const int n0 = blockIdx.x * 128;
    const int tid = threadIdx.x;
    const int w = tid >> 5, lane = tid & 31;
    const int r = lane >> 2, c = lane & 3;
    const int ms = (w & 3) * 16, nh = w >> 2;
    const float gamma = *gptr;
    const float* ob = g_o + (size_t)b * CHD * NPOS;

    float acc[8][4];
#pragma unroll
    for (int j = 0; j < 8; j++)
#pragma unroll
        for (int q = 0; q < 4; q++) acc[j][q] = 0.f;

#pragma unroll
    for (int p = 0; p < 2; p++) {
        int idx = tid + p * 256; int kk = idx >> 4, cc = idx & 15;
        cpa16(&Ws[kk * AWST + cc * 4], &g_wtd[(size_t)kk * 256 + ocb * 64 + cc * 4]);
    }
#pragma unroll
    for (int p = 0; p < 4; p++) {
        int idx = tid + p * 256; int kk = idx >> 5, cc = idx & 31;
        cpa16(&os[kk * AXST + cc * 4], &ob[(size_t)kk * NPOS + n0 + cc * 4]);
    }
    cpcommit();
    cpwait0(); __syncthreads();

    for (int it = 0; it < 4; it++) {
        const int cur = it & 1;
        if (it + 1 < 4) {
            const int nxt = cur ^ 1, k0g = (it + 1) * 32;
            float* Wd = Ws + nxt * 32 * AWST;
            float* xd = os + nxt * 32 * AXST;
#pragma unroll
            for (int p = 0; p < 2; p++) {
                int idx = tid + p * 256; int kk = idx >> 4, cc = idx & 15;
                cpa16(&Wd[kk * AWST + cc * 4], &g_wtd[(size_t)(k0g + kk) * 256 + ocb * 64 + cc * 4]);
            }
#pragma unroll
            for (int p = 0; p < 4; p++) {
                int idx = tid + p * 256; int kk = idx >> 5, cc = idx & 31;
                cpa16(&xd[kk * AXST + cc * 4], &ob[(size_t)(k0g + kk) * NPOS + n0 + cc * 4]);
            }
        }
        cpcommit();

        const float* Wc = Ws + cur * 32 * AWST;
        const float* xc = os + cur * 32 * AXST;
#pragma unroll
        for (int ks = 0; ks < 4; ks++) {
            const int k0 = ks * 8;
            uint32_t a0 = __float_as_uint(Wc[(k0 + c) * AWST + ms + r]);
            uint32_t a1 = __float_as_uint(Wc[(k0 + c) * AWST + ms + r + 8]);
            uint32_t a2 = __float_as_uint(Wc[(k0 + c + 4) * AWST + ms + r]);
            uint32_t a3 = __float_as_uint(Wc[(k0 + c + 4) * AWST + ms + r + 8]);
#pragma unroll
            for (int j = 0; j < 8; j++) {
                const int nn = nh * 32 + (j & 3) * 8 + (j >> 2) * 64;
                uint32_t b0 = __float_as_uint(xc[(k0 + c) * AXST + nn + r]);
                uint32_t b1 = __float_as_uint(xc[(k0 + c + 4) * AXST + nn + r]);
                mma8(acc[j][0], acc[j][1], acc[j][2], acc[j][3], a0, a1, a2, a3, b0, b1);
            }
        }
        cpwait0(); __syncthreads();
    }

    const float* xb = x + (size_t)b * CC * NPOS;
    float* outb = out + (size_t)b * CC * NPOS;
    const int oc0 = ocb * 64 + ms + r;
#pragma unroll
    for (int j = 0; j < 8; j++) {
        const int nn = nh * 32 + (j & 3) * 8 + (j >> 2) * 64;
        const int n = n0 + nn + 2 * c;
        size_t p0 = (size_t)oc0 * NPOS + n;
        size_t p1 = (size_t)(oc0 + 8) * NPOS + n;
        float2 x0 = *(const float2*)&xb[p0];
        float2 x1 = *(const float2*)&xb[p1];
        *(float2*)&outb[p0] = make_float2(fmaf(gamma, acc[j][0], x0.x),
                                          fmaf(gamma, acc[j][1], x0.y));
        *(float2*)&outb[p1] = make_float2(fmaf(gamma, acc[j][2], x1.x),
                                          fmaf(gamma, acc[j][3], x1.y));
    }
}

// ============================================================
extern "C" void kernel_launch(void* const* d_in, const int* in_sizes, int n_in,
                              void* d_out, int out_size) {
    const float* x     = (const float*)d_in[0];
    const float* Wf    = (const float*)d_in[1];
    const float* Wg    = (const float*)d_in[2];
    const float* Wh    = (const float*)d_in[3];
    const float* Wo    = (const float*)d_in[4];
    const float* gamma = (const float*)d_in[5];
    float* out = (float*)d_out;

    cudaFuncSetAttribute(kA, cudaFuncAttributeMaxDynamicSharedMemorySize, SMEM_A_BYTES);
    cudaFuncSetAttribute(kC, cudaFuncAttributeMaxDynamicSharedMemorySize, SMEM_C_BYTES);
    cudaFuncSetAttribute(kD, cudaFuncAttributeMaxDynamicSharedMemorySize, SMEM_D_BYTES);

    kT<<<320, 256>>>(Wf, Wg, Wh, Wo);
    kA<<<dim3(32, 3, 8), 256, SMEM_A_BYTES>>>(x);
    kC<<<dim3(64, 8), 256, SMEM_C_BYTES>>>();
    kD<<<dim3(32, 4, 8), 256, SMEM_D_BYTES>>>(x, gamma, out);
}

// round 8
// speedup vs baseline: 3.7035x; 1.2297x over previous
#include <cuda_runtime.h>
#include <cuda_bf16.h>
#include <cstdint>

#define BB 8
#define CC 256
#define NPOS 4096   // 64*64
#define MPOS 1024   // 32*32
#define CF 32       // C/8
#define CHD 128     // C/2

// ---- scratch (static device globals; no allocation) ----
__device__ float g_f[(size_t)BB * CF * NPOS];                 // f (tf32-rounded fp32)
__device__ float g_gp[(size_t)BB * CF * MPOS];                // pooled g (tf32-rounded fp32)
__device__ __nv_bfloat16 g_hp[(size_t)BB * CHD * MPOS];       // pooled h (bf16)
__device__ float g_o[(size_t)BB * CHD * NPOS];                // attention out (tf32-rounded fp32)

// ---- helpers ----
__device__ __forceinline__ void cpa16(void* s, const void* g) {
    unsigned sa = (unsigned)__cvta_generic_to_shared(s);
    asm volatile("cp.async.ca.shared.global [%0], [%1], 16;\n" :: "r"(sa), "l"(g));
}
__device__ __forceinline__ void cpcommit() { asm volatile("cp.async.commit_group;\n" ::); }
__device__ __forceinline__ void cpwait0()  { asm volatile("cp.async.wait_group 0;\n" ::); }

__device__ __forceinline__ float tf32r(float x) {
    uint32_t u;
    asm("cvt.rna.tf32.f32 %0, %1;" : "=r"(u) : "f"(x));
    return __uint_as_float(u);
}

__device__ __forceinline__ void mma8(float& c0, float& c1, float& c2, float& c3,
                                     uint32_t a0, uint32_t a1, uint32_t a2, uint32_t a3,
                                     uint32_t b0, uint32_t b1) {
    asm volatile("mma.sync.aligned.m16n8k8.row.col.f32.tf32.tf32.f32 "
                 "{%0,%1,%2,%3}, {%4,%5,%6,%7}, {%8,%9}, {%0,%1,%2,%3};"
                 : "+f"(c0), "+f"(c1), "+f"(c2), "+f"(c3)
                 : "r"(a0), "r"(a1), "r"(a2), "r"(a3), "r"(b0), "r"(b1));
}

__device__ __forceinline__ void mma16b(float& c0, float& c1, float& c2, float& c3,
                                       uint32_t a0, uint32_t a1, uint32_t a2, uint32_t a3,
                                       uint32_t b0, uint32_t b1) {
    asm volatile("mma.sync.aligned.m16n8k16.row.col.f32.bf16.bf16.f32 "
                 "{%0,%1,%2,%3}, {%4,%5,%6,%7}, {%8,%9}, {%0,%1,%2,%3};"
                 : "+f"(c0), "+f"(c1), "+f"(c2), "+f"(c3)
                 : "r"(a0), "r"(a1), "r"(a2), "r"(a3), "r"(b0), "r"(b1));
}

extern __shared__ float smc[];

// ============================================================
// Kernel A: [f;g;h] = Wcat @ x via tf32 mma, raw-weight loads,
// pooled epilogue (g fp32, h bf16).
// grid (32 n-tiles of 128, 3 oc-tiles of 64, 8 b), 256 thr = 8 warps.
// smem: Ws 2x[64 oc][36] (raw [oc][k] chunk), xs 2x[32 k][136].
// ============================================================
#define WST 36
#define AXST 136
#define KA_WS 0
#define KA_XS (2 * 64 * WST)
#define SMEM_A_BYTES ((KA_XS + 2 * 32 * AXST) * 4)

__global__ __launch_bounds__(256, 3) void kA(const float* __restrict__ x,
                                             const float* __restrict__ Wf,
                                             const float* __restrict__ Wg,
                                             const float* __restrict__ Wh) {
    float* Ws = smc + KA_WS;   // 2 x [64][36]
    float* xs = smc + KA_XS;   // 2 x [32][136]
    const int b = blockIdx.z, ocb = blockIdx.y;
    const int n0 = blockIdx.x * 128;
    const int tid = threadIdx.x;
    const int w = tid >> 5, lane = tid & 31;
    const int r = lane >> 2, c = lane & 3;
    const int ms = (w & 3) * 16, nh = w >> 2;
    const float* xb = x + (size_t)b * CC * NPOS;

    float acc[8][4];
#pragma unroll
    for (int j = 0; j < 8; j++)
#pragma unroll
        for (int q = 0; q < 4; q++) acc[j][q] = 0.f;

    // weight-row source (concat of Wf/Wg/Wh)
    auto wrow = [&](int row) -> const float* {
        if (ocb == 0) return (row < 32) ? Wf + (size_t)row * 256 : Wg + (size_t)(row - 32) * 256;
        return Wh + (size_t)((ocb - 1) * 64 + row) * 256;
    };

    // preload chunk 0
#pragma unroll
    for (int p = 0; p < 2; p++) {
        int idx = tid + p * 256; int row = idx >> 3, cc = idx & 7;
        cpa16(&Ws[row * WST + cc * 4], wrow(row) + cc * 4);
    }
#pragma unroll
    for (int p = 0; p < 4; p++) {
        int idx = tid + p * 256; int kk = idx >> 5, cc = idx & 31;
        cpa16(&xs[kk * AXST + cc * 4], &xb[(size_t)kk * NPOS + n0 + cc * 4]);
    }
    cpcommit();
    cpwait0(); __syncthreads();

    for (int it = 0; it < 8; it++) {
        const int cur = it & 1;
        if (it + 1 < 8) {
            const int nxt = cur ^ 1, k0g = (it + 1) * 32;
            float* Wd = Ws + nxt * 64 * WST;
            float* xd = xs + nxt * 32 * AXST;
#pragma unroll
            for (int p = 0; p < 2; p++) {
                int idx = tid + p * 256; int row = idx >> 3, cc = idx & 7;
                cpa16(&Wd[row * WST + cc * 4], wrow(row) + k0g + cc * 4);
            }
#pragma unroll
            for (int p = 0; p < 4; p++) {
                int idx = tid + p * 256; int kk = idx >> 5, cc = idx & 31;
                cpa16(&xd[kk * AXST + cc * 4], &xb[(size_t)(k0g + kk) * NPOS + n0 + cc * 4]);
            }
        }
        cpcommit();

        const float* Wc = Ws + cur * 64 * WST;
        const float* xc = xs + cur * 32 * AXST;
#pragma unroll
        for (int ks = 0; ks < 4; ks++) {
            const int k0 = ks * 8;
            uint32_t a0 = __float_as_uint(Wc[(ms + r) * WST + k0 + c]);
            uint32_t a1 = __float_as_uint(Wc[(ms + r + 8) * WST + k0 + c]);
            uint32_t a2 = __float_as_uint(Wc[(ms + r) * WST + k0 + c + 4]);
            uint32_t a3 = __float_as_uint(Wc[(ms + r + 8) * WST + k0 + c + 4]);
#pragma unroll
            for (int j = 0; j < 8; j++) {
                const int nn = nh * 32 + (j & 3) * 8 + (j >> 2) * 64;
                uint32_t b0 = __float_as_uint(xc[(k0 + c) * AXST + nn + r]);
                uint32_t b1 = __float_as_uint(xc[(k0 + c + 4) * AXST + nn + r]);
                mma8(acc[j][0], acc[j][1], acc[j][2], acc[j][3], a0, a1, a2, a3, b0, b1);
            }
        }
        cpwait0(); __syncthreads();
    }

    // epilogue
    if (ocb == 0 && ms < 32) {
        float* fb = g_f + (size_t)b * CF * NPOS;
#pragma unroll
        for (int j = 0; j < 8; j++) {
            const int nn = nh * 32 + (j & 3) * 8 + (j >> 2) * 64;
            const int n = n0 + nn + 2 * c;
            *(float2*)&fb[(size_t)(ms + r) * NPOS + n] =
                make_float2(tf32r(acc[j][0]), tf32r(acc[j][1]));
            *(float2*)&fb[(size_t)(ms + r + 8) * NPOS + n] =
                make_float2(tf32r(acc[j][2]), tf32r(acc[j][3]));
        }
    } else {
        const int oc0 = ocb * 64 + ms + r;
#pragma unroll
        for (int j = 0; j < 4; j++) {
            float vlo = fmaxf(fmaxf(acc[j][0], acc[j][1]), fmaxf(acc[j + 4][0], acc[j + 4][1]));
            float vhi = fmaxf(fmaxf(acc[j][2], acc[j][3]), fmaxf(acc[j + 4][2], acc[j + 4][3]));
            const int pm = blockIdx.x * 32 + nh * 16 + j * 4 + c;
            if (ocb == 0) {
                float* dst = g_gp + ((size_t)b * CF + (oc0 - 32)) * MPOS;
                dst[pm] = tf32r(vlo);
                dst[8 * MPOS + pm] = tf32r(vhi);
            } else {
                __nv_bfloat16* dst = g_hp + ((size_t)b * CHD + (oc0 - 64)) * MPOS;
                dst[pm] = __float2bfloat16(vlo);
                dst[8 * MPOS + pm] = __float2bfloat16(vhi);
            }
        }
    }
}

// ============================================================
// Kernel C: attention. Score: tf32 m16n8k8. O-phase: bf16 m16n8k16.
// grid (64 q-tiles, 8 b), 256 thr = 8 warps, Mt=64, 16 m-tiles.
// hs: bf16 [c=128][m-pairs], stride 36 u32. ps: bf16 [n=64][m-pairs], 36 u32.
// ============================================================
#define FST 72
#define GST2 72
#define HSTU 36   // u32 stride (72 halfs)
#define PSTH 72   // half stride
#define KC_FS 0
#define KC_GS (32 * FST)
#define KC_HS (KC_GS + 32 * GST2)
#define KC_PS (KC_HS + 2 * 128 * HSTU)
#define KC_R4 (KC_PS + 64 * HSTU)
#define KC_RS (KC_R4 + 4 * 64)
#define SMEM_C_FLOATS (KC_RS + 64)
#define SMEM_C_BYTES (SMEM_C_FLOATS * 4)

__global__ __launch_bounds__(256, 3) void kC() {
    float* fs   = smc + KC_FS;                       // [k=32][72] fp32
    float* gs   = smc + KC_GS;                       // [k=32][72] fp32
    uint32_t* hs = (uint32_t*)(smc + KC_HS);         // 2 x [128][36] bf16x2
    uint32_t* psu = (uint32_t*)(smc + KC_PS);        // [64][36] bf16x2
    __nv_bfloat16* psh = (__nv_bfloat16*)(smc + KC_PS);
    float* r4   = smc + KC_R4;
    float* rsum = smc + KC_RS;

    const int b = blockIdx.y;
    const int n0 = blockIdx.x * 64;
    const int tid = threadIdx.x;
    const int w = tid >> 5, lane = tid & 31;
    const int r = lane >> 2, c = lane & 3;
    const float* gp = g_gp + (size_t)b * CF * MPOS;
    const __nv_bfloat16* hp = g_hp + (size_t)b * CHD * MPOS;
    const float* fp = g_f + (size_t)b * CF * NPOS + n0;

    // initial loads: fs + gs(t0) fp32, hs(t0) bf16
#pragma unroll
    for (int p = 0; p < 2; p++) {
        int idx = tid + p * 256; int rr = idx >> 4, cc = idx & 15;
        cpa16(&fs[rr * FST + cc * 4], &fp[(size_t)rr * NPOS + cc * 4]);
        cpa16(&gs[rr * GST2 + cc * 4], &gp[(size_t)rr * MPOS + cc * 4]);
    }
#pragma unroll
    for (int p = 0; p < 4; p++) {
        int idx = tid + p * 256; int rr = idx >> 3, cc = idx & 7;
        cpa16(&hs[rr * HSTU + cc * 4], &hp[(size_t)rr * MPOS + cc * 8]);
    }
    cpcommit();
    cpwait0(); __syncthreads();

    const int ms = (w & 3) * 16;
    const int nb = (w >> 2) * 32;
    const int cb = w * 16;

    float rs8[8];
#pragma unroll
    for (int i = 0; i < 8; i++) rs8[i] = 0.f;
    float oc[8][4];
#pragma unroll
    for (int i = 0; i < 8; i++)
#pragma unroll
        for (int j = 0; j < 4; j++) oc[i][j] = 0.f;

    for (int t = 0; t < 16; t++) {
        const int cur = t & 1;
        const uint32_t* hsc = hs + cur * 128 * HSTU;

        // prefetch hs(t+1) bf16 into alternate buffer
        if (t + 1 < 16) {
            const int m1 = (t + 1) * 64;
            uint32_t* hsd = hs + (cur ^ 1) * 128 * HSTU;
#pragma unroll
            for (int p = 0; p < 4; p++) {
                int idx = tid + p * 256; int rr = idx >> 3, cc = idx & 7;
                cpa16(&hsd[rr * HSTU + cc * 4], &hp[(size_t)rr * MPOS + m1 + cc * 8]);
            }
        }
        cpcommit();

        // ---- score mma (tf32): warp = m16 strip x n32 ----
        float sc[4][4];
#pragma unroll
        for (int j = 0; j < 4; j++)
#pragma unroll
            for (int q = 0; q < 4; q++) sc[j][q] = 0.f;
#pragma unroll
        for (int ks = 0; ks < 4; ks++) {
            const int k0 = ks * 8;
            uint32_t a0 = __float_as_uint(gs[(k0 + c) * GST2 + ms + r]);
            uint32_t a1 = __float_as_uint(gs[(k0 + c) * GST2 + ms + r + 8]);
            uint32_t a2 = __float_as_uint(gs[(k0 + c + 4) * GST2 + ms + r]);
            uint32_t a3 = __float_as_uint(gs[(k0 + c + 4) * GST2 + ms + r + 8]);
#pragma unroll
            for (int j = 0; j < 4; j++) {
                uint32_t b0 = __float_as_uint(fs[(k0 + c) * FST + nb + j * 8 + r]);
                uint32_t b1 = __float_as_uint(fs[(k0 + c + 4) * FST + nb + j * 8 + r]);
                mma8(sc[j][0], sc[j][1], sc[j][2], sc[j][3], a0, a1, a2, a3, b0, b1);
            }
        }

        // ---- exp, store P bf16 as [n][m], rowsum partials ----
#pragma unroll
        for (int j = 0; j < 4; j++) {
            float e0 = __expf(sc[j][0]);
            float e1 = __expf(sc[j][1]);
            float e2 = __expf(sc[j][2]);
            float e3 = __expf(sc[j][3]);
            const int n = nb + j * 8 + 2 * c;
            psh[(size_t)n * PSTH + ms + r]           = __float2bfloat16(e0);
            psh[(size_t)(n + 1) * PSTH + ms + r]     = __float2bfloat16(e1);
            psh[(size_t)n * PSTH + ms + r + 8]       = __float2bfloat16(e2);
            psh[(size_t)(n + 1) * PSTH + ms + r + 8] = __float2bfloat16(e3);
            float p0 = e0 + e2, p1 = e1 + e3;
#pragma unroll
            for (int off = 4; off < 32; off <<= 1) {
                p0 += __shfl_xor_sync(0xffffffffu, p0, off);
                p1 += __shfl_xor_sync(0xffffffffu, p1, off);
            }
            rs8[2 * j]     += p0;
            rs8[2 * j + 1] += p1;
        }
        __syncthreads();   // ps visible; gs free

        // prefetch gs(t+1)
        if (t + 1 < 16) {
            const int m1 = (t + 1) * 64;
#pragma unroll
            for (int p = 0; p < 2; p++) {
                int idx = tid + p * 256; int rr = idx >> 4, cc = idx & 15;
                cpa16(&gs[rr * GST2 + cc * 4], &gp[(size_t)rr * MPOS + m1 + cc * 4]);
            }
        }
        cpcommit();

        // ---- o mma (bf16 k16): warp = c16 x n64, m64 in 4 chunks ----
#pragma unroll
        for (int km = 0; km < 4; km++) {
            const int mo = km * 8;   // u32 offset (= 16 halfs)
            uint32_t a0 = hsc[(cb + r) * HSTU + mo + c];
            uint32_t a1 = hsc[(cb + r + 8) * HSTU + mo + c];
            uint32_t a2 = hsc[(cb + r) * HSTU + mo + c + 4];
            uint32_t a3 = hsc[(cb + r + 8) * HSTU + mo + c + 4];
#pragma unroll
            for (int j = 0; j < 8; j++) {
                uint32_t b0 = psu[(j * 8 + r) * HSTU + mo + c];
                uint32_t b1 = psu[(j * 8 + r) * HSTU + mo + c + 4];
                mma16b(oc[j][0], oc[j][1], oc[j][2], oc[j][3], a0, a1, a2, a3, b0, b1);
            }
        }
        cpwait0();
        __syncthreads();   // next tiles resident; ps free
    }

    // ---- rowsum combine across the 4 m-strip warps ----
    if (r == 0) {
#pragma unroll
        for (int j = 0; j < 4; j++) {
            r4[(w & 3) * 64 + nb + j * 8 + 2 * c]     = rs8[2 * j];
            r4[(w & 3) * 64 + nb + j * 8 + 2 * c + 1] = rs8[2 * j + 1];
        }
    }
    __syncthreads();
    if (tid < 64)
        rsum[tid] = 1.f / (r4[tid] + r4[64 + tid] + r4[128 + tid] + r4[192 + tid]);
    __syncthreads();

    // ---- normalize + store O (tf32-rounded fp32) ----
    float* ob = g_o + (size_t)b * CHD * NPOS + n0;
#pragma unroll
    for (int j = 0; j < 8; j++) {
        const int n = j * 8 + 2 * c;
        float i0 = rsum[n], i1 = rsum[n + 1];
        *(float2*)&ob[(size_t)(cb + r) * NPOS + n] =
            make_float2(tf32r(oc[j][0] * i0), tf32r(oc[j][1] * i1));
        *(float2*)&ob[(size_t)(cb + r + 8) * NPOS + n] =
            make_float2(tf32r(oc[j][2] * i0), tf32r(oc[j][3] * i1));
    }
}

// ============================================================
// Kernel D: out = gamma * (Wo @ o) + x via tf32 mma, raw Wo loads.
// grid (32 n-tiles of 128, 4 oc-tiles of 64, 8 b), 256 thr = 8 warps.
// ============================================================
#define KD_WS 0
#define KD_XS (2 * 64 * WST)
#define SMEM_D_BYTES ((KD_XS + 2 * 32 * AXST) * 4)

__global__ __launch_bounds__(256, 3) void kD(const float* __restrict__ x,
                                             const float* __restrict__ Wo,
                                             const float* __restrict__ gptr,
                                             float* __restrict__ out) {
    float* Ws = smc + KD_WS;   // 2 x [64][36]  ([oc][k] chunk)
    float* os = smc + KD_XS;   // 2 x [32][136] ([k][n])
    const int b = blockIdx.z, ocb = blockIdx.y;
    const int n0 = blockIdx.x * 128;
    const int tid = threadIdx.x;
    const int w = tid >> 5, lane = tid & 31;
    const int r = lane >> 2, c = lane & 3;
    const int ms = (w & 3) * 16, nh = w >> 2;
    const float gamma = *gptr;
    const float* ob = g_o + (size_t)b * CHD * NPOS;
    const float* wbase = Wo + (size_t)ocb * 64 * CHD;

    float acc[8][4];
#pragma unroll
    for (int j = 0; j < 8; j++)
#pragma unroll
        for (int q = 0; q < 4; q++) acc[j][q] = 0.f;

#pragma unroll
    for (int p = 0; p < 2; p++) {
        int idx = tid + p * 256; int row = idx >> 3, cc = idx & 7;
        cpa16(&Ws[row * WST + cc * 4], &wbase[(size_t)row * CHD + cc * 4]);
    }
#pragma unroll
    for (int p = 0; p < 4; p++) {
        int idx = tid + p * 256; int kk = idx >> 5, cc = idx & 31;
        cpa16(&os[kk * AXST + cc * 4], &ob[(size_t)kk * NPOS + n0 + cc * 4]);
    }
    cpcommit();
    cpwait0(); __syncthreads();

    for (int it = 0; it < 4; it++) {
        const int cur = it & 1;
        if (it + 1 < 4) {
            const int nxt = cur ^ 1, k0g = (it + 1) * 32;
            float* Wd = Ws + nxt * 64 * WST;
            float* xd = os + nxt * 32 * AXST;
#pragma unroll
            for (int p = 0; p < 2; p++) {
                int idx = tid + p * 256; int row = idx >> 3, cc = idx & 7;
                cpa16(&Wd[row * WST + cc * 4], &wbase[(size_t)row * CHD + k0g + cc * 4]);
            }
#pragma unroll
            for (int p = 0; p < 4; p++) {
                int idx = tid + p * 256; int kk = idx >> 5, cc = idx & 31;
                cpa16(&xd[kk * AXST + cc * 4], &ob[(size_t)(k0g + kk) * NPOS + n0 + cc * 4]);
            }
        }
        cpcommit();

        const float* Wc = Ws + cur * 64 * WST;
        const float* xc = os + cur * 32 * AXST;
#pragma unroll
        for (int ks = 0; ks < 4; ks++) {
            const int k0 = ks * 8;
            uint32_t a0 = __float_as_uint(Wc[(ms + r) * WST + k0 + c]);
            uint32_t a1 = __float_as_uint(Wc[(ms + r + 8) * WST + k0 + c]);
            uint32_t a2 = __float_as_uint(Wc[(ms + r) * WST + k0 + c + 4]);
            uint32_t a3 = __float_as_uint(Wc[(ms + r + 8) * WST + k0 + c + 4]);
#pragma unroll
            for (int j = 0; j < 8; j++) {
                const int nn = nh * 32 + (j & 3) * 8 + (j >> 2) * 64;
                uint32_t b0 = __float_as_uint(xc[(k0 + c) * AXST + nn + r]);
                uint32_t b1 = __float_as_uint(xc[(k0 + c + 4) * AXST + nn + r]);
                mma8(acc[j][0], acc[j][1], acc[j][2], acc[j][3], a0, a1, a2, a3, b0, b1);
            }
        }
        cpwait0(); __syncthreads();
    }

    const float* xb = x + (size_t)b * CC * NPOS;
    float* outb = out + (size_t)b * CC * NPOS;
    const int oc0 = ocb * 64 + ms + r;
#pragma unroll
    for (int j = 0; j < 8; j++) {
        const int nn = nh * 32 + (j & 3) * 8 + (j >> 2) * 64;
        const int n = n0 + nn + 2 * c;
        size_t p0 = (size_t)oc0 * NPOS + n;
        size_t p1 = (size_t)(oc0 + 8) * NPOS + n;
        float2 x0 = *(const float2*)&xb[p0];
        float2 x1 = *(const float2*)&xb[p1];
        *(float2*)&outb[p0] = make_float2(fmaf(gamma, acc[j][0], x0.x),
                                          fmaf(gamma, acc[j][1], x0.y));
        *(float2*)&outb[p1] = make_float2(fmaf(gamma, acc[j][2], x1.x),
                                          fmaf(gamma, acc[j][3], x1.y));
    }
}

// ============================================================
extern "C" void kernel_launch(void* const* d_in, const int* in_sizes, int n_in,
                              void* d_out, int out_size) {
    const float* x     = (const float*)d_in[0];
    const float* Wf    = (const float*)d_in[1];
    const float* Wg    = (const float*)d_in[2];
    const float* Wh    = (const float*)d_in[3];
    const float* Wo    = (const float*)d_in[4];
    const float* gamma = (const float*)d_in[5];
    float* out = (float*)d_out;

    cudaFuncSetAttribute(kA, cudaFuncAttributeMaxDynamicSharedMemorySize, SMEM_A_BYTES);
    cudaFuncSetAttribute(kC, cudaFuncAttributeMaxDynamicSharedMemorySize, SMEM_C_BYTES);
    cudaFuncSetAttribute(kD, cudaFuncAttributeMaxDynamicSharedMemorySize, SMEM_D_BYTES);

    kA<<<dim3(32, 3, 8), 256, SMEM_A_BYTES>>>(x, Wf, Wg, Wh);
    kC<<<dim3(64, 8), 256, SMEM_C_BYTES>>>();
    kD<<<dim3(32, 4, 8), 256, SMEM_D_BYTES>>>(x, Wo, gamma, out);
}

// round 9
// speedup vs baseline: 3.7752x; 1.0194x over previous
#include <cuda_runtime.h>
#include <cuda_bf16.h>
#include <cstdint>

#define BB 8
#define CC 256
#define NPOS 4096   // 64*64
#define MPOS 1024   // 32*32
#define CF 32       // C/8
#define CHD 128     // C/2

// ---- scratch (static device globals; no allocation) ----
__device__ float g_f[(size_t)BB * CF * NPOS];                 // f (tf32-rounded fp32)
__device__ float g_gp[(size_t)BB * CF * MPOS];                // pooled g (tf32-rounded fp32)
__device__ __nv_bfloat16 g_hp[(size_t)BB * CHD * MPOS];       // pooled h (bf16)
__device__ float g_o[(size_t)BB * CHD * NPOS];                // attention out (tf32-rounded fp32)

// ---- helpers ----
__device__ __forceinline__ void cpa16(void* s, const void* g) {
    unsigned sa = (unsigned)__cvta_generic_to_shared(s);
    asm volatile("cp.async.ca.shared.global [%0], [%1], 16;\n" :: "r"(sa), "l"(g));
}
__device__ __forceinline__ void cpcommit() { asm volatile("cp.async.commit_group;\n" ::); }
__device__ __forceinline__ void cpwait0()  { asm volatile("cp.async.wait_group 0;\n" ::); }

__device__ __forceinline__ float tf32r(float x) {
    uint32_t u;
    asm("cvt.rna.tf32.f32 %0, %1;" : "=r"(u) : "f"(x));
    return __uint_as_float(u);
}

__device__ __forceinline__ void mma8(float& c0, float& c1, float& c2, float& c3,
                                     uint32_t a0, uint32_t a1, uint32_t a2, uint32_t a3,
                                     uint32_t b0, uint32_t b1) {
    asm volatile("mma.sync.aligned.m16n8k8.row.col.f32.tf32.tf32.f32 "
                 "{%0,%1,%2,%3}, {%4,%5,%6,%7}, {%8,%9}, {%0,%1,%2,%3};"
                 : "+f"(c0), "+f"(c1), "+f"(c2), "+f"(c3)
                 : "r"(a0), "r"(a1), "r"(a2), "r"(a3), "r"(b0), "r"(b1));
}

__device__ __forceinline__ void mma16b(float& c0, float& c1, float& c2, float& c3,
                                       uint32_t a0, uint32_t a1, uint32_t a2, uint32_t a3,
                                       uint32_t b0, uint32_t b1) {
    asm volatile("mma.sync.aligned.m16n8k16.row.col.f32.bf16.bf16.f32 "
                 "{%0,%1,%2,%3}, {%4,%5,%6,%7}, {%8,%9}, {%0,%1,%2,%3};"
                 : "+f"(c0), "+f"(c1), "+f"(c2), "+f"(c3)
                 : "r"(a0), "r"(a1), "r"(a2), "r"(a3), "r"(b0), "r"(b1));
}

__device__ __forceinline__ void ldm4(uint32_t& r0, uint32_t& r1, uint32_t& r2, uint32_t& r3,
                                     uint32_t saddr) {
    asm volatile("ldmatrix.sync.aligned.m8n8.x4.shared.b16 {%0,%1,%2,%3}, [%4];"
                 : "=r"(r0), "=r"(r1), "=r"(r2), "=r"(r3) : "r"(saddr));
}

extern __shared__ float smc[];

// ============================================================
// Kernel A: [f;g;h] = Wcat @ x via tf32 mma, raw-weight loads,
// pooled epilogue (g fp32, h bf16).
// grid (32 n-tiles of 128, 3 oc-tiles of 64, 8 b), 256 thr = 8 warps.
// ============================================================
#define WST 36
#define AXST 136
#define KA_WS 0
#define KA_XS (2 * 64 * WST)
#define SMEM_A_BYTES ((KA_XS + 2 * 32 * AXST) * 4)

__global__ __launch_bounds__(256, 4) void kA(const float* __restrict__ x,
                                             const float* __restrict__ Wf,
                                             const float* __restrict__ Wg,
                                             const float* __restrict__ Wh) {
    float* Ws = smc + KA_WS;   // 2 x [64][36]
    float* xs = smc + KA_XS;   // 2 x [32][136]
    const int b = blockIdx.z, ocb = blockIdx.y;
    const int n0 = blockIdx.x * 128;
    const int tid = threadIdx.x;
    const int w = tid >> 5, lane = tid & 31;
    const int r = lane >> 2, c = lane & 3;
    const int ms = (w & 3) * 16, nh = w >> 2;
    const float* xb = x + (size_t)b * CC * NPOS;

    float acc[8][4];
#pragma unroll
    for (int j = 0; j < 8; j++)
#pragma unroll
        for (int q = 0; q < 4; q++) acc[j][q] = 0.f;

    auto wrow = [&](int row) -> const float* {
        if (ocb == 0) return (row < 32) ? Wf + (size_t)row * 256 : Wg + (size_t)(row - 32) * 256;
        return Wh + (size_t)((ocb - 1) * 64 + row) * 256;
    };

#pragma unroll
    for (int p = 0; p < 2; p++) {
        int idx = tid + p * 256; int row = idx >> 3, cc = idx & 7;
        cpa16(&Ws[row * WST + cc * 4], wrow(row) + cc * 4);
    }
#pragma unroll
    for (int p = 0; p < 4; p++) {
        int idx = tid + p * 256; int kk = idx >> 5, cc = idx & 31;
        cpa16(&xs[kk * AXST + cc * 4], &xb[(size_t)kk * NPOS + n0 + cc * 4]);
    }
    cpcommit();
    cpwait0(); __syncthreads();

    for (int it = 0; it < 8; it++) {
        const int cur = it & 1;
        if (it + 1 < 8) {
            const int nxt = cur ^ 1, k0g = (it + 1) * 32;
            float* Wd = Ws + nxt * 64 * WST;
            float* xd = xs + nxt * 32 * AXST;
#pragma unroll
            for (int p = 0; p < 2; p++) {
                int idx = tid + p * 256; int row = idx >> 3, cc = idx & 7;
                cpa16(&Wd[row * WST + cc * 4], wrow(row) + k0g + cc * 4);
            }
#pragma unroll
            for (int p = 0; p < 4; p++) {
                int idx = tid + p * 256; int kk = idx >> 5, cc = idx & 31;
                cpa16(&xd[kk * AXST + cc * 4], &xb[(size_t)(k0g + kk) * NPOS + n0 + cc * 4]);
            }
        }
        cpcommit();

        const float* Wc = Ws + cur * 64 * WST;
        const float* xc = xs + cur * 32 * AXST;
#pragma unroll
        for (int ks = 0; ks < 4; ks++) {
            const int k0 = ks * 8;
            uint32_t a0 = __float_as_uint(Wc[(ms + r) * WST + k0 + c]);
            uint32_t a1 = __float_as_uint(Wc[(ms + r + 8) * WST + k0 + c]);
            uint32_t a2 = __float_as_uint(Wc[(ms + r) * WST + k0 + c + 4]);
            uint32_t a3 = __float_as_uint(Wc[(ms + r + 8) * WST + k0 + c + 4]);
#pragma unroll
            for (int j = 0; j < 8; j++) {
                const int nn = nh * 32 + (j & 3) * 8 + (j >> 2) * 64;
                uint32_t b0 = __float_as_uint(xc[(k0 + c) * AXST + nn + r]);
                uint32_t b1 = __float_as_uint(xc[(k0 + c + 4) * AXST + nn + r]);
                mma8(acc[j][0], acc[j][1], acc[j][2], acc[j][3], a0, a1, a2, a3, b0, b1);
            }
        }
        cpwait0(); __syncthreads();
    }

    // epilogue
    if (ocb == 0 && ms < 32) {
        float* fb = g_f + (size_t)b * CF * NPOS;
#pragma unroll
        for (int j = 0; j < 8; j++) {
            const int nn = nh * 32 + (j & 3) * 8 + (j >> 2) * 64;
            const int n = n0 + nn + 2 * c;
            *(float2*)&fb[(size_t)(ms + r) * NPOS + n] =
                make_float2(tf32r(acc[j][0]), tf32r(acc[j][1]));
            *(float2*)&fb[(size_t)(ms + r + 8) * NPOS + n] =
                make_float2(tf32r(acc[j][2]), tf32r(acc[j][3]));
        }
    } else {
        const int oc0 = ocb * 64 + ms + r;
#pragma unroll
        for (int j = 0; j < 4; j++) {
            float vlo = fmaxf(fmaxf(acc[j][0], acc[j][1]), fmaxf(acc[j + 4][0], acc[j + 4][1]));
            float vhi = fmaxf(fmaxf(acc[j][2], acc[j][3]), fmaxf(acc[j + 4][2], acc[j + 4][3]));
            const int pm = blockIdx.x * 32 + nh * 16 + j * 4 + c;
            if (ocb == 0) {
                float* dst = g_gp + ((size_t)b * CF + (oc0 - 32)) * MPOS;
                dst[pm] = tf32r(vlo);
                dst[8 * MPOS + pm] = tf32r(vhi);
            } else {
                __nv_bfloat16* dst = g_hp + ((size_t)b * CHD + (oc0 - 64)) * MPOS;
                dst[pm] = __float2bfloat16(vlo);
                dst[8 * MPOS + pm] = __float2bfloat16(vhi);
            }
        }
    }
}

// ============================================================
// Kernel C: attention. Score: tf32 m16n8k8. O-phase: bf16 m16n8k16
// with ldmatrix fragment loads.
// grid (64 q-tiles, 8 b), 256 thr = 8 warps, Mt=64, 16 m-tiles.
// ============================================================
#define FST 72
#define GST2 72
#define HSTU 36   // u32 stride (72 halfs)
#define PSTH 72   // half stride
#define KC_FS 0
#define KC_GS (32 * FST)
#define KC_HS (KC_GS + 32 * GST2)
#define KC_PS (KC_HS + 2 * 128 * HSTU)
#define KC_R4 (KC_PS + 64 * HSTU)
#define KC_RS (KC_R4 + 4 * 64)
#define SMEM_C_FLOATS (KC_RS + 64)
#define SMEM_C_BYTES (SMEM_C_FLOATS * 4)

__global__ __launch_bounds__(256, 3) void kC() {
    float* fs   = smc + KC_FS;                       // [k=32][72] fp32
    float* gs   = smc + KC_GS;                       // [k=32][72] fp32
    uint32_t* hs = (uint32_t*)(smc + KC_HS);         // 2 x [128][36] bf16x2
    uint32_t* psu = (uint32_t*)(smc + KC_PS);        // [64][36] bf16x2
    __nv_bfloat16* psh = (__nv_bfloat16*)(smc + KC_PS);
    float* r4   = smc + KC_R4;
    float* rsum = smc + KC_RS;

    const int b = blockIdx.y;
    const int n0 = blockIdx.x * 64;
    const int tid = threadIdx.x;
    const int w = tid >> 5, lane = tid & 31;
    const int r = lane >> 2, c = lane & 3;
    const float* gp = g_gp + (size_t)b * CF * MPOS;
    const __nv_bfloat16* hp = g_hp + (size_t)b * CHD * MPOS;
    const float* fp = g_f + (size_t)b * CF * NPOS + n0;

#pragma unroll
    for (int p = 0; p < 2; p++) {
        int idx = tid + p * 256; int rr = idx >> 4, cc = idx & 15;
        cpa16(&fs[rr * FST + cc * 4], &fp[(size_t)rr * NPOS + cc * 4]);
        cpa16(&gs[rr * GST2 + cc * 4], &gp[(size_t)rr * MPOS + cc * 4]);
    }
#pragma unroll
    for (int p = 0; p < 4; p++) {
        int idx = tid + p * 256; int rr = idx >> 3, cc = idx & 7;
        cpa16(&hs[rr * HSTU + cc * 4], &hp[(size_t)rr * MPOS + cc * 8]);
    }
    cpcommit();
    cpwait0(); __syncthreads();

    const int ms = (w & 3) * 16;
    const int nb = (w >> 2) * 32;
    const int cb = w * 16;

    // ldmatrix per-lane offsets (u32 units)
    const int i7 = lane & 7, s2 = (lane >> 3) & 1, s4 = lane >> 4;
    const uint32_t a_off = (uint32_t)((cb + s2 * 8 + i7) * HSTU + s4 * 4);
    const uint32_t b_off = (uint32_t)((s4 * 8 + i7) * HSTU + s2 * 4);
    const uint32_t ps_sb = (uint32_t)__cvta_generic_to_shared(psu);

    float rs8[8];
#pragma unroll
    for (int i = 0; i < 8; i++) rs8[i] = 0.f;
    float oc[8][4];
#pragma unroll
    for (int i = 0; i < 8; i++)
#pragma unroll
        for (int j = 0; j < 4; j++) oc[i][j] = 0.f;

    for (int t = 0; t < 16; t++) {
        const int cur = t & 1;
        const uint32_t* hsc = hs + cur * 128 * HSTU;

        // prefetch hs(t+1) bf16 into alternate buffer
        if (t + 1 < 16) {
            const int m1 = (t + 1) * 64;
            uint32_t* hsd = hs + (cur ^ 1) * 128 * HSTU;
#pragma unroll
            for (int p = 0; p < 4; p++) {
                int idx = tid + p * 256; int rr = idx >> 3, cc = idx & 7;
                cpa16(&hsd[rr * HSTU + cc * 4], &hp[(size_t)rr * MPOS + m1 + cc * 8]);
            }
        }
        cpcommit();

        // ---- score mma (tf32): warp = m16 strip x n32 ----
        float sc[4][4];
#pragma unroll
        for (int j = 0; j < 4; j++)
#pragma unroll
            for (int q = 0; q < 4; q++) sc[j][q] = 0.f;
#pragma unroll
        for (int ks = 0; ks < 4; ks++) {
            const int k0 = ks * 8;
            uint32_t a0 = __float_as_uint(gs[(k0 + c) * GST2 + ms + r]);
            uint32_t a1 = __float_as_uint(gs[(k0 + c) * GST2 + ms + r + 8]);
            uint32_t a2 = __float_as_uint(gs[(k0 + c + 4) * GST2 + ms + r]);
            uint32_t a3 = __float_as_uint(gs[(k0 + c + 4) * GST2 + ms + r + 8]);
#pragma unroll
            for (int j = 0; j < 4; j++) {
                uint32_t b0 = __float_as_uint(fs[(k0 + c) * FST + nb + j * 8 + r]);
                uint32_t b1 = __float_as_uint(fs[(k0 + c + 4) * FST + nb + j * 8 + r]);
                mma8(sc[j][0], sc[j][1], sc[j][2], sc[j][3], a0, a1, a2, a3, b0, b1);
            }
        }

        // ---- exp, store P bf16 as [n][m], rowsum partials ----
#pragma unroll
        for (int j = 0; j < 4; j++) {
            float e0 = __expf(sc[j][0]);
            float e1 = __expf(sc[j][1]);
            float e2 = __expf(sc[j][2]);
            float e3 = __expf(sc[j][3]);
            const int n = nb + j * 8 + 2 * c;
            psh[(size_t)n * PSTH + ms + r]           = __float2bfloat16(e0);
            psh[(size_t)(n + 1) * PSTH + ms + r]     = __float2bfloat16(e1);
            psh[(size_t)n * PSTH + ms + r + 8]       = __float2bfloat16(e2);
            psh[(size_t)(n + 1) * PSTH + ms + r + 8] = __float2bfloat16(e3);
            float p0 = e0 + e2, p1 = e1 + e3;
#pragma unroll
            for (int off = 4; off < 32; off <<= 1) {
                p0 += __shfl_xor_sync(0xffffffffu, p0, off);
                p1 += __shfl_xor_sync(0xffffffffu, p1, off);
            }
            rs8[2 * j]     += p0;
            rs8[2 * j + 1] += p1;
        }
        __syncthreads();   // ps visible; gs free

        // prefetch gs(t+1)
        if (t + 1 < 16) {
            const int m1 = (t + 1) * 64;
#pragma unroll
            for (int p = 0; p < 2; p++) {
                int idx = tid + p * 256; int rr = idx >> 4, cc = idx & 15;
                cpa16(&gs[rr * GST2 + cc * 4], &gp[(size_t)rr * MPOS + m1 + cc * 4]);
            }
        }
        cpcommit();

        // ---- o mma (bf16 k16, ldmatrix): warp = c16 x n64 ----
        {
            const uint32_t hs_sb = (uint32_t)__cvta_generic_to_shared(hsc);
#pragma unroll
            for (int km = 0; km < 4; km++) {
                const uint32_t mo = km * 8;
                uint32_t a0, a1, a2, a3;
                ldm4(a0, a1, a2, a3, hs_sb + (a_off + mo) * 4);
#pragma unroll
                for (int jp = 0; jp < 4; jp++) {
                    uint32_t b0, b1, b2, b3;
                    ldm4(b0, b1, b2, b3, ps_sb + (b_off + jp * 16 * HSTU + mo) * 4);
                    mma16b(oc[2 * jp][0], oc[2 * jp][1], oc[2 * jp][2], oc[2 * jp][3],
                           a0, a1, a2, a3, b0, b1);
                    mma16b(oc[2 * jp + 1][0], oc[2 * jp + 1][1], oc[2 * jp + 1][2], oc[2 * jp + 1][3],
                           a0, a1, a2, a3, b2, b3);
                }
            }
        }
        cpwait0();
        __syncthreads();   // next tiles resident; ps free
    }

    // ---- rowsum combine across the 4 m-strip warps ----
    if (r == 0) {
#pragma unroll
        for (int j = 0; j < 4; j++) {
            r4[(w & 3) * 64 + nb + j * 8 + 2 * c]     = rs8[2 * j];
            r4[(w & 3) * 64 + nb + j * 8 + 2 * c + 1] = rs8[2 * j + 1];
        }
    }
    __syncthreads();
    if (tid < 64)
        rsum[tid] = 1.f / (r4[tid] + r4[64 + tid] + r4[128 + tid] + r4[192 + tid]);
    __syncthreads();

    // ---- normalize + store O (tf32-rounded fp32) ----
    float* ob = g_o + (size_t)b * CHD * NPOS + n0;
#pragma unroll
    for (int j = 0; j < 8; j++) {
        const int n = j * 8 + 2 * c;
        float i0 = rsum[n], i1 = rsum[n + 1];
        *(float2*)&ob[(size_t)(cb + r) * NPOS + n] =
            make_float2(tf32r(oc[j][0] * i0), tf32r(oc[j][1] * i1));
        *(float2*)&ob[(size_t)(cb + r + 8) * NPOS + n] =
            make_float2(tf32r(oc[j][2] * i0), tf32r(oc[j][3] * i1));
    }
}

// ============================================================
// Kernel D: out = gamma * (Wo @ o) + x via tf32 mma, raw Wo loads.
// grid (32 n-tiles of 128, 4 oc-tiles of 64, 8 b), 256 thr = 8 warps.
// ============================================================
#define KD_WS 0
#define KD_XS (2 * 64 * WST)
#define SMEM_D_BYTES ((KD_XS + 2 * 32 * AXST) * 4)

__global__ __launch_bounds__(256, 4) void kD(const float* __restrict__ x,
                                             const float* __restrict__ Wo,
                                             const float* __restrict__ gptr,
                                             float* __restrict__ out) {
    float* Ws = smc + KD_WS;   // 2 x [64][36]  ([oc][k] chunk)
    float* os = smc + KD_XS;   // 2 x [32][136] ([k][n])
    const int b = blockIdx.z, ocb = blockIdx.y;
    const int n0 = blockIdx.x * 128;
    const int tid = threadIdx.x;
    const int w = tid >> 5, lane = tid & 31;
    const int r = lane >> 2, c = lane & 3;
    const int ms = (w & 3) * 16, nh = w >> 2;
    const float gamma = *gptr;
    const float* ob = g_o + (size_t)b * CHD * NPOS;
    const float* wbase = Wo + (size_t)ocb * 64 * CHD;

    float acc[8][4];
#pragma unroll
    for (int j = 0; j < 8; j++)
#pragma unroll
        for (int q = 0; q < 4; q++) acc[j][q] = 0.f;

#pragma unroll
    for (int p = 0; p < 2; p++) {
        int idx = tid + p * 256; int row = idx >> 3, cc = idx & 7;
        cpa16(&Ws[row * WST + cc * 4], &wbase[(size_t)row * CHD + cc * 4]);
    }
#pragma unroll
    for (int p = 0; p < 4; p++) {
        int idx = tid + p * 256; int kk = idx >> 5, cc = idx & 31;
        cpa16(&os[kk * AXST + cc * 4], &ob[(size_t)kk * NPOS + n0 + cc * 4]);
    }
    cpcommit();
    cpwait0(); __syncthreads();

    for (int it = 0; it < 4; it++) {
        const int cur = it & 1;
        if (it + 1 < 4) {
            const int nxt = cur ^ 1, k0g = (it + 1) * 32;
            float* Wd = Ws + nxt * 64 * WST;
            float* xd = os + nxt * 32 * AXST;
#pragma unroll
            for (int p = 0; p < 2; p++) {
                int idx = tid + p * 256; int row = idx >> 3, cc = idx & 7;
                cpa16(&Wd[row * WST + cc * 4], &wbase[(size_t)row * CHD + k0g + cc * 4]);
            }
#pragma unroll
            for (int p = 0; p < 4; p++) {
                int idx = tid + p * 256; int kk = idx >> 5, cc = idx & 31;
                cpa16(&xd[kk * AXST + cc * 4], &ob[(size_t)(k0g + kk) * NPOS + n0 + cc * 4]);
            }
        }
        cpcommit();

        const float* Wc = Ws + cur * 64 * WST;
        const float* xc = os + cur * 32 * AXST;
#pragma unroll
        for (int ks = 0; ks < 4; ks++) {
            const int k0 = ks * 8;
            uint32_t a0 = __float_as_uint(Wc[(ms + r) * WST + k0 + c]);
            uint32_t a1 = __float_as_uint(Wc[(ms + r + 8) * WST + k0 + c]);
            uint32_t a2 = __float_as_uint(Wc[(ms + r) * WST + k0 + c + 4]);
            uint32_t a3 = __float_as_uint(Wc[(ms + r + 8) * WST + k0 + c + 4]);
#pragma unroll
            for (int j = 0; j < 8; j++) {
                const int nn = nh * 32 + (j & 3) * 8 + (j >> 2) * 64;
                uint32_t b0 = __float_as_uint(xc[(k0 + c) * AXST + nn + r]);
                uint32_t b1 = __float_as_uint(xc[(k0 + c + 4) * AXST + nn + r]);
                mma8(acc[j][0], acc[j][1], acc[j][2], acc[j][3], a0, a1, a2, a3, b0, b1);
            }
        }
        cpwait0(); __syncthreads();
    }

    const float* xb = x + (size_t)b * CC * NPOS;
    float* outb = out + (size_t)b * CC * NPOS;
    const int oc0 = ocb * 64 + ms + r;
#pragma unroll
    for (int j = 0; j < 8; j++) {
        const int nn = nh * 32 + (j & 3) * 8 + (j >> 2) * 64;
        const int n = n0 + nn + 2 * c;
        size_t p0 = (size_t)oc0 * NPOS + n;
        size_t p1 = (size_t)(oc0 + 8) * NPOS + n;
        float2 x0 = *(const float2*)&xb[p0];
        float2 x1 = *(const float2*)&xb[p1];
        *(float2*)&outb[p0] = make_float2(fmaf(gamma, acc[j][0], x0.x),
                                          fmaf(gamma, acc[j][1], x0.y));
        *(float2*)&outb[p1] = make_float2(fmaf(gamma, acc[j][2], x1.x),
                                          fmaf(gamma, acc[j][3], x1.y));
    }
}

// ============================================================
extern "C" void kernel_launch(void* const* d_in, const int* in_sizes, int n_in,
                              void* d_out, int out_size) {
    const float* x     = (const float*)d_in[0];
    const float* Wf    = (const float*)d_in[1];
    const float* Wg    = (const float*)d_in[2];
    const float* Wh    = (const float*)d_in[3];
    const float* Wo    = (const float*)d_in[4];
    const float* gamma = (const float*)d_in[5];
    float* out = (float*)d_out;

    cudaFuncSetAttribute(kA, cudaFuncAttributeMaxDynamicSharedMemorySize, SMEM_A_BYTES);
    cudaFuncSetAttribute(kC, cudaFuncAttributeMaxDynamicSharedMemorySize, SMEM_C_BYTES);
    cudaFuncSetAttribute(kD, cudaFuncAttributeMaxDynamicSharedMemorySize, SMEM_D_BYTES);

    kA<<<dim3(32, 3, 8), 256, SMEM_A_BYTES>>>(x, Wf, Wg, Wh);
    kC<<<dim3(64, 8), 256, SMEM_C_BYTES>>>();
    kD<<<dim3(32, 4, 8), 256, SMEM_D_BYTES>>>(x, Wo, gamma, out);
}

// round 10
// speedup vs baseline: 4.2413x; 1.1235x over previous
#include <cuda_runtime.h>
#include <cuda_bf16.h>
#include <cstdint>

#define BB 8
#define CC 256
#define NPOS 4096   // 64*64
#define MPOS 1024   // 32*32
#define CF 32       // C/8
#define CHD 128     // C/2

// ---- scratch (static device globals; no allocation) ----
__device__ float g_f[(size_t)BB * CF * NPOS];                      // f (tf32-rounded fp32)
__device__ float g_gp[(size_t)BB * CF * MPOS];                     // pooled g (tf32-rounded fp32)
__device__ __align__(16) __nv_bfloat16 g_hp[(size_t)BB * CHD * MPOS];   // pooled h (bf16)
__device__ __align__(16) __nv_bfloat16 g_ob[(size_t)BB * NPOS * CHD];   // attention out, [b][n][c] bf16

// ---- helpers ----
__device__ __forceinline__ void cpa16(void* s, const void* g) {
    unsigned sa = (unsigned)__cvta_generic_to_shared(s);
    asm volatile("cp.async.ca.shared.global [%0], [%1], 16;\n" :: "r"(sa), "l"(g));
}
__device__ __forceinline__ void cpcommit() { asm volatile("cp.async.commit_group;\n" ::); }
__device__ __forceinline__ void cpwait0()  { asm volatile("cp.async.wait_group 0;\n" ::); }

__device__ __forceinline__ float tf32r(float x) {
    uint32_t u;
    asm("cvt.rna.tf32.f32 %0, %1;" : "=r"(u) : "f"(x));
    return __uint_as_float(u);
}

__device__ __forceinline__ void mma8(float& c0, float& c1, float& c2, float& c3,
                                     uint32_t a0, uint32_t a1, uint32_t a2, uint32_t a3,
                                     uint32_t b0, uint32_t b1) {
    asm volatile("mma.sync.aligned.m16n8k8.row.col.f32.tf32.tf32.f32 "
                 "{%0,%1,%2,%3}, {%4,%5,%6,%7}, {%8,%9}, {%0,%1,%2,%3};"
                 : "+f"(c0), "+f"(c1), "+f"(c2), "+f"(c3)
                 : "r"(a0), "r"(a1), "r"(a2), "r"(a3), "r"(b0), "r"(b1));
}

__device__ __forceinline__ void mma16b(float& c0, float& c1, float& c2, float& c3,
                                       uint32_t a0, uint32_t a1, uint32_t a2, uint32_t a3,
                                       uint32_t b0, uint32_t b1) {
    asm volatile("mma.sync.aligned.m16n8k16.row.col.f32.bf16.bf16.f32 "
                 "{%0,%1,%2,%3}, {%4,%5,%6,%7}, {%8,%9}, {%0,%1,%2,%3};"
                 : "+f"(c0), "+f"(c1), "+f"(c2), "+f"(c3)
                 : "r"(a0), "r"(a1), "r"(a2), "r"(a3), "r"(b0), "r"(b1));
}

__device__ __forceinline__ void ldm4(uint32_t& r0, uint32_t& r1, uint32_t& r2, uint32_t& r3,
                                     uint32_t saddr) {
    asm volatile("ldmatrix.sync.aligned.m8n8.x4.shared.b16 {%0,%1,%2,%3}, [%4];"
                 : "=r"(r0), "=r"(r1), "=r"(r2), "=r"(r3) : "r"(saddr));
}

extern __shared__ float smc[];

// ============================================================
// Kernel A: [f;g;h] = Wcat @ x via tf32 mma, raw-weight loads,
// pooled epilogue (g fp32, h bf16). (R8 config: 3 blocks/SM)
// ============================================================
#define WST 36
#define AXST 136
#define KA_WS 0
#define KA_XS (2 * 64 * WST)
#define SMEM_A_BYTES ((KA_XS + 2 * 32 * AXST) * 4)

__global__ __launch_bounds__(256, 3) void kA(const float* __restrict__ x,
                                             const float* __restrict__ Wf,
                                             const float* __restrict__ Wg,
                                             const float* __restrict__ Wh) {
    float* Ws = smc + KA_WS;   // 2 x [64][36]
    float* xs = smc + KA_XS;   // 2 x [32][136]
    const int b = blockIdx.z, ocb = blockIdx.y;
    const int n0 = blockIdx.x * 128;
    const int tid = threadIdx.x;
    const int w = tid >> 5, lane = tid & 31;
    const int r = lane >> 2, c = lane & 3;
    const int ms = (w & 3) * 16, nh = w >> 2;
    const float* xb = x + (size_t)b * CC * NPOS;

    float acc[8][4];
#pragma unroll
    for (int j = 0; j < 8; j++)
#pragma unroll
        for (int q = 0; q < 4; q++) acc[j][q] = 0.f;

    auto wrow = [&](int row) -> const float* {
        if (ocb == 0) return (row < 32) ? Wf + (size_t)row * 256 : Wg + (size_t)(row - 32) * 256;
        return Wh + (size_t)((ocb - 1) * 64 + row) * 256;
    };

#pragma unroll
    for (int p = 0; p < 2; p++) {
        int idx = tid + p * 256; int row = idx >> 3, cc = idx & 7;
        cpa16(&Ws[row * WST + cc * 4], wrow(row) + cc * 4);
    }
#pragma unroll
    for (int p = 0; p < 4; p++) {
        int idx = tid + p * 256; int kk = idx >> 5, cc = idx & 31;
        cpa16(&xs[kk * AXST + cc * 4], &xb[(size_t)kk * NPOS + n0 + cc * 4]);
    }
    cpcommit();
    cpwait0(); __syncthreads();

    for (int it = 0; it < 8; it++) {
        const int cur = it & 1;
        if (it + 1 < 8) {
            const int nxt = cur ^ 1, k0g = (it + 1) * 32;
            float* Wd = Ws + nxt * 64 * WST;
            float* xd = xs + nxt * 32 * AXST;
#pragma unroll
            for (int p = 0; p < 2; p++) {
                int idx = tid + p * 256; int row = idx >> 3, cc = idx & 7;
                cpa16(&Wd[row * WST + cc * 4], wrow(row) + k0g + cc * 4);
            }
#pragma unroll
            for (int p = 0; p < 4; p++) {
                int idx = tid + p * 256; int kk = idx >> 5, cc = idx & 31;
                cpa16(&xd[kk * AXST + cc * 4], &xb[(size_t)(k0g + kk) * NPOS + n0 + cc * 4]);
            }
        }
        cpcommit();

        const float* Wc = Ws + cur * 64 * WST;
        const float* xc = xs + cur * 32 * AXST;
#pragma unroll
        for (int ks = 0; ks < 4; ks++) {
            const int k0 = ks * 8;
            uint32_t a0 = __float_as_uint(Wc[(ms + r) * WST + k0 + c]);
            uint32_t a1 = __float_as_uint(Wc[(ms + r + 8) * WST + k0 + c]);
            uint32_t a2 = __float_as_uint(Wc[(ms + r) * WST + k0 + c + 4]);
            uint32_t a3 = __float_as_uint(Wc[(ms + r + 8) * WST + k0 + c + 4]);
#pragma unroll
            for (int j = 0; j < 8; j++) {
                const int nn = nh * 32 + (j & 3) * 8 + (j >> 2) * 64;
                uint32_t b0 = __float_as_uint(xc[(k0 + c) * AXST + nn + r]);
                uint32_t b1 = __float_as_uint(xc[(k0 + c + 4) * AXST + nn + r]);
                mma8(acc[j][0], acc[j][1], acc[j][2], acc[j][3], a0, a1, a2, a3, b0, b1);
            }
        }
        cpwait0(); __syncthreads();
    }

    // epilogue
    if (ocb == 0 && ms < 32) {
        float* fb = g_f + (size_t)b * CF * NPOS;
#pragma unroll
        for (int j = 0; j < 8; j++) {
            const int nn = nh * 32 + (j & 3) * 8 + (j >> 2) * 64;
            const int n = n0 + nn + 2 * c;
            *(float2*)&fb[(size_t)(ms + r) * NPOS + n] =
                make_float2(tf32r(acc[j][0]), tf32r(acc[j][1]));
            *(float2*)&fb[(size_t)(ms + r + 8) * NPOS + n] =
                make_float2(tf32r(acc[j][2]), tf32r(acc[j][3]));
        }
    } else {
        const int oc0 = ocb * 64 + ms + r;
#pragma unroll
        for (int j = 0; j < 4; j++) {
            float vlo = fmaxf(fmaxf(acc[j][0], acc[j][1]), fmaxf(acc[j + 4][0], acc[j + 4][1]));
            float vhi = fmaxf(fmaxf(acc[j][2], acc[j][3]), fmaxf(acc[j + 4][2], acc[j + 4][3]));
            const int pm = blockIdx.x * 32 + nh * 16 + j * 4 + c;
            if (ocb == 0) {
                float* dst = g_gp + ((size_t)b * CF + (oc0 - 32)) * MPOS;
                dst[pm] = tf32r(vlo);
                dst[8 * MPOS + pm] = tf32r(vhi);
            } else {
                __nv_bfloat16* dst = g_hp + ((size_t)b * CHD + (oc0 - 64)) * MPOS;
                dst[pm] = __float2bfloat16(vlo);
                dst[8 * MPOS + pm] = __float2bfloat16(vhi);
            }
        }
    }
}

// ============================================================
// Kernel C: attention. Score: tf32 m16n8k8. O-phase: bf16 m16n8k16
// with ldmatrix. Rowsum shfl reduction hoisted out of tile loop.
// O stored bf16 in [n][c] layout for kD.
// ============================================================
#define FST 72
#define GST2 72
#define HSTU 36   // u32 stride (72 halfs)
#define PSTH 72   // half stride
#define KC_FS 0
#define KC_GS (32 * FST)
#define KC_HS (KC_GS + 32 * GST2)
#define KC_PS (KC_HS + 2 * 128 * HSTU)
#define KC_R4 (KC_PS + 64 * HSTU)
#define KC_RS (KC_R4 + 4 * 64)
#define SMEM_C_FLOATS (KC_RS + 64)
#define SMEM_C_BYTES (SMEM_C_FLOATS * 4)

__global__ __launch_bounds__(256, 3) void kC() {
    float* fs   = smc + KC_FS;                       // [k=32][72] fp32
    float* gs   = smc + KC_GS;                       // [k=32][72] fp32
    uint32_t* hs = (uint32_t*)(smc + KC_HS);         // 2 x [128][36] bf16x2
    uint32_t* psu = (uint32_t*)(smc + KC_PS);        // [64][36] bf16x2
    __nv_bfloat16* psh = (__nv_bfloat16*)(smc + KC_PS);
    float* r4   = smc + KC_R4;
    float* rsum = smc + KC_RS;

    const int b = blockIdx.y;
    const int n0 = blockIdx.x * 64;
    const int tid = threadIdx.x;
    const int w = tid >> 5, lane = tid & 31;
    const int r = lane >> 2, c = lane & 3;
    const float* gp = g_gp + (size_t)b * CF * MPOS;
    const __nv_bfloat16* hp = g_hp + (size_t)b * CHD * MPOS;
    const float* fp = g_f + (size_t)b * CF * NPOS + n0;

#pragma unroll
    for (int p = 0; p < 2; p++) {
        int idx = tid + p * 256; int rr = idx >> 4, cc = idx & 15;
        cpa16(&fs[rr * FST + cc * 4], &fp[(size_t)rr * NPOS + cc * 4]);
        cpa16(&gs[rr * GST2 + cc * 4], &gp[(size_t)rr * MPOS + cc * 4]);
    }
#pragma unroll
    for (int p = 0; p < 4; p++) {
        int idx = tid + p * 256; int rr = idx >> 3, cc = idx & 7;
        cpa16(&hs[rr * HSTU + cc * 4], &hp[(size_t)rr * MPOS + cc * 8]);
    }
    cpcommit();
    cpwait0(); __syncthreads();

    const int ms = (w & 3) * 16;
    const int nb = (w >> 2) * 32;
    const int cb = w * 16;

    // ldmatrix per-lane offsets (u32 units)
    const int i7 = lane & 7, s2 = (lane >> 3) & 1, s4 = lane >> 4;
    const uint32_t a_off = (uint32_t)((cb + s2 * 8 + i7) * HSTU + s4 * 4);
    const uint32_t b_off = (uint32_t)((s4 * 8 + i7) * HSTU + s2 * 4);
    const uint32_t ps_sb = (uint32_t)__cvta_generic_to_shared(psu);

    float rs8[8];
#pragma unroll
    for (int i = 0; i < 8; i++) rs8[i] = 0.f;
    float oc[8][4];
#pragma unroll
    for (int i = 0; i < 8; i++)
#pragma unroll
        for (int j = 0; j < 4; j++) oc[i][j] = 0.f;

    for (int t = 0; t < 16; t++) {
        const int cur = t & 1;
        const uint32_t* hsc = hs + cur * 128 * HSTU;

        if (t + 1 < 16) {
            const int m1 = (t + 1) * 64;
            uint32_t* hsd = hs + (cur ^ 1) * 128 * HSTU;
#pragma unroll
            for (int p = 0; p < 4; p++) {
                int idx = tid + p * 256; int rr = idx >> 3, cc = idx & 7;
                cpa16(&hsd[rr * HSTU + cc * 4], &hp[(size_t)rr * MPOS + m1 + cc * 8]);
            }
        }
        cpcommit();

        // ---- score mma (tf32) ----
        float sc[4][4];
#pragma unroll
        for (int j = 0; j < 4; j++)
#pragma unroll
            for (int q = 0; q < 4; q++) sc[j][q] = 0.f;
#pragma unroll
        for (int ks = 0; ks < 4; ks++) {
            const int k0 = ks * 8;
            uint32_t a0 = __float_as_uint(gs[(k0 + c) * GST2 + ms + r]);
            uint32_t a1 = __float_as_uint(gs[(k0 + c) * GST2 + ms + r + 8]);
            uint32_t a2 = __float_as_uint(gs[(k0 + c + 4) * GST2 + ms + r]);
            uint32_t a3 = __float_as_uint(gs[(k0 + c + 4) * GST2 + ms + r + 8]);
#pragma unroll
            for (int j = 0; j < 4; j++) {
                uint32_t b0 = __float_as_uint(fs[(k0 + c) * FST + nb + j * 8 + r]);
                uint32_t b1 = __float_as_uint(fs[(k0 + c + 4) * FST + nb + j * 8 + r]);
                mma8(sc[j][0], sc[j][1], sc[j][2], sc[j][3], a0, a1, a2, a3, b0, b1);
            }
        }

        // ---- exp, store P bf16, accumulate raw rowsum partials ----
#pragma unroll
        for (int j = 0; j < 4; j++) {
            float e0 = __expf(sc[j][0]);
            float e1 = __expf(sc[j][1]);
            float e2 = __expf(sc[j][2]);
            float e3 = __expf(sc[j][3]);
            const int n = nb + j * 8 + 2 * c;
            psh[(size_t)n * PSTH + ms + r]           = __float2bfloat16(e0);
            psh[(size_t)(n + 1) * PSTH + ms + r]     = __float2bfloat16(e1);
            psh[(size_t)n * PSTH + ms + r + 8]       = __float2bfloat16(e2);
            psh[(size_t)(n + 1) * PSTH + ms + r + 8] = __float2bfloat16(e3);
            rs8[2 * j]     += e0 + e2;
            rs8[2 * j + 1] += e1 + e3;
        }
        __syncthreads();   // ps visible; gs free

        if (t + 1 < 16) {
            const int m1 = (t + 1) * 64;
#pragma unroll
            for (int p = 0; p < 2; p++) {
                int idx = tid + p * 256; int rr = idx >> 4, cc = idx & 15;
                cpa16(&gs[rr * GST2 + cc * 4], &gp[(size_t)rr * MPOS + m1 + cc * 4]);
            }
        }
        cpcommit();

        // ---- o mma (bf16 k16, ldmatrix) ----
        {
            const uint32_t hs_sb = (uint32_t)__cvta_generic_to_shared(hsc);
#pragma unroll
            for (int km = 0; km < 4; km++) {
                const uint32_t mo = km * 8;
                uint32_t a0, a1, a2, a3;
                ldm4(a0, a1, a2, a3, hs_sb + (a_off + mo) * 4);
#pragma unroll
                for (int jp = 0; jp < 4; jp++) {
                    uint32_t b0, b1, b2, b3;
                    ldm4(b0, b1, b2, b3, ps_sb + (b_off + jp * 16 * HSTU + mo) * 4);
                    mma16b(oc[2 * jp][0], oc[2 * jp][1], oc[2 * jp][2], oc[2 * jp][3],
                           a0, a1, a2, a3, b0, b1);
                    mma16b(oc[2 * jp + 1][0], oc[2 * jp + 1][1], oc[2 * jp + 1][2], oc[2 * jp + 1][3],
                           a0, a1, a2, a3, b2, b3);
                }
            }
        }
        cpwait0();
        __syncthreads();
    }

    // ---- rowsum: single shfl reduce over r-lanes, combine warps ----
#pragma unroll
    for (int j = 0; j < 4; j++) {
        float p0 = rs8[2 * j], p1 = rs8[2 * j + 1];
#pragma unroll
        for (int off = 4; off < 32; off <<= 1) {
            p0 += __shfl_xor_sync(0xffffffffu, p0, off);
            p1 += __shfl_xor_sync(0xffffffffu, p1, off);
        }
        rs8[2 * j] = p0; rs8[2 * j + 1] = p1;
    }
    if (r == 0) {
#pragma unroll
        for (int j = 0; j < 4; j++) {
            r4[(w & 3) * 64 + nb + j * 8 + 2 * c]     = rs8[2 * j];
            r4[(w & 3) * 64 + nb + j * 8 + 2 * c + 1] = rs8[2 * j + 1];
        }
    }
    __syncthreads();
    if (tid < 64)
        rsum[tid] = 1.f / (r4[tid] + r4[64 + tid] + r4[128 + tid] + r4[192 + tid]);
    __syncthreads();

    // ---- normalize + store O bf16 in [n][c] layout ----
    __nv_bfloat16* ob = g_ob + (size_t)b * NPOS * CHD;
#pragma unroll
    for (int j = 0; j < 8; j++) {
        const int n = n0 + j * 8 + 2 * c;
        float i0 = rsum[j * 8 + 2 * c], i1 = rsum[j * 8 + 2 * c + 1];
        ob[(size_t)n * CHD + cb + r]           = __float2bfloat16(oc[j][0] * i0);
        ob[(size_t)(n + 1) * CHD + cb + r]     = __float2bfloat16(oc[j][1] * i1);
        ob[(size_t)n * CHD + cb + r + 8]       = __float2bfloat16(oc[j][2] * i0);
        ob[(size_t)(n + 1) * CHD + cb + r + 8] = __float2bfloat16(oc[j][3] * i1);
    }
}

// ============================================================
// Kernel D: out = gamma * (Wo @ o) + x via bf16 mma + ldmatrix.
// grid (32 n-tiles of 128, 4 oc-tiles of 64, 8 b), 256 thr = 8 warps.
// W converted fp32->bf16 in-kernel into smem [oc=64][k=128] (stride 68 u32);
// o tiles [n=128][k=32] bf16 (stride 20 u32), double-buffered.
// ============================================================
#define WKST 68   // u32 stride for W smem (136 halfs)
#define OST  20   // u32 stride for o smem (40 halfs)
#define KD_W 0
#define KD_O (64 * WKST)
#define SMEM_D_BYTES ((KD_O + 2 * 128 * OST) * 4)

__global__ __launch_bounds__(256, 4) void kD(const float* __restrict__ x,
                                             const float* __restrict__ Wo,
                                             const float* __restrict__ gptr,
                                             float* __restrict__ out) {
    uint32_t* Wb = (uint32_t*)smc + KD_W;   // [64][68] bf16x2
    uint32_t* os = (uint32_t*)smc + KD_O;   // 2 x [128][20] bf16x2
    const int b = blockIdx.z, ocb = blockIdx.y;
    const int n0 = blockIdx.x * 128;
    const int tid = threadIdx.x;
    const int w = tid >> 5, lane = tid & 31;
    const int r = lane >> 2, c = lane & 3;
    const int ms = (w & 3) * 16, nh = w >> 2;
    const float gamma = *gptr;
    const __nv_bfloat16* obp = g_ob + (size_t)b * NPOS * CHD;

    // o tile stage 0 (k 0..31)
#pragma unroll
    for (int p = 0; p < 2; p++) {
        int idx = tid + p * 256; int rr = idx >> 2, cc = idx & 3;
        cpa16(&os[rr * OST + cc * 4], &obp[(size_t)(n0 + rr) * CHD + cc * 8]);
    }
    cpcommit();

    // convert Wo slice [64][128] fp32 -> bf16 smem
#pragma unroll
    for (int p = 0; p < 8; p++) {
        int idx = tid + p * 256; int row = idx >> 5, cc = idx & 31;
        float4 v = *(const float4*)&Wo[(size_t)(ocb * 64 + row) * CHD + cc * 4];
        __nv_bfloat162 lo = __floats2bfloat162_rn(v.x, v.y);
        __nv_bfloat162 hi = __floats2bfloat162_rn(v.z, v.w);
        Wb[row * WKST + cc * 2]     = *(uint32_t*)&lo;
        Wb[row * WKST + cc * 2 + 1] = *(uint32_t*)&hi;
    }
    cpwait0(); __syncthreads();

    const int i7 = lane & 7, s2 = (lane >> 3) & 1, s4 = lane >> 4;
    const uint32_t w_sb = (uint32_t)__cvta_generic_to_shared(Wb);
    const uint32_t o_sb = (uint32_t)__cvta_generic_to_shared(os);
    const uint32_t a_off = (uint32_t)((ms + s2 * 8 + i7) * WKST + s4 * 4);
    const uint32_t b_off = (uint32_t)((nh * 64 + s4 * 8 + i7) * OST + s2 * 4);

    float acc[8][4];
#pragma unroll
    for (int j = 0; j < 8; j++)
#pragma unroll
        for (int q = 0; q < 4; q++) acc[j][q] = 0.f;

    for (int st = 0; st < 4; st++) {
        const int cur = st & 1;
        if (st + 1 < 4) {
            const int k0h = (st + 1) * 32;
            uint32_t* osd = os + (cur ^ 1) * 128 * OST;
#pragma unroll
            for (int p = 0; p < 2; p++) {
                int idx = tid + p * 256; int rr = idx >> 2, cc = idx & 3;
                cpa16(&osd[rr * OST + cc * 4], &obp[(size_t)(n0 + rr) * CHD + k0h + cc * 8]);
            }
        }
        cpcommit();

        const uint32_t o_cur = o_sb + cur * 128 * OST * 4;
#pragma unroll
        for (int ks2 = 0; ks2 < 2; ks2++) {
            const int s = st * 2 + ks2;            // k16 step 0..7
            uint32_t a0, a1, a2, a3;
            ldm4(a0, a1, a2, a3, w_sb + (a_off + s * 8) * 4);
#pragma unroll
            for (int jp = 0; jp < 4; jp++) {
                uint32_t b0, b1, b2, b3;
                ldm4(b0, b1, b2, b3, o_cur + (b_off + jp * 16 * OST + ks2 * 8) * 4);
                mma16b(acc[2 * jp][0], acc[2 * jp][1], acc[2 * jp][2], acc[2 * jp][3],
                       a0, a1, a2, a3, b0, b1);
                mma16b(acc[2 * jp + 1][0], acc[2 * jp + 1][1], acc[2 * jp + 1][2], acc[2 * jp + 1][3],
                       a0, a1, a2, a3, b2, b3);
            }
        }
        cpwait0(); __syncthreads();
    }

    const float* xb = x + (size_t)b * CC * NPOS;
    float* outb = out + (size_t)b * CC * NPOS;
    const int oc0 = ocb * 64 + ms + r;
#pragma unroll
    for (int j = 0; j < 8; j++) {
        const int n = n0 + nh * 64 + j * 8 + 2 * c;
        size_t p0 = (size_t)oc0 * NPOS + n;
        size_t p1 = (size_t)(oc0 + 8) * NPOS + n;
        float2 x0 = *(const float2*)&xb[p0];
        float2 x1 = *(const float2*)&xb[p1];
        *(float2*)&outb[p0] = make_float2(fmaf(gamma, acc[j][0], x0.x),
                                          fmaf(gamma, acc[j][1], x0.y));
        *(float2*)&outb[p1] = make_float2(fmaf(gamma, acc[j][2], x1.x),
                                          fmaf(gamma, acc[j][3], x1.y));
    }
}

// ============================================================
extern "C" void kernel_launch(void* const* d_in, const int* in_sizes, int n_in,
                              void* d_out, int out_size) {
    const float* x     = (const float*)d_in[0];
    const float* Wf    = (const float*)d_in[1];
    const float* Wg    = (const float*)d_in[2];
    const float* Wh    = (const float*)d_in[3];
    const float* Wo    = (const float*)d_in[4];
    const float* gamma = (const float*)d_in[5];
    float* out = (float*)d_out;

    cudaFuncSetAttribute(kA, cudaFuncAttributeMaxDynamicSharedMemorySize, SMEM_A_BYTES);
    cudaFuncSetAttribute(kC, cudaFuncAttributeMaxDynamicSharedMemorySize, SMEM_C_BYTES);
    cudaFuncSetAttribute(kD, cudaFuncAttributeMaxDynamicSharedMemorySize, SMEM_D_BYTES);

    kA<<<dim3(32, 3, 8), 256, SMEM_A_BYTES>>>(x, Wf, Wg, Wh);
    kC<<<dim3(64, 8), 256, SMEM_C_BYTES>>>();
    kD<<<dim3(32, 4, 8), 256, SMEM_D_BYTES>>>(x, Wo, gamma, out);
}

// round 11
// speedup vs baseline: 5.0486x; 1.1903x over previous
#include <cuda_runtime.h>
#include <cuda_bf16.h>
#include <cstdint>

#define BB 8
#define CC 256
#define NPOS 4096   // 64*64
#define MPOS 1024   // 32*32
#define CF 32       // C/8
#define CHD 128     // C/2

// ---- scratch (static device globals; no allocation) ----
__device__ float g_f[(size_t)BB * CF * NPOS];                      // f (tf32-rounded fp32)
__device__ float g_gp[(size_t)BB * CF * MPOS];                     // pooled g (tf32-rounded fp32)
__device__ __align__(16) __nv_bfloat16 g_hp[(size_t)BB * CHD * MPOS];   // pooled h (bf16)
__device__ __align__(16) __nv_bfloat16 g_ob[(size_t)BB * NPOS * CHD];   // attention out, [b][n][c] bf16

// ---- helpers ----
__device__ __forceinline__ void cpa16(void* s, const void* g) {
    unsigned sa = (unsigned)__cvta_generic_to_shared(s);
    asm volatile("cp.async.ca.shared.global [%0], [%1], 16;\n" :: "r"(sa), "l"(g));
}
__device__ __forceinline__ void cpcommit() { asm volatile("cp.async.commit_group;\n" ::); }
__device__ __forceinline__ void cpwait0()  { asm volatile("cp.async.wait_group 0;\n" ::); }

__device__ __forceinline__ float tf32r(float x) {
    uint32_t u;
    asm("cvt.rna.tf32.f32 %0, %1;" : "=r"(u) : "f"(x));
    return __uint_as_float(u);
}

__device__ __forceinline__ void mma8(float& c0, float& c1, float& c2, float& c3,
                                     uint32_t a0, uint32_t a1, uint32_t a2, uint32_t a3,
                                     uint32_t b0, uint32_t b1) {
    asm volatile("mma.sync.aligned.m16n8k8.row.col.f32.tf32.tf32.f32 "
                 "{%0,%1,%2,%3}, {%4,%5,%6,%7}, {%8,%9}, {%0,%1,%2,%3};"
                 : "+f"(c0), "+f"(c1), "+f"(c2), "+f"(c3)
                 : "r"(a0), "r"(a1), "r"(a2), "r"(a3), "r"(b0), "r"(b1));
}

__device__ __forceinline__ void mma16b(float& c0, float& c1, float& c2, float& c3,
                                       uint32_t a0, uint32_t a1, uint32_t a2, uint32_t a3,
                                       uint32_t b0, uint32_t b1) {
    asm volatile("mma.sync.aligned.m16n8k16.row.col.f32.bf16.bf16.f32 "
                 "{%0,%1,%2,%3}, {%4,%5,%6,%7}, {%8,%9}, {%0,%1,%2,%3};"
                 : "+f"(c0), "+f"(c1), "+f"(c2), "+f"(c3)
                 : "r"(a0), "r"(a1), "r"(a2), "r"(a3), "r"(b0), "r"(b1));
}

__device__ __forceinline__ void ldm4(uint32_t& r0, uint32_t& r1, uint32_t& r2, uint32_t& r3,
                                     uint32_t saddr) {
    asm volatile("ldmatrix.sync.aligned.m8n8.x4.shared.b16 {%0,%1,%2,%3}, [%4];"
                 : "=r"(r0), "=r"(r1), "=r"(r2), "=r"(r3) : "r"(saddr));
}

extern __shared__ float smc[];

// ============================================================
// Kernel A: [f;g;h] = Wcat @ x via tf32 mma (unchanged from R10).
// ============================================================
#define WST 36
#define AXST 136
#define KA_WS 0
#define KA_XS (2 * 64 * WST)
#define SMEM_A_BYTES ((KA_XS + 2 * 32 * AXST) * 4)

__global__ __launch_bounds__(256, 3) void kA(const float* __restrict__ x,
                                             const float* __restrict__ Wf,
                                             const float* __restrict__ Wg,
                                             const float* __restrict__ Wh) {
    float* Ws = smc + KA_WS;   // 2 x [64][36]
    float* xs = smc + KA_XS;   // 2 x [32][136]
    const int b = blockIdx.z, ocb = blockIdx.y;
    const int n0 = blockIdx.x * 128;
    const int tid = threadIdx.x;
    const int w = tid >> 5, lane = tid & 31;
    const int r = lane >> 2, c = lane & 3;
    const int ms = (w & 3) * 16, nh = w >> 2;
    const float* xb = x + (size_t)b * CC * NPOS;

    float acc[8][4];
#pragma unroll
    for (int j = 0; j < 8; j++)
#pragma unroll
        for (int q = 0; q < 4; q++) acc[j][q] = 0.f;

    auto wrow = [&](int row) -> const float* {
        if (ocb == 0) return (row < 32) ? Wf + (size_t)row * 256 : Wg + (size_t)(row - 32) * 256;
        return Wh + (size_t)((ocb - 1) * 64 + row) * 256;
    };

#pragma unroll
    for (int p = 0; p < 2; p++) {
        int idx = tid + p * 256; int row = idx >> 3, cc = idx & 7;
        cpa16(&Ws[row * WST + cc * 4], wrow(row) + cc * 4);
    }
#pragma unroll
    for (int p = 0; p < 4; p++) {
        int idx = tid + p * 256; int kk = idx >> 5, cc = idx & 31;
        cpa16(&xs[kk * AXST + cc * 4], &xb[(size_t)kk * NPOS + n0 + cc * 4]);
    }
    cpcommit();
    cpwait0(); __syncthreads();

    for (int it = 0; it < 8; it++) {
        const int cur = it & 1;
        if (it + 1 < 8) {
            const int nxt = cur ^ 1, k0g = (it + 1) * 32;
            float* Wd = Ws + nxt * 64 * WST;
            float* xd = xs + nxt * 32 * AXST;
#pragma unroll
            for (int p = 0; p < 2; p++) {
                int idx = tid + p * 256; int row = idx >> 3, cc = idx & 7;
                cpa16(&Wd[row * WST + cc * 4], wrow(row) + k0g + cc * 4);
            }
#pragma unroll
            for (int p = 0; p < 4; p++) {
                int idx = tid + p * 256; int kk = idx >> 5, cc = idx & 31;
                cpa16(&xd[kk * AXST + cc * 4], &xb[(size_t)(k0g + kk) * NPOS + n0 + cc * 4]);
            }
        }
        cpcommit();

        const float* Wc = Ws + cur * 64 * WST;
        const float* xc = xs + cur * 32 * AXST;
#pragma unroll
        for (int ks = 0; ks < 4; ks++) {
            const int k0 = ks * 8;
            uint32_t a0 = __float_as_uint(Wc[(ms + r) * WST + k0 + c]);
            uint32_t a1 = __float_as_uint(Wc[(ms + r + 8) * WST + k0 + c]);
            uint32_t a2 = __float_as_uint(Wc[(ms + r) * WST + k0 + c + 4]);
            uint32_t a3 = __float_as_uint(Wc[(ms + r + 8) * WST + k0 + c + 4]);
#pragma unroll
            for (int j = 0; j < 8; j++) {
                const int nn = nh * 32 + (j & 3) * 8 + (j >> 2) * 64;
                uint32_t b0 = __float_as_uint(xc[(k0 + c) * AXST + nn + r]);
                uint32_t b1 = __float_as_uint(xc[(k0 + c + 4) * AXST + nn + r]);
                mma8(acc[j][0], acc[j][1], acc[j][2], acc[j][3], a0, a1, a2, a3, b0, b1);
            }
        }
        cpwait0(); __syncthreads();
    }

    // epilogue
    if (ocb == 0 && ms < 32) {
        float* fb = g_f + (size_t)b * CF * NPOS;
#pragma unroll
        for (int j = 0; j < 8; j++) {
            const int nn = nh * 32 + (j & 3) * 8 + (j >> 2) * 64;
            const int n = n0 + nn + 2 * c;
            *(float2*)&fb[(size_t)(ms + r) * NPOS + n] =
                make_float2(tf32r(acc[j][0]), tf32r(acc[j][1]));
            *(float2*)&fb[(size_t)(ms + r + 8) * NPOS + n] =
                make_float2(tf32r(acc[j][2]), tf32r(acc[j][3]));
        }
    } else {
        const int oc0 = ocb * 64 + ms + r;
#pragma unroll
        for (int j = 0; j < 4; j++) {
            float vlo = fmaxf(fmaxf(acc[j][0], acc[j][1]), fmaxf(acc[j + 4][0], acc[j + 4][1]));
            float vhi = fmaxf(fmaxf(acc[j][2], acc[j][3]), fmaxf(acc[j + 4][2], acc[j + 4][3]));
            const int pm = blockIdx.x * 32 + nh * 16 + j * 4 + c;
            if (ocb == 0) {
                float* dst = g_gp + ((size_t)b * CF + (oc0 - 32)) * MPOS;
                dst[pm] = tf32r(vlo);
                dst[8 * MPOS + pm] = tf32r(vhi);
            } else {
                __nv_bfloat16* dst = g_hp + ((size_t)b * CHD + (oc0 - 64)) * MPOS;
                dst[pm] = __float2bfloat16(vlo);
                dst[8 * MPOS + pm] = __float2bfloat16(vhi);
            }
        }
    }
}

// ============================================================
// Kernel C: FA2-style attention. Score tf32 mma with QUERIES as M
// -> C-frags exp'd and packed in-register into bf16 A-frags for the
// o-mma (no P smem round trip, no P barrier). One warp = n16 strip
// x all 128 channels, full m per warp. 1 sync per tile.
// grid (32 q-tiles of 128, 8 b), 256 thr = 8 warps, Mt=64, 16 tiles.
// smem: fs [32][136] fp32, gs 2x[32][72] fp32, hs 2x[128][36 u32] bf16.
// ============================================================
#define CFST 136
#define CGST 72
#define CHSTU 36
#define KC_FS 0
#define KC_GS (32 * CFST)
#define KC_HS (KC_GS + 2 * 32 * CGST)
#define SMEM_C_FLOATS (KC_HS + 2 * 128 * CHSTU)
#define SMEM_C_BYTES (SMEM_C_FLOATS * 4)

__global__ __launch_bounds__(256, 2) void kC() {
    float* fs = smc + KC_FS;                    // [32][136]
    float* gs = smc + KC_GS;                    // 2 x [32][72]
    uint32_t* hs = (uint32_t*)(smc + KC_HS);    // 2 x [128][36]

    const int b = blockIdx.y;
    const int n0 = blockIdx.x * 128;
    const int tid = threadIdx.x;
    const int w = tid >> 5, lane = tid & 31;
    const int r = lane >> 2, c = lane & 3;
    const int nq0 = w * 16;                     // warp's query strip
    const float* gp = g_gp + (size_t)b * CF * MPOS;
    const __nv_bfloat16* hp = g_hp + (size_t)b * CHD * MPOS;
    const float* fp = g_f + (size_t)b * CF * NPOS + n0;

    // initial loads: fs (whole), gs(t0), hs(t0)
#pragma unroll
    for (int p = 0; p < 4; p++) {
        int idx = tid + p * 256; int rr = idx >> 5, cc = idx & 31;
        cpa16(&fs[rr * CFST + cc * 4], &fp[(size_t)rr * NPOS + cc * 4]);
    }
#pragma unroll
    for (int p = 0; p < 2; p++) {
        int idx = tid + p * 256; int rr = idx >> 4, cc = idx & 15;
        cpa16(&gs[rr * CGST + cc * 4], &gp[(size_t)rr * MPOS + cc * 4]);
    }
#pragma unroll
    for (int p = 0; p < 4; p++) {
        int idx = tid + p * 256; int rr = idx >> 3, cc = idx & 7;
        cpa16(&hs[rr * CHSTU + cc * 4], &hp[(size_t)rr * MPOS + cc * 8]);
    }
    cpcommit(); cpwait0(); __syncthreads();

    const int i7 = lane & 7, s2 = (lane >> 3) & 1, s4 = lane >> 4;

    float rs0 = 0.f, rs1 = 0.f;
    float acc[16][4];
#pragma unroll
    for (int i = 0; i < 16; i++)
#pragma unroll
        for (int q = 0; q < 4; q++) acc[i][q] = 0.f;

    for (int t = 0; t < 16; t++) {
        const int cur = t & 1;
        const float* gsc = gs + cur * 32 * CGST;
        const uint32_t* hsc = hs + cur * 128 * CHSTU;

        // prefetch t+1 into alternate buffers (free since end of t-1)
        if (t + 1 < 16) {
            const int m1 = (t + 1) * 64;
            float* gsd = gs + (cur ^ 1) * 32 * CGST;
            uint32_t* hsd = hs + (cur ^ 1) * 128 * CHSTU;
#pragma unroll
            for (int p = 0; p < 2; p++) {
                int idx = tid + p * 256; int rr = idx >> 4, cc = idx & 15;
                cpa16(&gsd[rr * CGST + cc * 4], &gp[(size_t)rr * MPOS + m1 + cc * 4]);
            }
#pragma unroll
            for (int p = 0; p < 4; p++) {
                int idx = tid + p * 256; int rr = idx >> 3, cc = idx & 7;
                cpa16(&hsd[rr * CHSTU + cc * 4], &hp[(size_t)rr * MPOS + m1 + cc * 8]);
            }
        }
        cpcommit();

        // ---- score mma (tf32): S[n16][m8], A = f, B = g ----
        uint32_t af[4][4];   // bf16 A-frags for o-mma, one per m16 chunk
#pragma unroll
        for (int half = 0; half < 2; half++) {
            float sc[4][4];
#pragma unroll
            for (int j2 = 0; j2 < 4; j2++)
#pragma unroll
                for (int q = 0; q < 4; q++) sc[j2][q] = 0.f;
#pragma unroll
            for (int ks = 0; ks < 4; ks++) {
                const int k0 = ks * 8;
                uint32_t a0 = __float_as_uint(fs[(k0 + c) * CFST + nq0 + r]);
                uint32_t a1 = __float_as_uint(fs[(k0 + c) * CFST + nq0 + r + 8]);
                uint32_t a2 = __float_as_uint(fs[(k0 + c + 4) * CFST + nq0 + r]);
                uint32_t a3 = __float_as_uint(fs[(k0 + c + 4) * CFST + nq0 + r + 8]);
#pragma unroll
                for (int j2 = 0; j2 < 4; j2++) {
                    const int mof = half * 32 + j2 * 8;
                    uint32_t b0 = __float_as_uint(gsc[(k0 + c) * CGST + mof + r]);
                    uint32_t b1 = __float_as_uint(gsc[(k0 + c + 4) * CGST + mof + r]);
                    mma8(sc[j2][0], sc[j2][1], sc[j2][2], sc[j2][3],
                         a0, a1, a2, a3, b0, b1);
                }
            }
            // exp + pack C-frags -> bf16 A-frags (k16 = two m8 tiles)
#pragma unroll
            for (int mo2 = 0; mo2 < 2; mo2++) {
                float e00 = __expf(sc[2 * mo2][0]),     e01 = __expf(sc[2 * mo2][1]);
                float e02 = __expf(sc[2 * mo2][2]),     e03 = __expf(sc[2 * mo2][3]);
                float e10 = __expf(sc[2 * mo2 + 1][0]), e11 = __expf(sc[2 * mo2 + 1][1]);
                float e12 = __expf(sc[2 * mo2 + 1][2]), e13 = __expf(sc[2 * mo2 + 1][3]);
                __nv_bfloat162 p0 = __floats2bfloat162_rn(e00, e01);
                __nv_bfloat162 p1 = __floats2bfloat162_rn(e02, e03);
                __nv_bfloat162 p2 = __floats2bfloat162_rn(e10, e11);
                __nv_bfloat162 p3 = __floats2bfloat162_rn(e12, e13);
                const int mo = half * 2 + mo2;
                af[mo][0] = *(uint32_t*)&p0;   // (row r,   m8 #0)
                af[mo][1] = *(uint32_t*)&p1;   // (row r+8, m8 #0)
                af[mo][2] = *(uint32_t*)&p2;   // (row r,   m8 #1)
                af[mo][3] = *(uint32_t*)&p3;   // (row r+8, m8 #1)
                rs0 += (e00 + e01) + (e10 + e11);
                rs1 += (e02 + e03) + (e12 + e13);
            }
        }

        // ---- o-mma (bf16 k16): o^T[n16][c128] += P * h, A from regs ----
        {
            const uint32_t hs_sb = (uint32_t)__cvta_generic_to_shared(hsc);
#pragma unroll
            for (int mo = 0; mo < 4; mo++) {
#pragma unroll
                for (int cg = 0; cg < 8; cg++) {
                    uint32_t b0, b1, b2, b3;
                    ldm4(b0, b1, b2, b3,
                         hs_sb + (uint32_t)(((cg * 16 + s4 * 8 + i7) * CHSTU + s2 * 4 + mo * 8) * 4));
                    mma16b(acc[2 * cg][0], acc[2 * cg][1], acc[2 * cg][2], acc[2 * cg][3],
                           af[mo][0], af[mo][1], af[mo][2], af[mo][3], b0, b1);
                    mma16b(acc[2 * cg + 1][0], acc[2 * cg + 1][1], acc[2 * cg + 1][2], acc[2 * cg + 1][3],
                           af[mo][0], af[mo][1], af[mo][2], af[mo][3], b2, b3);
                }
            }
        }
        cpwait0();
        __syncthreads();   // t+1 buffers resident; cur buffers free
    }

    // ---- rowsum: warp-local xor reduce over the 4 c-lanes ----
#pragma unroll
    for (int off = 1; off < 4; off <<= 1) {
        rs0 += __shfl_xor_sync(0xffffffffu, rs0, off);
        rs1 += __shfl_xor_sync(0xffffffffu, rs1, off);
    }
    const float inv0 = 1.f / rs0, inv1 = 1.f / rs1;

    // ---- normalize + store o^T as bf16 [n][c] ----
    __nv_bfloat16* ob = g_ob + (size_t)b * NPOS * CHD;
    const int nrow = n0 + nq0 + r;
#pragma unroll
    for (int tt = 0; tt < 16; tt++) {
        __nv_bfloat162 v0 = __floats2bfloat162_rn(acc[tt][0] * inv0, acc[tt][1] * inv0);
        __nv_bfloat162 v1 = __floats2bfloat162_rn(acc[tt][2] * inv1, acc[tt][3] * inv1);
        *(uint32_t*)&ob[(size_t)nrow * CHD + tt * 8 + 2 * c] = *(uint32_t*)&v0;
        *(uint32_t*)&ob[(size_t)(nrow + 8) * CHD + tt * 8 + 2 * c] = *(uint32_t*)&v1;
    }
}

// ============================================================
// Kernel D: out = gamma * (Wo @ o) + x via bf16 mma + ldmatrix
// (unchanged from R10).
// ============================================================
#define WKST 68   // u32 stride for W smem (136 halfs)
#define OST  20   // u32 stride for o smem (40 halfs)
#define KD_W 0
#define KD_O (64 * WKST)
#define SMEM_D_BYTES ((KD_O + 2 * 128 * OST) * 4)

__global__ __launch_bounds__(256, 4) void kD(const float* __restrict__ x,
                                             const float* __restrict__ Wo,
                                             const float* __restrict__ gptr,
                                             float* __restrict__ out) {
    uint32_t* Wb = (uint32_t*)smc + KD_W;   // [64][68] bf16x2
    uint32_t* os = (uint32_t*)smc + KD_O;   // 2 x [128][20] bf16x2
    const int b = blockIdx.z, ocb = blockIdx.y;
    const int n0 = blockIdx.x * 128;
    const int tid = threadIdx.x;
    const int w = tid >> 5, lane = tid & 31;
    const int r = lane >> 2, c = lane & 3;
    const int ms = (w & 3) * 16, nh = w >> 2;
    const float gamma = *gptr;
    const __nv_bfloat16* obp = g_ob + (size_t)b * NPOS * CHD;

#pragma unroll
    for (int p = 0; p < 2; p++) {
        int idx = tid + p * 256; int rr = idx >> 2, cc = idx & 3;
        cpa16(&os[rr * OST + cc * 4], &obp[(size_t)(n0 + rr) * CHD + cc * 8]);
    }
    cpcommit();

#pragma unroll
    for (int p = 0; p < 8; p++) {
        int idx = tid + p * 256; int row = idx >> 5, cc = idx & 31;
        float4 v = *(const float4*)&Wo[(size_t)(ocb * 64 + row) * CHD + cc * 4];
        __nv_bfloat162 lo = __floats2bfloat162_rn(v.x, v.y);
        __nv_bfloat162 hi = __floats2bfloat162_rn(v.z, v.w);
        Wb[row * WKST + cc * 2]     = *(uint32_t*)&lo;
        Wb[row * WKST + cc * 2 + 1] = *(uint32_t*)&hi;
    }
    cpwait0(); __syncthreads();

    const int i7 = lane & 7, s2 = (lane >> 3) & 1, s4 = lane >> 4;
    const uint32_t w_sb = (uint32_t)__cvta_generic_to_shared(Wb);
    const uint32_t o_sb = (uint32_t)__cvta_generic_to_shared(os);
    const uint32_t a_off = (uint32_t)((ms + s2 * 8 + i7) * WKST + s4 * 4);
    const uint32_t b_off = (uint32_t)((nh * 64 + s4 * 8 + i7) * OST + s2 * 4);

    float acc[8][4];
#pragma unroll
    for (int j = 0; j < 8; j++)
#pragma unroll
        for (int q = 0; q < 4; q++) acc[j][q] = 0.f;

    for (int st = 0; st < 4; st++) {
        const int cur = st & 1;
        if (st + 1 < 4) {
            const int k0h = (st + 1) * 32;
            uint32_t* osd = os + (cur ^ 1) * 128 * OST;
#pragma unroll
            for (int p = 0; p < 2; p++) {
                int idx = tid + p * 256; int rr = idx >> 2, cc = idx & 3;
                cpa16(&osd[rr * OST + cc * 4], &obp[(size_t)(n0 + rr) * CHD + k0h + cc * 8]);
            }
        }
        cpcommit();

        const uint32_t o_cur = o_sb + cur * 128 * OST * 4;
#pragma unroll
        for (int ks2 = 0; ks2 < 2; ks2++) {
            const int s = st * 2 + ks2;
            uint32_t a0, a1, a2, a3;
            ldm4(a0, a1, a2, a3, w_sb + (a_off + s * 8) * 4);
#pragma unroll
            for (int jp = 0; jp < 4; jp++) {
                uint32_t b0, b1, b2, b3;
                ldm4(b0, b1, b2, b3, o_cur + (b_off + jp * 16 * OST + ks2 * 8) * 4);
                mma16b(acc[2 * jp][0], acc[2 * jp][1], acc[2 * jp][2], acc[2 * jp][3],
                       a0, a1, a2, a3, b0, b1);
                mma16b(acc[2 * jp + 1][0], acc[2 * jp + 1][1], acc[2 * jp + 1][2], acc[2 * jp + 1][3],
                       a0, a1, a2, a3, b2, b3);
            }
        }
        cpwait0(); __syncthreads();
    }

    const float* xb = x + (size_t)b * CC * NPOS;
    float* outb = out + (size_t)b * CC * NPOS;
    const int oc0 = ocb * 64 + ms + r;
#pragma unroll
    for (int j = 0; j < 8; j++) {
        const int n = n0 + nh * 64 + j * 8 + 2 * c;
        size_t p0 = (size_t)oc0 * NPOS + n;
        size_t p1 = (size_t)(oc0 + 8) * NPOS + n;
        float2 x0 = *(const float2*)&xb[p0];
        float2 x1 = *(const float2*)&xb[p1];
        *(float2*)&outb[p0] = make_float2(fmaf(gamma, acc[j][0], x0.x),
                                          fmaf(gamma, acc[j][1], x0.y));
        *(float2*)&outb[p1] = make_float2(fmaf(gamma, acc[j][2], x1.x),
                                          fmaf(gamma, acc[j][3], x1.y));
    }
}

// ============================================================
extern "C" void kernel_launch(void* const* d_in, const int* in_sizes, int n_in,
                              void* d_out, int out_size) {
    const float* x     = (const float*)d_in[0];
    const float* Wf    = (const float*)d_in[1];
    const float* Wg    = (const float*)d_in[2];
    const float* Wh    = (const float*)d_in[3];
    const float* Wo    = (const float*)d_in[4];
    const float* gamma = (const float*)d_in[5];
    float* out = (float*)d_out;

    cudaFuncSetAttribute(kA, cudaFuncAttributeMaxDynamicSharedMemorySize, SMEM_A_BYTES);
    cudaFuncSetAttribute(kC, cudaFuncAttributeMaxDynamicSharedMemorySize, SMEM_C_BYTES);
    cudaFuncSetAttribute(kD, cudaFuncAttributeMaxDynamicSharedMemorySize, SMEM_D_BYTES);

    kA<<<dim3(32, 3, 8), 256, SMEM_A_BYTES>>>(x, Wf, Wg, Wh);
    kC<<<dim3(32, 8), 256, SMEM_C_BYTES>>>();
    kD<<<dim3(32, 4, 8), 256, SMEM_D_BYTES>>>(x, Wo, gamma, out);
}

// round 12
// speedup vs baseline: 5.4041x; 1.0704x over previous
#include <cuda_runtime.h>
#include <cuda_bf16.h>
#include <cstdint>

#define BB 8
#define CC 256
#define NPOS 4096   // 64*64
#define MPOS 1024   // 32*32
#define CF 32       // C/8
#define CHD 128     // C/2

// ---- scratch (static device globals; no allocation) ----
__device__ float g_f[(size_t)BB * CF * NPOS];                      // f (tf32-rounded fp32)
__device__ float g_gp[(size_t)BB * CF * MPOS];                     // pooled g (tf32-rounded fp32)
__device__ __align__(16) __nv_bfloat16 g_hp[(size_t)BB * CHD * MPOS];   // pooled h (bf16)

// ---- helpers ----
__device__ __forceinline__ void cpa16(void* s, const void* g) {
    unsigned sa = (unsigned)__cvta_generic_to_shared(s);
    asm volatile("cp.async.ca.shared.global [%0], [%1], 16;\n" :: "r"(sa), "l"(g));
}
__device__ __forceinline__ void cpcommit() { asm volatile("cp.async.commit_group;\n" ::); }
__device__ __forceinline__ void cpwait0()  { asm volatile("cp.async.wait_group 0;\n" ::); }

__device__ __forceinline__ float tf32r(float x) {
    uint32_t u;
    asm("cvt.rna.tf32.f32 %0, %1;" : "=r"(u) : "f"(x));
    return __uint_as_float(u);
}

__device__ __forceinline__ void mma8(float& c0, float& c1, float& c2, float& c3,
                                     uint32_t a0, uint32_t a1, uint32_t a2, uint32_t a3,
                                     uint32_t b0, uint32_t b1) {
    asm volatile("mma.sync.aligned.m16n8k8.row.col.f32.tf32.tf32.f32 "
                 "{%0,%1,%2,%3}, {%4,%5,%6,%7}, {%8,%9}, {%0,%1,%2,%3};"
                 : "+f"(c0), "+f"(c1), "+f"(c2), "+f"(c3)
                 : "r"(a0), "r"(a1), "r"(a2), "r"(a3), "r"(b0), "r"(b1));
}

__device__ __forceinline__ void mma16b(float& c0, float& c1, float& c2, float& c3,
                                       uint32_t a0, uint32_t a1, uint32_t a2, uint32_t a3,
                                       uint32_t b0, uint32_t b1) {
    asm volatile("mma.sync.aligned.m16n8k16.row.col.f32.bf16.bf16.f32 "
                 "{%0,%1,%2,%3}, {%4,%5,%6,%7}, {%8,%9}, {%0,%1,%2,%3};"
                 : "+f"(c0), "+f"(c1), "+f"(c2), "+f"(c3)
                 : "r"(a0), "r"(a1), "r"(a2), "r"(a3), "r"(b0), "r"(b1));
}

__device__ __forceinline__ void ldm4(uint32_t& r0, uint32_t& r1, uint32_t& r2, uint32_t& r3,
                                     uint32_t saddr) {
    asm volatile("ldmatrix.sync.aligned.m8n8.x4.shared.b16 {%0,%1,%2,%3}, [%4];"
                 : "=r"(r0), "=r"(r1), "=r"(r2), "=r"(r3) : "r"(saddr));
}

extern __shared__ float smc[];

// ============================================================
// Kernel A: [f;g;h] = Wcat @ x via tf32 mma (unchanged, proven).
// ============================================================
#define WST 36
#define AXST 136
#define KA_WS 0
#define KA_XS (2 * 64 * WST)
#define SMEM_A_BYTES ((KA_XS + 2 * 32 * AXST) * 4)

__global__ __launch_bounds__(256, 3) void kA(const float* __restrict__ x,
                                             const float* __restrict__ Wf,
                                             const float* __restrict__ Wg,
                                             const float* __restrict__ Wh) {
    float* Ws = smc + KA_WS;   // 2 x [64][36]
    float* xs = smc + KA_XS;   // 2 x [32][136]
    const int b = blockIdx.z, ocb = blockIdx.y;
    const int n0 = blockIdx.x * 128;
    const int tid = threadIdx.x;
    const int w = tid >> 5, lane = tid & 31;
    const int r = lane >> 2, c = lane & 3;
    const int ms = (w & 3) * 16, nh = w >> 2;
    const float* xb = x + (size_t)b * CC * NPOS;

    float acc[8][4];
#pragma unroll
    for (int j = 0; j < 8; j++)
#pragma unroll
        for (int q = 0; q < 4; q++) acc[j][q] = 0.f;

    auto wrow = [&](int row) -> const float* {
        if (ocb == 0) return (row < 32) ? Wf + (size_t)row * 256 : Wg + (size_t)(row - 32) * 256;
        return Wh + (size_t)((ocb - 1) * 64 + row) * 256;
    };

#pragma unroll
    for (int p = 0; p < 2; p++) {
        int idx = tid + p * 256; int row = idx >> 3, cc = idx & 7;
        cpa16(&Ws[row * WST + cc * 4], wrow(row) + cc * 4);
    }
#pragma unroll
    for (int p = 0; p < 4; p++) {
        int idx = tid + p * 256; int kk = idx >> 5, cc = idx & 31;
        cpa16(&xs[kk * AXST + cc * 4], &xb[(size_t)kk * NPOS + n0 + cc * 4]);
    }
    cpcommit();
    cpwait0(); __syncthreads();

    for (int it = 0; it < 8; it++) {
        const int cur = it & 1;
        if (it + 1 < 8) {
            const int nxt = cur ^ 1, k0g = (it + 1) * 32;
            float* Wd = Ws + nxt * 64 * WST;
            float* xd = xs + nxt * 32 * AXST;
#pragma unroll
            for (int p = 0; p < 2; p++) {
                int idx = tid + p * 256; int row = idx >> 3, cc = idx & 7;
                cpa16(&Wd[row * WST + cc * 4], wrow(row) + k0g + cc * 4);
            }
#pragma unroll
            for (int p = 0; p < 4; p++) {
                int idx = tid + p * 256; int kk = idx >> 5, cc = idx & 31;
                cpa16(&xd[kk * AXST + cc * 4], &xb[(size_t)(k0g + kk) * NPOS + n0 + cc * 4]);
            }
        }
        cpcommit();

        const float* Wc = Ws + cur * 64 * WST;
        const float* xc = xs + cur * 32 * AXST;
#pragma unroll
        for (int ks = 0; ks < 4; ks++) {
            const int k0 = ks * 8;
            uint32_t a0 = __float_as_uint(Wc[(ms + r) * WST + k0 + c]);
            uint32_t a1 = __float_as_uint(Wc[(ms + r + 8) * WST + k0 + c]);
            uint32_t a2 = __float_as_uint(Wc[(ms + r) * WST + k0 + c + 4]);
            uint32_t a3 = __float_as_uint(Wc[(ms + r + 8) * WST + k0 + c + 4]);
#pragma unroll
            for (int j = 0; j < 8; j++) {
                const int nn = nh * 32 + (j & 3) * 8 + (j >> 2) * 64;
                uint32_t b0 = __float_as_uint(xc[(k0 + c) * AXST + nn + r]);
                uint32_t b1 = __float_as_uint(xc[(k0 + c + 4) * AXST + nn + r]);
                mma8(acc[j][0], acc[j][1], acc[j][2], acc[j][3], a0, a1, a2, a3, b0, b1);
            }
        }
        cpwait0(); __syncthreads();
    }

    // epilogue
    if (ocb == 0 && ms < 32) {
        float* fb = g_f + (size_t)b * CF * NPOS;
#pragma unroll
        for (int j = 0; j < 8; j++) {
            const int nn = nh * 32 + (j & 3) * 8 + (j >> 2) * 64;
            const int n = n0 + nn + 2 * c;
            *(float2*)&fb[(size_t)(ms + r) * NPOS + n] =
                make_float2(tf32r(acc[j][0]), tf32r(acc[j][1]));
            *(float2*)&fb[(size_t)(ms + r + 8) * NPOS + n] =
                make_float2(tf32r(acc[j][2]), tf32r(acc[j][3]));
        }
    } else {
        const int oc0 = ocb * 64 + ms + r;
#pragma unroll
        for (int j = 0; j < 4; j++) {
            float vlo = fmaxf(fmaxf(acc[j][0], acc[j][1]), fmaxf(acc[j + 4][0], acc[j + 4][1]));
            float vhi = fmaxf(fmaxf(acc[j][2], acc[j][3]), fmaxf(acc[j + 4][2], acc[j + 4][3]));
            const int pm = blockIdx.x * 32 + nh * 16 + j * 4 + c;
            if (ocb == 0) {
                float* dst = g_gp + ((size_t)b * CF + (oc0 - 32)) * MPOS;
                dst[pm] = tf32r(vlo);
                dst[8 * MPOS + pm] = tf32r(vhi);
            } else {
                __nv_bfloat16* dst = g_hp + ((size_t)b * CHD + (oc0 - 64)) * MPOS;
                dst[pm] = __float2bfloat16(vlo);
                dst[8 * MPOS + pm] = __float2bfloat16(vhi);
            }
        }
    }
}

// ============================================================
// Kernel C2: FA2 attention (R11 mainloop, unchanged) + FUSED kD:
// o^T kept in smem (dead fs/gs region), then 4 passes of the proven
// kD mma over oc-64 slices (Wo converted into the dead hs region).
// grid (32 q-tiles of 128, 8 b), 256 thr = 8 warps.
// ============================================================
#define CFST 136
#define CGST 72
#define CHSTU 36
#define KC_FS 0
#define KC_GS (32 * CFST)
#define KC_HS (KC_GS + 2 * 32 * CGST)
#define SMEM_C_FLOATS (KC_HS + 2 * 128 * CHSTU)
#define SMEM_C_BYTES (SMEM_C_FLOATS * 4)
// fused-kD smem (unions with the above):
#define OST2 68   // u32 stride for o^T smem rows (k=128 halfs = 64 u32 + pad)
#define WKST 68   // u32 stride for Wo smem rows

__global__ __launch_bounds__(256, 2) void kC2(const float* __restrict__ x,
                                              const float* __restrict__ Wo,
                                              const float* __restrict__ gptr,
                                              float* __restrict__ out) {
    float* fs = smc + KC_FS;                    // [32][136]
    float* gs = smc + KC_GS;                    // 2 x [32][72]
    uint32_t* hs = (uint32_t*)(smc + KC_HS);    // 2 x [128][36]
    uint32_t* os = (uint32_t*)smc;              // [128][68] bf16x2 (unions fs/gs)
    uint32_t* Wb = (uint32_t*)(smc + KC_HS);    // [64][68] bf16x2 (unions hs)

    const int b = blockIdx.y;
    const int n0 = blockIdx.x * 128;
    const int tid = threadIdx.x;
    const int w = tid >> 5, lane = tid & 31;
    const int r = lane >> 2, c = lane & 3;
    const int nq0 = w * 16;
    const float* gp = g_gp + (size_t)b * CF * MPOS;
    const __nv_bfloat16* hp = g_hp + (size_t)b * CHD * MPOS;
    const float* fp = g_f + (size_t)b * CF * NPOS + n0;

    // initial loads: fs (whole), gs(t0), hs(t0)
#pragma unroll
    for (int p = 0; p < 4; p++) {
        int idx = tid + p * 256; int rr = idx >> 5, cc = idx & 31;
        cpa16(&fs[rr * CFST + cc * 4], &fp[(size_t)rr * NPOS + cc * 4]);
    }
#pragma unroll
    for (int p = 0; p < 2; p++) {
        int idx = tid + p * 256; int rr = idx >> 4, cc = idx & 15;
        cpa16(&gs[rr * CGST + cc * 4], &gp[(size_t)rr * MPOS + cc * 4]);
    }
#pragma unroll
    for (int p = 0; p < 4; p++) {
        int idx = tid + p * 256; int rr = idx >> 3, cc = idx & 7;
        cpa16(&hs[rr * CHSTU + cc * 4], &hp[(size_t)rr * MPOS + cc * 8]);
    }
    cpcommit(); cpwait0(); __syncthreads();

    const int i7 = lane & 7, s2 = (lane >> 3) & 1, s4 = lane >> 4;

    float rs0 = 0.f, rs1 = 0.f;
    {
        float acc[16][4];
#pragma unroll
        for (int i = 0; i < 16; i++)
#pragma unroll
            for (int q = 0; q < 4; q++) acc[i][q] = 0.f;

        for (int t = 0; t < 16; t++) {
            const int cur = t & 1;
            const float* gsc = gs + cur * 32 * CGST;
            const uint32_t* hsc = hs + cur * 128 * CHSTU;

            if (t + 1 < 16) {
                const int m1 = (t + 1) * 64;
                float* gsd = gs + (cur ^ 1) * 32 * CGST;
                uint32_t* hsd = hs + (cur ^ 1) * 128 * CHSTU;
#pragma unroll
                for (int p = 0; p < 2; p++) {
                    int idx = tid + p * 256; int rr = idx >> 4, cc = idx & 15;
                    cpa16(&gsd[rr * CGST + cc * 4], &gp[(size_t)rr * MPOS + m1 + cc * 4]);
                }
#pragma unroll
                for (int p = 0; p < 4; p++) {
                    int idx = tid + p * 256; int rr = idx >> 3, cc = idx & 7;
                    cpa16(&hsd[rr * CHSTU + cc * 4], &hp[(size_t)rr * MPOS + m1 + cc * 8]);
                }
            }
            cpcommit();

            // ---- score mma (tf32): S[n16][m8], A = f, B = g ----
            uint32_t af[4][4];
#pragma unroll
            for (int half = 0; half < 2; half++) {
                float sc[4][4];
#pragma unroll
                for (int j2 = 0; j2 < 4; j2++)
#pragma unroll
                    for (int q = 0; q < 4; q++) sc[j2][q] = 0.f;
#pragma unroll
                for (int ks = 0; ks < 4; ks++) {
                    const int k0 = ks * 8;
                    uint32_t a0 = __float_as_uint(fs[(k0 + c) * CFST + nq0 + r]);
                    uint32_t a1 = __float_as_uint(fs[(k0 + c) * CFST + nq0 + r + 8]);
                    uint32_t a2 = __float_as_uint(fs[(k0 + c + 4) * CFST + nq0 + r]);
                    uint32_t a3 = __float_as_uint(fs[(k0 + c + 4) * CFST + nq0 + r + 8]);
#pragma unroll
                    for (int j2 = 0; j2 < 4; j2++) {
                        const int mof = half * 32 + j2 * 8;
                        uint32_t b0 = __float_as_uint(gsc[(k0 + c) * CGST + mof + r]);
                        uint32_t b1 = __float_as_uint(gsc[(k0 + c + 4) * CGST + mof + r]);
                        mma8(sc[j2][0], sc[j2][1], sc[j2][2], sc[j2][3],
                             a0, a1, a2, a3, b0, b1);
                    }
                }
#pragma unroll
                for (int mo2 = 0; mo2 < 2; mo2++) {
                    float e00 = __expf(sc[2 * mo2][0]),     e01 = __expf(sc[2 * mo2][1]);
                    float e02 = __expf(sc[2 * mo2][2]),     e03 = __expf(sc[2 * mo2][3]);
                    float e10 = __expf(sc[2 * mo2 + 1][0]), e11 = __expf(sc[2 * mo2 + 1][1]);
                    float e12 = __expf(sc[2 * mo2 + 1][2]), e13 = __expf(sc[2 * mo2 + 1][3]);
                    __nv_bfloat162 p0 = __floats2bfloat162_rn(e00, e01);
                    __nv_bfloat162 p1 = __floats2bfloat162_rn(e02, e03);
                    __nv_bfloat162 p2 = __floats2bfloat162_rn(e10, e11);
                    __nv_bfloat162 p3 = __floats2bfloat162_rn(e12, e13);
                    const int mo = half * 2 + mo2;
                    af[mo][0] = *(uint32_t*)&p0;
                    af[mo][1] = *(uint32_t*)&p1;
                    af[mo][2] = *(uint32_t*)&p2;
                    af[mo][3] = *(uint32_t*)&p3;
                    rs0 += (e00 + e01) + (e10 + e11);
                    rs1 += (e02 + e03) + (e12 + e13);
                }
            }

            // ---- o-mma (bf16 k16): o^T[n16][c128] += P * h ----
            {
                const uint32_t hs_sb = (uint32_t)__cvta_generic_to_shared(hsc);
#pragma unroll
                for (int mo = 0; mo < 4; mo++) {
#pragma unroll
                    for (int cg = 0; cg < 8; cg++) {
                        uint32_t b0, b1, b2, b3;
                        ldm4(b0, b1, b2, b3,
                             hs_sb + (uint32_t)(((cg * 16 + s4 * 8 + i7) * CHSTU + s2 * 4 + mo * 8) * 4));
                        mma16b(acc[2 * cg][0], acc[2 * cg][1], acc[2 * cg][2], acc[2 * cg][3],
                               af[mo][0], af[mo][1], af[mo][2], af[mo][3], b0, b1);
                        mma16b(acc[2 * cg + 1][0], acc[2 * cg + 1][1], acc[2 * cg + 1][2], acc[2 * cg + 1][3],
                               af[mo][0], af[mo][1], af[mo][2], af[mo][3], b2, b3);
                    }
                }
            }
            cpwait0();
            __syncthreads();
        }

        // ---- rowsum: warp-local xor reduce over the 4 c-lanes ----
#pragma unroll
        for (int off = 1; off < 4; off <<= 1) {
            rs0 += __shfl_xor_sync(0xffffffffu, rs0, off);
            rs1 += __shfl_xor_sync(0xffffffffu, rs1, off);
        }
        const float inv0 = 1.f / rs0, inv1 = 1.f / rs1;

        // ---- normalize + store o^T bf16 [n][c] into SMEM (os) ----
        // (all smem reads of fs/gs/hs completed at the final mainloop sync)
#pragma unroll
        for (int tt = 0; tt < 16; tt++) {
            __nv_bfloat162 v0 = __floats2bfloat162_rn(acc[tt][0] * inv0, acc[tt][1] * inv0);
            __nv_bfloat162 v1 = __floats2bfloat162_rn(acc[tt][2] * inv1, acc[tt][3] * inv1);
            os[(nq0 + r) * OST2 + tt * 4 + c]     = *(uint32_t*)&v0;
            os[(nq0 + r + 8) * OST2 + tt * 4 + c] = *(uint32_t*)&v1;
        }
    }

    // ================= fused kD phase =================
    const float gamma = *gptr;
    const int ms = (w & 3) * 16, nh = w >> 2;
    const uint32_t w_sb = (uint32_t)__cvta_generic_to_shared(Wb);
    const uint32_t o_sb = (uint32_t)__cvta_generic_to_shared(os);
    const uint32_t a_off = (uint32_t)((ms + s2 * 8 + i7) * WKST + s4 * 4);
    const uint32_t b_off = (uint32_t)((nh * 64 + s4 * 8 + i7) * OST2 + s2 * 4);
    const float* xb = x + (size_t)b * CC * NPOS;
    float* outb = out + (size_t)b * CC * NPOS;

    // convert Wo slice for pass 0 (hs region is dead after mainloop)
#pragma unroll
    for (int p = 0; p < 8; p++) {
        int idx = tid + p * 256; int row = idx >> 5, cc = idx & 31;
        float4 v = *(const float4*)&Wo[(size_t)row * CHD + cc * 4];
        __nv_bfloat162 lo = __floats2bfloat162_rn(v.x, v.y);
        __nv_bfloat162 hi = __floats2bfloat162_rn(v.z, v.w);
        Wb[row * WKST + cc * 2]     = *(uint32_t*)&lo;
        Wb[row * WKST + cc * 2 + 1] = *(uint32_t*)&hi;
    }
    __syncthreads();   // os + Wb(0) visible to all warps

    for (int pass = 0; pass < 4; pass++) {
        float acc[8][4];
#pragma unroll
        for (int j = 0; j < 8; j++)
#pragma unroll
            for (int q = 0; q < 4; q++) acc[j][q] = 0.f;

#pragma unroll
        for (int s = 0; s < 8; s++) {
            uint32_t a0, a1, a2, a3;
            ldm4(a0, a1, a2, a3, w_sb + (a_off + s * 8) * 4);
#pragma unroll
            for (int jp = 0; jp < 4; jp++) {
                uint32_t b0, b1, b2, b3;
                ldm4(b0, b1, b2, b3, o_sb + (b_off + jp * 16 * OST2 + s * 8) * 4);
                mma16b(acc[2 * jp][0], acc[2 * jp][1], acc[2 * jp][2], acc[2 * jp][3],
                       a0, a1, a2, a3, b0, b1);
                mma16b(acc[2 * jp + 1][0], acc[2 * jp + 1][1], acc[2 * jp + 1][2], acc[2 * jp + 1][3],
                       a0, a1, a2, a3, b2, b3);
            }
        }

        // epilogue: out = gamma * acc + x
        const int oc0 = pass * 64 + ms + r;
#pragma unroll
        for (int j = 0; j < 8; j++) {
            const int n = n0 + nh * 64 + j * 8 + 2 * c;
            size_t p0 = (size_t)oc0 * NPOS + n;
            size_t p1 = (size_t)(oc0 + 8) * NPOS + n;
            float2 x0 = *(const float2*)&xb[p0];
            float2 x1 = *(const float2*)&xb[p1];
            *(float2*)&outb[p0] = make_float2(fmaf(gamma, acc[j][0], x0.x),
                                              fmaf(gamma, acc[j][1], x0.y));
            *(float2*)&outb[p1] = make_float2(fmaf(gamma, acc[j][2], x1.x),
                                              fmaf(gamma, acc[j][3], x1.y));
        }

        if (pass < 3) {
            __syncthreads();   // all ldmatrix reads of Wb done
#pragma unroll
            for (int p = 0; p < 8; p++) {
                int idx = tid + p * 256; int row = idx >> 5, cc = idx & 31;
                float4 v = *(const float4*)&Wo[(size_t)((pass + 1) * 64 + row) * CHD + cc * 4];
                __nv_bfloat162 lo = __floats2bfloat162_rn(v.x, v.y);
                __nv_bfloat162 hi = __floats2bfloat162_rn(v.z, v.w);
                Wb[row * WKST + cc * 2]     = *(uint32_t*)&lo;
                Wb[row * WKST + cc * 2 + 1] = *(uint32_t*)&hi;
            }
            __syncthreads();   // Wb(pass+1) visible
        }
    }
}

// ============================================================
extern "C" void kernel_launch(void* const* d_in, const int* in_sizes, int n_in,
                              void* d_out, int out_size) {
    const float* x     = (const float*)d_in[0];
    const float* Wf    = (const float*)d_in[1];
    const float* Wg    = (const float*)d_in[2];
    const float* Wh    = (const float*)d_in[3];
    const float* Wo    = (const float*)d_in[4];
    const float* gamma = (const float*)d_in[5];
    float* out = (float*)d_out;

    cudaFuncSetAttribute(kA, cudaFuncAttributeMaxDynamicSharedMemorySize, SMEM_A_BYTES);
    cudaFuncSetAttribute(kC2, cudaFuncAttributeMaxDynamicSharedMemorySize, SMEM_C_BYTES);

    kA<<<dim3(32, 3, 8), 256, SMEM_A_BYTES>>>(x, Wf, Wg, Wh);
    kC2<<<dim3(32, 8), 256, SMEM_C_BYTES>>>(x, Wo, gamma, out);
}

// round 14
// speedup vs baseline: 5.4226x; 1.0034x over previous
#include <cuda_runtime.h>
#include <cuda_bf16.h>
#include <cstdint>

#define BB 8
#define CC 256
#define NPOS 4096   // 64*64
#define MPOS 1024   // 32*32
#define CF 32       // C/8
#define CHD 128     // C/2

// ---- scratch (static device globals; no allocation) ----
__device__ float g_f[(size_t)BB * CF * NPOS];                      // f*log2e (tf32-rounded fp32)
__device__ float g_gp[(size_t)BB * CF * MPOS];                     // pooled g (tf32-rounded fp32)
__device__ __align__(16) __nv_bfloat16 g_hp[(size_t)BB * CHD * MPOS];   // pooled h (bf16)

// ---- helpers ----
__device__ __forceinline__ void cpa16(void* s, const void* g) {
    unsigned sa = (unsigned)__cvta_generic_to_shared(s);
    asm volatile("cp.async.ca.shared.global [%0], [%1], 16;\n" :: "r"(sa), "l"(g));
}
__device__ __forceinline__ void cpcommit() { asm volatile("cp.async.commit_group;\n" ::); }
__device__ __forceinline__ void cpwait0()  { asm volatile("cp.async.wait_group 0;\n" ::); }

__device__ __forceinline__ float tf32r(float x) {
    uint32_t u;
    asm("cvt.rna.tf32.f32 %0, %1;" : "=r"(u) : "f"(x));
    return __uint_as_float(u);
}
__device__ __forceinline__ float ex2f(float x) {
    float y;
    asm("ex2.approx.f32 %0, %1;" : "=f"(y) : "f"(x));
    return y;
}

__device__ __forceinline__ void mma8(float& c0, float& c1, float& c2, float& c3,
                                     uint32_t a0, uint32_t a1, uint32_t a2, uint32_t a3,
                                     uint32_t b0, uint32_t b1) {
    asm volatile("mma.sync.aligned.m16n8k8.row.col.f32.tf32.tf32.f32 "
                 "{%0,%1,%2,%3}, {%4,%5,%6,%7}, {%8,%9}, {%0,%1,%2,%3};"
                 : "+f"(c0), "+f"(c1), "+f"(c2), "+f"(c3)
                 : "r"(a0), "r"(a1), "r"(a2), "r"(a3), "r"(b0), "r"(b1));
}

__device__ __forceinline__ void mma16b(float& c0, float& c1, float& c2, float& c3,
                                       uint32_t a0, uint32_t a1, uint32_t a2, uint32_t a3,
                                       uint32_t b0, uint32_t b1) {
    asm volatile("mma.sync.aligned.m16n8k16.row.col.f32.bf16.bf16.f32 "
                 "{%0,%1,%2,%3}, {%4,%5,%6,%7}, {%8,%9}, {%0,%1,%2,%3};"
                 : "+f"(c0), "+f"(c1), "+f"(c2), "+f"(c3)
                 : "r"(a0), "r"(a1), "r"(a2), "r"(a3), "r"(b0), "r"(b1));
}

__device__ __forceinline__ void ldm4(uint32_t& r0, uint32_t& r1, uint32_t& r2, uint32_t& r3,
                                     uint32_t saddr) {
    asm volatile("ldmatrix.sync.aligned.m8n8.x4.shared.b16 {%0,%1,%2,%3}, [%4];"
                 : "=r"(r0), "=r"(r1), "=r"(r2), "=r"(r3) : "r"(saddr));
}

extern __shared__ float smc[];

// ============================================================
// Kernel A: [f;g;h] = Wcat @ x via tf32 mma — PROVEN R12 version
// (n-tile 128), with LOG2E pre-scale added to the f epilogue.
// grid (32 n-tiles of 128, 3 oc-tiles of 64, 8 b), 256 thr = 8 warps.
// ============================================================
#define WST 36
#define AXST 136
#define KA_WS 0
#define KA_XS (2 * 64 * WST)
#define SMEM_A_BYTES ((KA_XS + 2 * 32 * AXST) * 4)
#define LOG2E 1.4426950408889634f

__global__ __launch_bounds__(256, 3) void kA(const float* __restrict__ x,
                                             const float* __restrict__ Wf,
                                             const float* __restrict__ Wg,
                                             const float* __restrict__ Wh) {
    float* Ws = smc + KA_WS;   // 2 x [64][36]
    float* xs = smc + KA_XS;   // 2 x [32][136]
    const int b = blockIdx.z, ocb = blockIdx.y;
    const int n0 = blockIdx.x * 128;
    const int tid = threadIdx.x;
    const int w = tid >> 5, lane = tid & 31;
    const int r = lane >> 2, c = lane & 3;
    const int ms = (w & 3) * 16, nh = w >> 2;
    const float* xb = x + (size_t)b * CC * NPOS;

    float acc[8][4];
#pragma unroll
    for (int j = 0; j < 8; j++)
#pragma unroll
        for (int q = 0; q < 4; q++) acc[j][q] = 0.f;

    auto wrow = [&](int row) -> const float* {
        if (ocb == 0) return (row < 32) ? Wf + (size_t)row * 256 : Wg + (size_t)(row - 32) * 256;
        return Wh + (size_t)((ocb - 1) * 64 + row) * 256;
    };

#pragma unroll
    for (int p = 0; p < 2; p++) {
        int idx = tid + p * 256; int row = idx >> 3, cc = idx & 7;
        cpa16(&Ws[row * WST + cc * 4], wrow(row) + cc * 4);
    }
#pragma unroll
    for (int p = 0; p < 4; p++) {
        int idx = tid + p * 256; int kk = idx >> 5, cc = idx & 31;
        cpa16(&xs[kk * AXST + cc * 4], &xb[(size_t)kk * NPOS + n0 + cc * 4]);
    }
    cpcommit();
    cpwait0(); __syncthreads();

    for (int it = 0; it < 8; it++) {
        const int cur = it & 1;
        if (it + 1 < 8) {
            const int nxt = cur ^ 1, k0g = (it + 1) * 32;
            float* Wd = Ws + nxt * 64 * WST;
            float* xd = xs + nxt * 32 * AXST;
#pragma unroll
            for (int p = 0; p < 2; p++) {
                int idx = tid + p * 256; int row = idx >> 3, cc = idx & 7;
                cpa16(&Wd[row * WST + cc * 4], wrow(row) + k0g + cc * 4);
            }
#pragma unroll
            for (int p = 0; p < 4; p++) {
                int idx = tid + p * 256; int kk = idx >> 5, cc = idx & 31;
                cpa16(&xd[kk * AXST + cc * 4], &xb[(size_t)(k0g + kk) * NPOS + n0 + cc * 4]);
            }
        }
        cpcommit();

        const float* Wc = Ws + cur * 64 * WST;
        const float* xc = xs + cur * 32 * AXST;
#pragma unroll
        for (int ks = 0; ks < 4; ks++) {
            const int k0 = ks * 8;
            uint32_t a0 = __float_as_uint(Wc[(ms + r) * WST + k0 + c]);
            uint32_t a1 = __float_as_uint(Wc[(ms + r + 8) * WST + k0 + c]);
            uint32_t a2 = __float_as_uint(Wc[(ms + r) * WST + k0 + c + 4]);
            uint32_t a3 = __float_as_uint(Wc[(ms + r + 8) * WST + k0 + c + 4]);
#pragma unroll
            for (int j = 0; j < 8; j++) {
                const int nn = nh * 32 + (j & 3) * 8 + (j >> 2) * 64;
                uint32_t b0 = __float_as_uint(xc[(k0 + c) * AXST + nn + r]);
                uint32_t b1 = __float_as_uint(xc[(k0 + c + 4) * AXST + nn + r]);
                mma8(acc[j][0], acc[j][1], acc[j][2], acc[j][3], a0, a1, a2, a3, b0, b1);
            }
        }
        cpwait0(); __syncthreads();
    }

    // epilogue
    if (ocb == 0 && ms < 32) {
        // f rows: pre-scale by log2(e), tf32-round, store
        float* fb = g_f + (size_t)b * CF * NPOS;
#pragma unroll
        for (int j = 0; j < 8; j++) {
            const int nn = nh * 32 + (j & 3) * 8 + (j >> 2) * 64;
            const int n = n0 + nn + 2 * c;
            *(float2*)&fb[(size_t)(ms + r) * NPOS + n] =
                make_float2(tf32r(acc[j][0] * LOG2E), tf32r(acc[j][1] * LOG2E));
            *(float2*)&fb[(size_t)(ms + r + 8) * NPOS + n] =
                make_float2(tf32r(acc[j][2] * LOG2E), tf32r(acc[j][3] * LOG2E));
        }
    } else {
        const int oc0 = ocb * 64 + ms + r;
#pragma unroll
        for (int j = 0; j < 4; j++) {
            float vlo = fmaxf(fmaxf(acc[j][0], acc[j][1]), fmaxf(acc[j + 4][0], acc[j + 4][1]));
            float vhi = fmaxf(fmaxf(acc[j][2], acc[j][3]), fmaxf(acc[j + 4][2], acc[j + 4][3]));
            const int pm = blockIdx.x * 32 + nh * 16 + j * 4 + c;
            if (ocb == 0) {
                float* dst = g_gp + ((size_t)b * CF + (oc0 - 32)) * MPOS;
                dst[pm] = tf32r(vlo);
                dst[8 * MPOS + pm] = tf32r(vhi);
            } else {
                __nv_bfloat16* dst = g_hp + ((size_t)b * CHD + (oc0 - 64)) * MPOS;
                dst[pm] = __float2bfloat16(vlo);
                dst[8 * MPOS + pm] = __float2bfloat16(vhi);
            }
        }
    }
}

// ============================================================
// Kernel C2: FA2 attention + fused kD.
// exp via raw ex2 (f pre-scaled), kD Wb double-buffered (1 sync/pass).
// grid (32 q-tiles of 128, 8 b), 256 thr = 8 warps.
// ============================================================
#define CFST 136
#define CGST 72
#define CHSTU 36
#define KC_FS 0
#define KC_GS (32 * CFST)
#define KC_HS (KC_GS + 2 * 32 * CGST)
#define SMEM_C_FLOATS (KC_HS + 2 * 128 * CHSTU)
#define SMEM_C_BYTES (SMEM_C_FLOATS * 4)
#define OST2 68   // u32 stride for o^T smem rows
#define WKST 68   // u32 stride for Wo smem rows

__global__ __launch_bounds__(256, 2) void kC2(const float* __restrict__ x,
                                              const float* __restrict__ Wo,
                                              const float* __restrict__ gptr,
                                              float* __restrict__ out) {
    float* fs = smc + KC_FS;                    // [32][136]
    float* gs = smc + KC_GS;                    // 2 x [32][72]
    uint32_t* hs = (uint32_t*)(smc + KC_HS);    // 2 x [128][36]
    uint32_t* os = (uint32_t*)smc;              // [128][68] bf16x2 (unions fs/gs)
    uint32_t* Wb = (uint32_t*)(smc + KC_HS);    // 2 x [64][68] bf16x2 (unions hs)

    const int b = blockIdx.y;
    const int n0 = blockIdx.x * 128;
    const int tid = threadIdx.x;
    const int w = tid >> 5, lane = tid & 31;
    const int r = lane >> 2, c = lane & 3;
    const int nq0 = w * 16;
    const float* gp = g_gp + (size_t)b * CF * MPOS;
    const __nv_bfloat16* hp = g_hp + (size_t)b * CHD * MPOS;
    const float* fp = g_f + (size_t)b * CF * NPOS + n0;

    // initial loads: fs (whole), gs(t0), hs(t0)
#pragma unroll
    for (int p = 0; p < 4; p++) {
        int idx = tid + p * 256; int rr = idx >> 5, cc = idx & 31;
        cpa16(&fs[rr * CFST + cc * 4], &fp[(size_t)rr * NPOS + cc * 4]);
    }
#pragma unroll
    for (int p = 0; p < 2; p++) {
        int idx = tid + p * 256; int rr = idx >> 4, cc = idx & 15;
        cpa16(&gs[rr * CGST + cc * 4], &gp[(size_t)rr * MPOS + cc * 4]);
    }
#pragma unroll
    for (int p = 0; p < 4; p++) {
        int idx = tid + p * 256; int rr = idx >> 3, cc = idx & 7;
        cpa16(&hs[rr * CHSTU + cc * 4], &hp[(size_t)rr * MPOS + cc * 8]);
    }
    cpcommit(); cpwait0(); __syncthreads();

    const int i7 = lane & 7, s2 = (lane >> 3) & 1, s4 = lane >> 4;

    float rs0 = 0.f, rs1 = 0.f;
    {
        float acc[16][4];
#pragma unroll
        for (int i = 0; i < 16; i++)
#pragma unroll
            for (int q = 0; q < 4; q++) acc[i][q] = 0.f;

        for (int t = 0; t < 16; t++) {
            const int cur = t & 1;
            const float* gsc = gs + cur * 32 * CGST;
            const uint32_t* hsc = hs + cur * 128 * CHSTU;

            if (t + 1 < 16) {
                const int m1 = (t + 1) * 64;
                float* gsd = gs + (cur ^ 1) * 32 * CGST;
                uint32_t* hsd = hs + (cur ^ 1) * 128 * CHSTU;
#pragma unroll
                for (int p = 0; p < 2; p++) {
                    int idx = tid + p * 256; int rr = idx >> 4, cc = idx & 15;
                    cpa16(&gsd[rr * CGST + cc * 4], &gp[(size_t)rr * MPOS + m1 + cc * 4]);
                }
#pragma unroll
                for (int p = 0; p < 4; p++) {
                    int idx = tid + p * 256; int rr = idx >> 3, cc = idx & 7;
                    cpa16(&hsd[rr * CHSTU + cc * 4], &hp[(size_t)rr * MPOS + m1 + cc * 8]);
                }
            }
            cpcommit();

            // ---- score mma (tf32): S'[n16][m8] = (f*log2e)^T g ----
            uint32_t af[4][4];
#pragma unroll
            for (int half = 0; half < 2; half++) {
                float sc[4][4];
#pragma unroll
                for (int j2 = 0; j2 < 4; j2++)
#pragma unroll
                    for (int q = 0; q < 4; q++) sc[j2][q] = 0.f;
#pragma unroll
                for (int ks = 0; ks < 4; ks++) {
                    const int k0 = ks * 8;
                    uint32_t a0 = __float_as_uint(fs[(k0 + c) * CFST + nq0 + r]);
                    uint32_t a1 = __float_as_uint(fs[(k0 + c) * CFST + nq0 + r + 8]);
                    uint32_t a2 = __float_as_uint(fs[(k0 + c + 4) * CFST + nq0 + r]);
                    uint32_t a3 = __float_as_uint(fs[(k0 + c + 4) * CFST + nq0 + r + 8]);
#pragma unroll
                    for (int j2 = 0; j2 < 4; j2++) {
                        const int mof = half * 32 + j2 * 8;
                        uint32_t b0 = __float_as_uint(gsc[(k0 + c) * CGST + mof + r]);
                        uint32_t b1 = __float_as_uint(gsc[(k0 + c + 4) * CGST + mof + r]);
                        mma8(sc[j2][0], sc[j2][1], sc[j2][2], sc[j2][3],
                             a0, a1, a2, a3, b0, b1);
                    }
                }
#pragma unroll
                for (int mo2 = 0; mo2 < 2; mo2++) {
                    float e00 = ex2f(sc[2 * mo2][0]),     e01 = ex2f(sc[2 * mo2][1]);
                    float e02 = ex2f(sc[2 * mo2][2]),     e03 = ex2f(sc[2 * mo2][3]);
                    float e10 = ex2f(sc[2 * mo2 + 1][0]), e11 = ex2f(sc[2 * mo2 + 1][1]);
                    float e12 = ex2f(sc[2 * mo2 + 1][2]), e13 = ex2f(sc[2 * mo2 + 1][3]);
                    __nv_bfloat162 p0 = __floats2bfloat162_rn(e00, e01);
                    __nv_bfloat162 p1 = __floats2bfloat162_rn(e02, e03);
                    __nv_bfloat162 p2 = __floats2bfloat162_rn(e10, e11);
                    __nv_bfloat162 p3 = __floats2bfloat162_rn(e12, e13);
                    const int mo = half * 2 + mo2;
                    af[mo][0] = *(uint32_t*)&p0;
                    af[mo][1] = *(uint32_t*)&p1;
                    af[mo][2] = *(uint32_t*)&p2;
                    af[mo][3] = *(uint32_t*)&p3;
                    rs0 += (e00 + e01) + (e10 + e11);
                    rs1 += (e02 + e03) + (e12 + e13);
                }
            }

            // ---- o-mma (bf16 k16): o^T[n16][c128] += P * h ----
            {
                const uint32_t hs_sb = (uint32_t)__cvta_generic_to_shared(hsc);
#pragma unroll
                for (int mo = 0; mo < 4; mo++) {
#pragma unroll
                    for (int cg = 0; cg < 8; cg++) {
                        uint32_t b0, b1, b2, b3;
                        ldm4(b0, b1, b2, b3,
                             hs_sb + (uint32_t)(((cg * 16 + s4 * 8 + i7) * CHSTU + s2 * 4 + mo * 8) * 4));
                        mma16b(acc[2 * cg][0], acc[2 * cg][1], acc[2 * cg][2], acc[2 * cg][3],
                               af[mo][0], af[mo][1], af[mo][2], af[mo][3], b0, b1);
                        mma16b(acc[2 * cg + 1][0], acc[2 * cg + 1][1], acc[2 * cg + 1][2], acc[2 * cg + 1][3],
                               af[mo][0], af[mo][1], af[mo][2], af[mo][3], b2, b3);
                    }
                }
            }
            cpwait0();
            __syncthreads();
        }

        // ---- rowsum: warp-local xor reduce over the 4 c-lanes ----
#pragma unroll
        for (int off = 1; off < 4; off <<= 1) {
            rs0 += __shfl_xor_sync(0xffffffffu, rs0, off);
            rs1 += __shfl_xor_sync(0xffffffffu, rs1, off);
        }
        const float inv0 = 1.f / rs0, inv1 = 1.f / rs1;

        // ---- normalize + store o^T bf16 [n][c] into SMEM (os) ----
#pragma unroll
        for (int tt = 0; tt < 16; tt++) {
            __nv_bfloat162 v0 = __floats2bfloat162_rn(acc[tt][0] * inv0, acc[tt][1] * inv0);
            __nv_bfloat162 v1 = __floats2bfloat162_rn(acc[tt][2] * inv1, acc[tt][3] * inv1);
            os[(nq0 + r) * OST2 + tt * 4 + c]     = *(uint32_t*)&v0;
            os[(nq0 + r + 8) * OST2 + tt * 4 + c] = *(uint32_t*)&v1;
        }
    }

    // ================= fused kD phase (Wb double-buffered) =================
    const float gamma = *gptr;
    const int ms = (w & 3) * 16, nh = w >> 2;
    const uint32_t o_sb = (uint32_t)__cvta_generic_to_shared(os);
    const uint32_t wb_sb = (uint32_t)__cvta_generic_to_shared(Wb);
    const uint32_t a_off = (uint32_t)((ms + s2 * 8 + i7) * WKST + s4 * 4);
    const uint32_t b_off = (uint32_t)((nh * 64 + s4 * 8 + i7) * OST2 + s2 * 4);
    const float* xb = x + (size_t)b * CC * NPOS;
    float* outb = out + (size_t)b * CC * NPOS;

    // convert Wo slice for pass 0 into Wb[0]
#pragma unroll
    for (int p = 0; p < 8; p++) {
        int idx = tid + p * 256; int row = idx >> 5, cc = idx & 31;
        float4 v = *(const float4*)&Wo[(size_t)row * CHD + cc * 4];
        __nv_bfloat162 lo = __floats2bfloat162_rn(v.x, v.y);
        __nv_bfloat162 hi = __floats2bfloat162_rn(v.z, v.w);
        Wb[row * WKST + cc * 2]     = *(uint32_t*)&lo;
        Wb[row * WKST + cc * 2 + 1] = *(uint32_t*)&hi;
    }
    __syncthreads();   // os + Wb[0] visible

    for (int pass = 0; pass < 4; pass++) {
        const uint32_t w_sb = wb_sb + (uint32_t)((pass & 1) * 64 * WKST * 4);
        float acc[8][4];
#pragma unroll
        for (int j = 0; j < 8; j++)
#pragma unroll
            for (int q = 0; q < 4; q++) acc[j][q] = 0.f;

#pragma unroll
        for (int s = 0; s < 8; s++) {
            uint32_t a0, a1, a2, a3;
            ldm4(a0, a1, a2, a3, w_sb + (a_off + s * 8) * 4);
#pragma unroll
            for (int jp = 0; jp < 4; jp++) {
                uint32_t b0, b1, b2, b3;
                ldm4(b0, b1, b2, b3, o_sb + (b_off + jp * 16 * OST2 + s * 8) * 4);
                mma16b(acc[2 * jp][0], acc[2 * jp][1], acc[2 * jp][2], acc[2 * jp][3],
                       a0, a1, a2, a3, b0, b1);
                mma16b(acc[2 * jp + 1][0], acc[2 * jp + 1][1], acc[2 * jp + 1][2], acc[2 * jp + 1][3],
                       a0, a1, a2, a3, b2, b3);
            }
        }

        // convert next pass's Wo slice into the alternate buffer
        if (pass < 3) {
            uint32_t* Wn = Wb + ((pass + 1) & 1) * 64 * WKST;
#pragma unroll
            for (int p = 0; p < 8; p++) {
                int idx = tid + p * 256; int row = idx >> 5, cc = idx & 31;
                float4 v = *(const float4*)&Wo[(size_t)((pass + 1) * 64 + row) * CHD + cc * 4];
                __nv_bfloat162 lo = __floats2bfloat162_rn(v.x, v.y);
                __nv_bfloat162 hi = __floats2bfloat162_rn(v.z, v.w);
                Wn[row * WKST + cc * 2]     = *(uint32_t*)&lo;
                Wn[row * WKST + cc * 2 + 1] = *(uint32_t*)&hi;
            }
        }

        // epilogue: out = gamma * acc + x
        const int oc0 = pass * 64 + ms + r;
#pragma unroll
        for (int j = 0; j < 8; j++) {
            const int n = n0 + nh * 64 + j * 8 + 2 * c;
            size_t p0 = (size_t)oc0 * NPOS + n;
            size_t p1 = (size_t)(oc0 + 8) * NPOS + n;
            float2 x0 = *(const float2*)&xb[p0];
            float2 x1 = *(const float2*)&xb[p1];
            *(float2*)&outb[p0] = make_float2(fmaf(gamma, acc[j][0], x0.x),
                                              fmaf(gamma, acc[j][1], x0.y));
            *(float2*)&outb[p1] = make_float2(fmaf(gamma, acc[j][2], x1.x),
                                              fmaf(gamma, acc[j][3], x1.y));
        }

        if (pass < 3) __syncthreads();   // Wb[next] visible; this pass's reads done
    }
}

// ============================================================
extern "C" void kernel_launch(void* const* d_in, const int* in_sizes, int n_in,
                              void* d_out, int out_size) {
    const float* x     = (const float*)d_in[0];
    const float* Wf    = (const float*)d_in[1];
    const float* Wg    = (const float*)d_in[2];
    const float* Wh    = (const float*)d_in[3];
    const float* Wo    = (const float*)d_in[4];
    const float* gamma = (const float*)d_in[5];
    float* out = (float*)d_out;

    cudaFuncSetAttribute(kA, cudaFuncAttributeMaxDynamicSharedMemorySize, SMEM_A_BYTES);
    cudaFuncSetAttribute(kC2, cudaFuncAttributeMaxDynamicSharedMemorySize, SMEM_C_BYTES);

    kA<<<dim3(32, 3, 8), 256, SMEM_A_BYTES>>>(x, Wf, Wg, Wh);
    kC2<<<dim3(32, 8), 256, SMEM_C_BYTES>>>(x, Wo, gamma, out);
}

// round 15
// speedup vs baseline: 5.6913x; 1.0495x over previous
#include <cuda_runtime.h>
#include <cuda_bf16.h>
#include <cstdint>

#define BB 8
#define CC 256
#define NPOS 4096   // 64*64
#define MPOS 1024   // 32*32
#define CF 32       // C/8
#define CHD 128     // C/2

// ---- scratch (static device globals; no allocation) ----
__device__ float g_f[(size_t)BB * CF * NPOS];                      // f*log2e (tf32-rounded fp32)
__device__ float g_gp[(size_t)BB * CF * MPOS];                     // pooled g (tf32-rounded fp32)
__device__ __align__(16) __nv_bfloat16 g_hp[(size_t)BB * CHD * MPOS];   // pooled h (bf16)

// ---- helpers ----
__device__ __forceinline__ void cpa16(void* s, const void* g) {
    unsigned sa = (unsigned)__cvta_generic_to_shared(s);
    asm volatile("cp.async.ca.shared.global [%0], [%1], 16;\n" :: "r"(sa), "l"(g));
}
__device__ __forceinline__ void cpcommit() { asm volatile("cp.async.commit_group;\n" ::); }
__device__ __forceinline__ void cpwait0()  { asm volatile("cp.async.wait_group 0;\n" ::); }

__device__ __forceinline__ float tf32r(float x) {
    uint32_t u;
    asm("cvt.rna.tf32.f32 %0, %1;" : "=r"(u) : "f"(x));
    return __uint_as_float(u);
}
__device__ __forceinline__ float ex2f(float x) {
    float y;
    asm("ex2.approx.f32 %0, %1;" : "=f"(y) : "f"(x));
    return y;
}

__device__ __forceinline__ void mma8(float& c0, float& c1, float& c2, float& c3,
                                     uint32_t a0, uint32_t a1, uint32_t a2, uint32_t a3,
                                     uint32_t b0, uint32_t b1) {
    asm volatile("mma.sync.aligned.m16n8k8.row.col.f32.tf32.tf32.f32 "
                 "{%0,%1,%2,%3}, {%4,%5,%6,%7}, {%8,%9}, {%0,%1,%2,%3};"
                 : "+f"(c0), "+f"(c1), "+f"(c2), "+f"(c3)
                 : "r"(a0), "r"(a1), "r"(a2), "r"(a3), "r"(b0), "r"(b1));
}

__device__ __forceinline__ void mma16b(float& c0, float& c1, float& c2, float& c3,
                                       uint32_t a0, uint32_t a1, uint32_t a2, uint32_t a3,
                                       uint32_t b0, uint32_t b1) {
    asm volatile("mma.sync.aligned.m16n8k16.row.col.f32.bf16.bf16.f32 "
                 "{%0,%1,%2,%3}, {%4,%5,%6,%7}, {%8,%9}, {%0,%1,%2,%3};"
                 : "+f"(c0), "+f"(c1), "+f"(c2), "+f"(c3)
                 : "r"(a0), "r"(a1), "r"(a2), "r"(a3), "r"(b0), "r"(b1));
}

__device__ __forceinline__ void ldm4(uint32_t& r0, uint32_t& r1, uint32_t& r2, uint32_t& r3,
                                     uint32_t saddr) {
    asm volatile("ldmatrix.sync.aligned.m8n8.x4.shared.b16 {%0,%1,%2,%3}, [%4];"
                 : "=r"(r0), "=r"(r1), "=r"(r2), "=r"(r3) : "r"(saddr));
}

extern __shared__ float smc[];

// ============================================================
// Kernel A: [f;g;h] = Wcat @ x via tf32 mma (proven R12/R14 version).
// grid (32 n-tiles of 128, 3 oc-tiles of 64, 8 b), 256 thr = 8 warps.
// ============================================================
#define WST 36
#define AXST 136
#define KA_WS 0
#define KA_XS (2 * 64 * WST)
#define SMEM_A_BYTES ((KA_XS + 2 * 32 * AXST) * 4)
#define LOG2E 1.4426950408889634f

__global__ __launch_bounds__(256, 3) void kA(const float* __restrict__ x,
                                             const float* __restrict__ Wf,
                                             const float* __restrict__ Wg,
                                             const float* __restrict__ Wh) {
    float* Ws = smc + KA_WS;   // 2 x [64][36]
    float* xs = smc + KA_XS;   // 2 x [32][136]
    const int b = blockIdx.z, ocb = blockIdx.y;
    const int n0 = blockIdx.x * 128;
    const int tid = threadIdx.x;
    const int w = tid >> 5, lane = tid & 31;
    const int r = lane >> 2, c = lane & 3;
    const int ms = (w & 3) * 16, nh = w >> 2;
    const float* xb = x + (size_t)b * CC * NPOS;

    float acc[8][4];
#pragma unroll
    for (int j = 0; j < 8; j++)
#pragma unroll
        for (int q = 0; q < 4; q++) acc[j][q] = 0.f;

    auto wrow = [&](int row) -> const float* {
        if (ocb == 0) return (row < 32) ? Wf + (size_t)row * 256 : Wg + (size_t)(row - 32) * 256;
        return Wh + (size_t)((ocb - 1) * 64 + row) * 256;
    };

#pragma unroll
    for (int p = 0; p < 2; p++) {
        int idx = tid + p * 256; int row = idx >> 3, cc = idx & 7;
        cpa16(&Ws[row * WST + cc * 4], wrow(row) + cc * 4);
    }
#pragma unroll
    for (int p = 0; p < 4; p++) {
        int idx = tid + p * 256; int kk = idx >> 5, cc = idx & 31;
        cpa16(&xs[kk * AXST + cc * 4], &xb[(size_t)kk * NPOS + n0 + cc * 4]);
    }
    cpcommit();
    cpwait0(); __syncthreads();

    for (int it = 0; it < 8; it++) {
        const int cur = it & 1;
        if (it + 1 < 8) {
            const int nxt = cur ^ 1, k0g = (it + 1) * 32;
            float* Wd = Ws + nxt * 64 * WST;
            float* xd = xs + nxt * 32 * AXST;
#pragma unroll
            for (int p = 0; p < 2; p++) {
                int idx = tid + p * 256; int row = idx >> 3, cc = idx & 7;
                cpa16(&Wd[row * WST + cc * 4], wrow(row) + k0g + cc * 4);
            }
#pragma unroll
            for (int p = 0; p < 4; p++) {
                int idx = tid + p * 256; int kk = idx >> 5, cc = idx & 31;
                cpa16(&xd[kk * AXST + cc * 4], &xb[(size_t)(k0g + kk) * NPOS + n0 + cc * 4]);
            }
        }
        cpcommit();

        const float* Wc = Ws + cur * 64 * WST;
        const float* xc = xs + cur * 32 * AXST;
#pragma unroll
        for (int ks = 0; ks < 4; ks++) {
            const int k0 = ks * 8;
            uint32_t a0 = __float_as_uint(Wc[(ms + r) * WST + k0 + c]);
            uint32_t a1 = __float_as_uint(Wc[(ms + r + 8) * WST + k0 + c]);
            uint32_t a2 = __float_as_uint(Wc[(ms + r) * WST + k0 + c + 4]);
            uint32_t a3 = __float_as_uint(Wc[(ms + r + 8) * WST + k0 + c + 4]);
#pragma unroll
            for (int j = 0; j < 8; j++) {
                const int nn = nh * 32 + (j & 3) * 8 + (j >> 2) * 64;
                uint32_t b0 = __float_as_uint(xc[(k0 + c) * AXST + nn + r]);
                uint32_t b1 = __float_as_uint(xc[(k0 + c + 4) * AXST + nn + r]);
                mma8(acc[j][0], acc[j][1], acc[j][2], acc[j][3], a0, a1, a2, a3, b0, b1);
            }
        }
        cpwait0(); __syncthreads();
    }

    // epilogue
    if (ocb == 0 && ms < 32) {
        float* fb = g_f + (size_t)b * CF * NPOS;
#pragma unroll
        for (int j = 0; j < 8; j++) {
            const int nn = nh * 32 + (j & 3) * 8 + (j >> 2) * 64;
            const int n = n0 + nn + 2 * c;
            *(float2*)&fb[(size_t)(ms + r) * NPOS + n] =
                make_float2(tf32r(acc[j][0] * LOG2E), tf32r(acc[j][1] * LOG2E));
            *(float2*)&fb[(size_t)(ms + r + 8) * NPOS + n] =
                make_float2(tf32r(acc[j][2] * LOG2E), tf32r(acc[j][3] * LOG2E));
        }
    } else {
        const int oc0 = ocb * 64 + ms + r;
#pragma unroll
        for (int j = 0; j < 4; j++) {
            float vlo = fmaxf(fmaxf(acc[j][0], acc[j][1]), fmaxf(acc[j + 4][0], acc[j + 4][1]));
            float vhi = fmaxf(fmaxf(acc[j][2], acc[j][3]), fmaxf(acc[j + 4][2], acc[j + 4][3]));
            const int pm = blockIdx.x * 32 + nh * 16 + j * 4 + c;
            if (ocb == 0) {
                float* dst = g_gp + ((size_t)b * CF + (oc0 - 32)) * MPOS;
                dst[pm] = tf32r(vlo);
                dst[8 * MPOS + pm] = tf32r(vhi);
            } else {
                __nv_bfloat16* dst = g_hp + ((size_t)b * CHD + (oc0 - 64)) * MPOS;
                dst[pm] = __float2bfloat16(vlo);
                dst[8 * MPOS + pm] = __float2bfloat16(vhi);
            }
        }
    }
}

// ============================================================
// Kernel C2: FA2 attention + fused kD. 512 threads, n-tile 256,
// grid (16 q-tiles, 8 b) = 128 blocks = 1 block/SM.
// warp w (0..15): n16 strip nq0 = w*16, full c128 + full m.
// ============================================================
#define CFST2 264
#define CGST 72
#define CHSTU 36
#define KC_FS 0
#define KC_GS (32 * CFST2)                 // 8448
#define KC_HS (KC_GS + 2 * 32 * CGST)      // 13056
#define KC_MAIN_FLOATS (KC_HS + 2 * 128 * CHSTU)   // 22272
#define KC_WB_U32 17408                     // os occupies u32 [0, 17408)
#define SMEM_C_FLOATS (KC_WB_U32 + 2 * 64 * 68)    // 26112
#define SMEM_C_BYTES (SMEM_C_FLOATS * 4)
#define OST2 68
#define WKST 68

__global__ __launch_bounds__(512, 1) void kC2(const float* __restrict__ x,
                                              const float* __restrict__ Wo,
                                              const float* __restrict__ gptr,
                                              float* __restrict__ out) {
    float* fs = smc + KC_FS;                    // [32][264] (only 256 cols loaded)
    float* gs = smc + KC_GS;                    // 2 x [32][72]
    uint32_t* hs = (uint32_t*)(smc + KC_HS);    // 2 x [128][36]
    uint32_t* os = (uint32_t*)smc;              // [256][68] bf16x2 (unions fs/gs/hs-buf0)
    uint32_t* Wb = (uint32_t*)smc + KC_WB_U32;  // 2 x [64][68] bf16x2 (unions hs-buf1 tail)

    const int b = blockIdx.y;
    const int n0 = blockIdx.x * 256;
    const int tid = threadIdx.x;
    const int w = tid >> 5, lane = tid & 31;
    const int r = lane >> 2, c = lane & 3;
    const int nq0 = w * 16;
    const float* gp = g_gp + (size_t)b * CF * MPOS;
    const __nv_bfloat16* hp = g_hp + (size_t)b * CHD * MPOS;
    const float* fp = g_f + (size_t)b * CF * NPOS + n0;

    // initial loads: fs (32x256), gs(t0), hs(t0)
#pragma unroll
    for (int p = 0; p < 4; p++) {
        int idx = tid + p * 512; int rr = idx >> 6, cc = idx & 63;
        cpa16(&fs[rr * CFST2 + cc * 4], &fp[(size_t)rr * NPOS + cc * 4]);
    }
    {
        int rr = tid >> 4, cc = tid & 15;
        cpa16(&gs[rr * CGST + cc * 4], &gp[(size_t)rr * MPOS + cc * 4]);
    }
#pragma unroll
    for (int p = 0; p < 2; p++) {
        int idx = tid + p * 512; int rr = idx >> 3, cc = idx & 7;
        cpa16(&hs[rr * CHSTU + cc * 4], &hp[(size_t)rr * MPOS + cc * 8]);
    }
    cpcommit(); cpwait0(); __syncthreads();

    const int i7 = lane & 7, s2 = (lane >> 3) & 1, s4 = lane >> 4;

    float rs0 = 0.f, rs1 = 0.f;
    {
        float acc[16][4];
#pragma unroll
        for (int i = 0; i < 16; i++)
#pragma unroll
            for (int q = 0; q < 4; q++) acc[i][q] = 0.f;

        for (int t = 0; t < 16; t++) {
            const int cur = t & 1;
            const float* gsc = gs + cur * 32 * CGST;
            const uint32_t* hsc = hs + cur * 128 * CHSTU;

            if (t + 1 < 16) {
                const int m1 = (t + 1) * 64;
                float* gsd = gs + (cur ^ 1) * 32 * CGST;
                uint32_t* hsd = hs + (cur ^ 1) * 128 * CHSTU;
                {
                    int rr = tid >> 4, cc = tid & 15;
                    cpa16(&gsd[rr * CGST + cc * 4], &gp[(size_t)rr * MPOS + m1 + cc * 4]);
                }
#pragma unroll
                for (int p = 0; p < 2; p++) {
                    int idx = tid + p * 512; int rr = idx >> 3, cc = idx & 7;
                    cpa16(&hsd[rr * CHSTU + cc * 4], &hp[(size_t)rr * MPOS + m1 + cc * 8]);
                }
            }
            cpcommit();

            // ---- score mma (tf32): S'[n16][m8] = (f*log2e)^T g ----
            uint32_t af[4][4];
#pragma unroll
            for (int half = 0; half < 2; half++) {
                float sc[4][4];
#pragma unroll
                for (int j2 = 0; j2 < 4; j2++)
#pragma unroll
                    for (int q = 0; q < 4; q++) sc[j2][q] = 0.f;
#pragma unroll
                for (int ks = 0; ks < 4; ks++) {
                    const int k0 = ks * 8;
                    uint32_t a0 = __float_as_uint(fs[(k0 + c) * CFST2 + nq0 + r]);
                    uint32_t a1 = __float_as_uint(fs[(k0 + c) * CFST2 + nq0 + r + 8]);
                    uint32_t a2 = __float_as_uint(fs[(k0 + c + 4) * CFST2 + nq0 + r]);
                    uint32_t a3 = __float_as_uint(fs[(k0 + c + 4) * CFST2 + nq0 + r + 8]);
#pragma unroll
                    for (int j2 = 0; j2 < 4; j2++) {
                        const int mof = half * 32 + j2 * 8;
                        uint32_t b0 = __float_as_uint(gsc[(k0 + c) * CGST + mof + r]);
                        uint32_t b1 = __float_as_uint(gsc[(k0 + c + 4) * CGST + mof + r]);
                        mma8(sc[j2][0], sc[j2][1], sc[j2][2], sc[j2][3],
                             a0, a1, a2, a3, b0, b1);
                    }
                }
#pragma unroll
                for (int mo2 = 0; mo2 < 2; mo2++) {
                    float e00 = ex2f(sc[2 * mo2][0]),     e01 = ex2f(sc[2 * mo2][1]);
                    float e02 = ex2f(sc[2 * mo2][2]),     e03 = ex2f(sc[2 * mo2][3]);
                    float e10 = ex2f(sc[2 * mo2 + 1][0]), e11 = ex2f(sc[2 * mo2 + 1][1]);
                    float e12 = ex2f(sc[2 * mo2 + 1][2]), e13 = ex2f(sc[2 * mo2 + 1][3]);
                    __nv_bfloat162 p0 = __floats2bfloat162_rn(e00, e01);
                    __nv_bfloat162 p1 = __floats2bfloat162_rn(e02, e03);
                    __nv_bfloat162 p2 = __floats2bfloat162_rn(e10, e11);
                    __nv_bfloat162 p3 = __floats2bfloat162_rn(e12, e13);
                    const int mo = half * 2 + mo2;
                    af[mo][0] = *(uint32_t*)&p0;
                    af[mo][1] = *(uint32_t*)&p1;
                    af[mo][2] = *(uint32_t*)&p2;
                    af[mo][3] = *(uint32_t*)&p3;
                    rs0 += (e00 + e01) + (e10 + e11);
                    rs1 += (e02 + e03) + (e12 + e13);
                }
            }

            // ---- o-mma (bf16 k16): o^T[n16][c128] += P * h ----
            {
                const uint32_t hs_sb = (uint32_t)__cvta_generic_to_shared(hsc);
#pragma unroll
                for (int mo = 0; mo < 4; mo++) {
#pragma unroll
                    for (int cg = 0; cg < 8; cg++) {
                        uint32_t b0, b1, b2, b3;
                        ldm4(b0, b1, b2, b3,
                             hs_sb + (uint32_t)(((cg * 16 + s4 * 8 + i7) * CHSTU + s2 * 4 + mo * 8) * 4));
                        mma16b(acc[2 * cg][0], acc[2 * cg][1], acc[2 * cg][2], acc[2 * cg][3],
                               af[mo][0], af[mo][1], af[mo][2], af[mo][3], b0, b1);
                        mma16b(acc[2 * cg + 1][0], acc[2 * cg + 1][1], acc[2 * cg + 1][2], acc[2 * cg + 1][3],
                               af[mo][0], af[mo][1], af[mo][2], af[mo][3], b2, b3);
                    }
                }
            }
            cpwait0();
            __syncthreads();
        }

        // ---- rowsum: warp-local xor reduce over the 4 c-lanes ----
#pragma unroll
        for (int off = 1; off < 4; off <<= 1) {
            rs0 += __shfl_xor_sync(0xffffffffu, rs0, off);
            rs1 += __shfl_xor_sync(0xffffffffu, rs1, off);
        }
        const float inv0 = 1.f / rs0, inv1 = 1.f / rs1;

        // ---- normalize + store o^T bf16 [n][c] into SMEM (os) ----
#pragma unroll
        for (int tt = 0; tt < 16; tt++) {
            __nv_bfloat162 v0 = __floats2bfloat162_rn(acc[tt][0] * inv0, acc[tt][1] * inv0);
            __nv_bfloat162 v1 = __floats2bfloat162_rn(acc[tt][2] * inv1, acc[tt][3] * inv1);
            os[(nq0 + r) * OST2 + tt * 4 + c]     = *(uint32_t*)&v0;
            os[(nq0 + r + 8) * OST2 + tt * 4 + c] = *(uint32_t*)&v1;
        }
    }

    // ================= fused kD phase (Wb double-buffered) =================
    const float gamma = *gptr;
    const int ms = (w & 3) * 16, nh = w >> 2;   // nh 0..3: n-quarter of 256
    const uint32_t o_sb = (uint32_t)__cvta_generic_to_shared(os);
    const uint32_t wb_sb = (uint32_t)__cvta_generic_to_shared(Wb);
    const uint32_t a_off = (uint32_t)((ms + s2 * 8 + i7) * WKST + s4 * 4);
    const uint32_t b_off = (uint32_t)((nh * 64 + s4 * 8 + i7) * OST2 + s2 * 4);
    const float* xb = x + (size_t)b * CC * NPOS;
    float* outb = out + (size_t)b * CC * NPOS;

    // convert Wo slice for pass 0 into Wb[0]
#pragma unroll
    for (int p = 0; p < 4; p++) {
        int idx = tid + p * 512; int row = idx >> 5, cc = idx & 31;
        float4 v = *(const float4*)&Wo[(size_t)row * CHD + cc * 4];
        __nv_bfloat162 lo = __floats2bfloat162_rn(v.x, v.y);
        __nv_bfloat162 hi = __floats2bfloat162_rn(v.z, v.w);
        Wb[row * WKST + cc * 2]     = *(uint32_t*)&lo;
        Wb[row * WKST + cc * 2 + 1] = *(uint32_t*)&hi;
    }
    __syncthreads();   // os + Wb[0] visible

    for (int pass = 0; pass < 4; pass++) {
        const uint32_t w_sb = wb_sb + (uint32_t)((pass & 1) * 64 * WKST * 4);
        float acc[8][4];
#pragma unroll
        for (int j = 0; j < 8; j++)
#pragma unroll
            for (int q = 0; q < 4; q++) acc[j][q] = 0.f;

#pragma unroll
        for (int s = 0; s < 8; s++) {
            uint32_t a0, a1, a2, a3;
            ldm4(a0, a1, a2, a3, w_sb + (a_off + s * 8) * 4);
#pragma unroll
            for (int jp = 0; jp < 4; jp++) {
                uint32_t b0, b1, b2, b3;
                ldm4(b0, b1, b2, b3, o_sb + (b_off + jp * 16 * OST2 + s * 8) * 4);
                mma16b(acc[2 * jp][0], acc[2 * jp][1], acc[2 * jp][2], acc[2 * jp][3],
                       a0, a1, a2, a3, b0, b1);
                mma16b(acc[2 * jp + 1][0], acc[2 * jp + 1][1], acc[2 * jp + 1][2], acc[2 * jp + 1][3],
                       a0, a1, a2, a3, b2, b3);
            }
        }

        // convert next pass's Wo slice into the alternate buffer
        if (pass < 3) {
            uint32_t* Wn = Wb + ((pass + 1) & 1) * 64 * WKST;
#pragma unroll
            for (int p = 0; p < 4; p++) {
                int idx = tid + p * 512; int row = idx >> 5, cc = idx & 31;
                float4 v = *(const float4*)&Wo[(size_t)((pass + 1) * 64 + row) * CHD + cc * 4];
                __nv_bfloat162 lo = __floats2bfloat162_rn(v.x, v.y);
                __nv_bfloat162 hi = __floats2bfloat162_rn(v.z, v.w);
                Wn[row * WKST + cc * 2]     = *(uint32_t*)&lo;
                Wn[row * WKST + cc * 2 + 1] = *(uint32_t*)&hi;
            }
        }

        // epilogue: out = gamma * acc + x
        const int oc0 = pass * 64 + ms + r;
#pragma unroll
        for (int j = 0; j < 8; j++) {
            const int n = n0 + nh * 64 + j * 8 + 2 * c;
            size_t p0 = (size_t)oc0 * NPOS + n;
            size_t p1 = (size_t)(oc0 + 8) * NPOS + n;
            float2 x0 = *(const float2*)&xb[p0];
            float2 x1 = *(const float2*)&xb[p1];
            *(float2*)&outb[p0] = make_float2(fmaf(gamma, acc[j][0], x0.x),
                                              fmaf(gamma, acc[j][1], x0.y));
            *(float2*)&outb[p1] = make_float2(fmaf(gamma, acc[j][2], x1.x),
                                              fmaf(gamma, acc[j][3], x1.y));
        }

        if (pass < 3) __syncthreads();   // Wb[next] visible; this pass's reads done
    }
}

// ============================================================
extern "C" void kernel_launch(void* const* d_in, const int* in_sizes, int n_in,
                              void* d_out, int out_size) {
    const float* x     = (const float*)d_in[0];
    const float* Wf    = (const float*)d_in[1];
    const float* Wg    = (const float*)d_in[2];
    const float* Wh    = (const float*)d_in[3];
    const float* Wo    = (const float*)d_in[4];
    const float* gamma = (const float*)d_in[5];
    float* out = (float*)d_out;

    cudaFuncSetAttribute(kA, cudaFuncAttributeMaxDynamicSharedMemorySize, SMEM_A_BYTES);
    cudaFuncSetAttribute(kC2, cudaFuncAttributeMaxDynamicSharedMemorySize, SMEM_C_BYTES);

    kA<<<dim3(32, 3, 8), 256, SMEM_A_BYTES>>>(x, Wf, Wg, Wh);
    kC2<<<dim3(16, 8), 512, SMEM_C_BYTES>>>(x, Wo, gamma, out);
}

// round 16
// speedup vs baseline: 5.7670x; 1.0133x over previous
#include <cuda_runtime.h>
#include <cuda_bf16.h>
#include <cstdint>

#define BB 8
#define CC 256
#define NPOS 4096   // 64*64
#define MPOS 1024   // 32*32
#define CF 32       // C/8
#define CHD 128     // C/2

// ---- scratch (static device globals; no allocation) ----
__device__ float g_f[(size_t)BB * CF * NPOS];                      // f*log2e (tf32-rounded fp32)
__device__ float g_gp[(size_t)BB * CF * MPOS];                     // pooled g (tf32-rounded fp32)
__device__ __align__(16) __nv_bfloat16 g_hp[(size_t)BB * CHD * MPOS];   // pooled h (bf16)

// ---- helpers ----
__device__ __forceinline__ void cpa16(void* s, const void* g) {
    unsigned sa = (unsigned)__cvta_generic_to_shared(s);
    asm volatile("cp.async.ca.shared.global [%0], [%1], 16;\n" :: "r"(sa), "l"(g));
}
__device__ __forceinline__ void cpcommit() { asm volatile("cp.async.commit_group;\n" ::); }
__device__ __forceinline__ void cpwait0()  { asm volatile("cp.async.wait_group 0;\n" ::); }

__device__ __forceinline__ float tf32r(float x) {
    uint32_t u;
    asm("cvt.rna.tf32.f32 %0, %1;" : "=r"(u) : "f"(x));
    return __uint_as_float(u);
}
__device__ __forceinline__ float ex2f(float x) {
    float y;
    asm("ex2.approx.f32 %0, %1;" : "=f"(y) : "f"(x));
    return y;
}

__device__ __forceinline__ void mma8(float& c0, float& c1, float& c2, float& c3,
                                     uint32_t a0, uint32_t a1, uint32_t a2, uint32_t a3,
                                     uint32_t b0, uint32_t b1) {
    asm volatile("mma.sync.aligned.m16n8k8.row.col.f32.tf32.tf32.f32 "
                 "{%0,%1,%2,%3}, {%4,%5,%6,%7}, {%8,%9}, {%0,%1,%2,%3};"
                 : "+f"(c0), "+f"(c1), "+f"(c2), "+f"(c3)
                 : "r"(a0), "r"(a1), "r"(a2), "r"(a3), "r"(b0), "r"(b1));
}

__device__ __forceinline__ void mma16b(float& c0, float& c1, float& c2, float& c3,
                                       uint32_t a0, uint32_t a1, uint32_t a2, uint32_t a3,
                                       uint32_t b0, uint32_t b1) {
    asm volatile("mma.sync.aligned.m16n8k16.row.col.f32.bf16.bf16.f32 "
                 "{%0,%1,%2,%3}, {%4,%5,%6,%7}, {%8,%9}, {%0,%1,%2,%3};"
                 : "+f"(c0), "+f"(c1), "+f"(c2), "+f"(c3)
                 : "r"(a0), "r"(a1), "r"(a2), "r"(a3), "r"(b0), "r"(b1));
}

__device__ __forceinline__ void ldm4(uint32_t& r0, uint32_t& r1, uint32_t& r2, uint32_t& r3,
                                     uint32_t saddr) {
    asm volatile("ldmatrix.sync.aligned.m8n8.x4.shared.b16 {%0,%1,%2,%3}, [%4];"
                 : "=r"(r0), "=r"(r1), "=r"(r2), "=r"(r3) : "r"(saddr));
}

extern __shared__ float smc[];

// ============================================================
// Kernel A: [f;g;h] = Wcat @ x via tf32 mma (proven, unchanged).
// grid (32 n-tiles of 128, 3 oc-tiles of 64, 8 b), 256 thr = 8 warps.
// ============================================================
#define WST 36
#define AXST 136
#define KA_WS 0
#define KA_XS (2 * 64 * WST)
#define SMEM_A_BYTES ((KA_XS + 2 * 32 * AXST) * 4)
#define LOG2E 1.4426950408889634f

__global__ __launch_bounds__(256, 3) void kA(const float* __restrict__ x,
                                             const float* __restrict__ Wf,
                                             const float* __restrict__ Wg,
                                             const float* __restrict__ Wh) {
    float* Ws = smc + KA_WS;   // 2 x [64][36]
    float* xs = smc + KA_XS;   // 2 x [32][136]
    const int b = blockIdx.z, ocb = blockIdx.y;
    const int n0 = blockIdx.x * 128;
    const int tid = threadIdx.x;
    const int w = tid >> 5, lane = tid & 31;
    const int r = lane >> 2, c = lane & 3;
    const int ms = (w & 3) * 16, nh = w >> 2;
    const float* xb = x + (size_t)b * CC * NPOS;

    float acc[8][4];
#pragma unroll
    for (int j = 0; j < 8; j++)
#pragma unroll
        for (int q = 0; q < 4; q++) acc[j][q] = 0.f;

    auto wrow = [&](int row) -> const float* {
        if (ocb == 0) return (row < 32) ? Wf + (size_t)row * 256 : Wg + (size_t)(row - 32) * 256;
        return Wh + (size_t)((ocb - 1) * 64 + row) * 256;
    };

#pragma unroll
    for (int p = 0; p < 2; p++) {
        int idx = tid + p * 256; int row = idx >> 3, cc = idx & 7;
        cpa16(&Ws[row * WST + cc * 4], wrow(row) + cc * 4);
    }
#pragma unroll
    for (int p = 0; p < 4; p++) {
        int idx = tid + p * 256; int kk = idx >> 5, cc = idx & 31;
        cpa16(&xs[kk * AXST + cc * 4], &xb[(size_t)kk * NPOS + n0 + cc * 4]);
    }
    cpcommit();
    cpwait0(); __syncthreads();

    for (int it = 0; it < 8; it++) {
        const int cur = it & 1;
        if (it + 1 < 8) {
            const int nxt = cur ^ 1, k0g = (it + 1) * 32;
            float* Wd = Ws + nxt * 64 * WST;
            float* xd = xs + nxt * 32 * AXST;
#pragma unroll
            for (int p = 0; p < 2; p++) {
                int idx = tid + p * 256; int row = idx >> 3, cc = idx & 7;
                cpa16(&Wd[row * WST + cc * 4], wrow(row) + k0g + cc * 4);
            }
#pragma unroll
            for (int p = 0; p < 4; p++) {
                int idx = tid + p * 256; int kk = idx >> 5, cc = idx & 31;
                cpa16(&xd[kk * AXST + cc * 4], &xb[(size_t)(k0g + kk) * NPOS + n0 + cc * 4]);
            }
        }
        cpcommit();

        const float* Wc = Ws + cur * 64 * WST;
        const float* xc = xs + cur * 32 * AXST;
#pragma unroll
        for (int ks = 0; ks < 4; ks++) {
            const int k0 = ks * 8;
            uint32_t a0 = __float_as_uint(Wc[(ms + r) * WST + k0 + c]);
            uint32_t a1 = __float_as_uint(Wc[(ms + r + 8) * WST + k0 + c]);
            uint32_t a2 = __float_as_uint(Wc[(ms + r) * WST + k0 + c + 4]);
            uint32_t a3 = __float_as_uint(Wc[(ms + r + 8) * WST + k0 + c + 4]);
#pragma unroll
            for (int j = 0; j < 8; j++) {
                const int nn = nh * 32 + (j & 3) * 8 + (j >> 2) * 64;
                uint32_t b0 = __float_as_uint(xc[(k0 + c) * AXST + nn + r]);
                uint32_t b1 = __float_as_uint(xc[(k0 + c + 4) * AXST + nn + r]);
                mma8(acc[j][0], acc[j][1], acc[j][2], acc[j][3], a0, a1, a2, a3, b0, b1);
            }
        }
        cpwait0(); __syncthreads();
    }

    // epilogue
    if (ocb == 0 && ms < 32) {
        float* fb = g_f + (size_t)b * CF * NPOS;
#pragma unroll
        for (int j = 0; j < 8; j++) {
            const int nn = nh * 32 + (j & 3) * 8 + (j >> 2) * 64;
            const int n = n0 + nn + 2 * c;
            *(float2*)&fb[(size_t)(ms + r) * NPOS + n] =
                make_float2(tf32r(acc[j][0] * LOG2E), tf32r(acc[j][1] * LOG2E));
            *(float2*)&fb[(size_t)(ms + r + 8) * NPOS + n] =
                make_float2(tf32r(acc[j][2] * LOG2E), tf32r(acc[j][3] * LOG2E));
        }
    } else {
        const int oc0 = ocb * 64 + ms + r;
#pragma unroll
        for (int j = 0; j < 4; j++) {
            float vlo = fmaxf(fmaxf(acc[j][0], acc[j][1]), fmaxf(acc[j + 4][0], acc[j + 4][1]));
            float vhi = fmaxf(fmaxf(acc[j][2], acc[j][3]), fmaxf(acc[j + 4][2], acc[j + 4][3]));
            const int pm = blockIdx.x * 32 + nh * 16 + j * 4 + c;
            if (ocb == 0) {
                float* dst = g_gp + ((size_t)b * CF + (oc0 - 32)) * MPOS;
                dst[pm] = tf32r(vlo);
                dst[8 * MPOS + pm] = tf32r(vhi);
            } else {
                __nv_bfloat16* dst = g_hp + ((size_t)b * CHD + (oc0 - 64)) * MPOS;
                dst[pm] = __float2bfloat16(vlo);
                dst[8 * MPOS + pm] = __float2bfloat16(vhi);
            }
        }
    }
}

// ============================================================
// Kernel C2: FA2 attention + fused kD. 512 threads, n-tile 256,
// grid (16,8) = 128 blocks = 1/SM. NEW: 6-slot g/h smem ring,
// 3-tile batches -> 1 barrier + 1 cp-wait per 3 tiles.
// ============================================================
#define CFST2 264
#define CGST 72
#define CHSTU 36
#define KC_FS 0
#define KC_GS (32 * CFST2)                  // 8448
#define KC_HS (KC_GS + 6 * 32 * CGST)       // 8448 + 13824 = 22272
#define SMEM_C_FLOATS (KC_HS + 6 * 128 * CHSTU)   // 22272 + 27648 = 49920
#define SMEM_C_BYTES (SMEM_C_FLOATS * 4)
#define KC_WB_U32 KC_HS    // Wb overlays hs region (dead in kD phase)
#define OST2 68
#define WKST 68

__global__ __launch_bounds__(512, 1) void kC2(const float* __restrict__ x,
                                              const float* __restrict__ Wo,
                                              const float* __restrict__ gptr,
                                              float* __restrict__ out) {
    float* fs = smc + KC_FS;                    // [32][264] (256 cols used)
    float* gs = smc + KC_GS;                    // 6 x [32][72]
    uint32_t* hs = (uint32_t*)(smc + KC_HS);    // 6 x [128][36]
    uint32_t* os = (uint32_t*)smc;              // [256][68] bf16x2 (unions fs+gs: 17408 < 22272)
    uint32_t* Wb = (uint32_t*)smc + KC_WB_U32;  // 2 x [64][68] bf16x2 (unions hs)

    const int b = blockIdx.y;
    const int n0 = blockIdx.x * 256;
    const int tid = threadIdx.x;
    const int w = tid >> 5, lane = tid & 31;
    const int r = lane >> 2, c = lane & 3;
    const int nq0 = w * 16;
    const float* gp = g_gp + (size_t)b * CF * MPOS;
    const __nv_bfloat16* hp = g_hp + (size_t)b * CHD * MPOS;
    const float* fp = g_f + (size_t)b * CF * NPOS + n0;

    // load-issue lambdas (per tile t into ring slot t%6)
    auto issue_tile = [&](int t) {
        const int slot = t % 6;
        const int m0 = t * 64;
        float* gsd = gs + slot * 32 * CGST;
        uint32_t* hsd = hs + slot * 128 * CHSTU;
        {
            int rr = tid >> 4, cc = tid & 15;
            cpa16(&gsd[rr * CGST + cc * 4], &gp[(size_t)rr * MPOS + m0 + cc * 4]);
        }
#pragma unroll
        for (int p = 0; p < 2; p++) {
            int idx = tid + p * 512; int rr = idx >> 3, cc = idx & 7;
            cpa16(&hsd[rr * CHSTU + cc * 4], &hp[(size_t)rr * MPOS + m0 + cc * 8]);
        }
    };

    // prologue: fs (32x256) + batch 0 (tiles 0..2)
#pragma unroll
    for (int p = 0; p < 4; p++) {
        int idx = tid + p * 512; int rr = idx >> 6, cc = idx & 63;
        cpa16(&fs[rr * CFST2 + cc * 4], &fp[(size_t)rr * NPOS + cc * 4]);
    }
    issue_tile(0); issue_tile(1); issue_tile(2);
    cpcommit(); cpwait0(); __syncthreads();

    const int i7 = lane & 7, s2 = (lane >> 3) & 1, s4 = lane >> 4;

    float rs0 = 0.f, rs1 = 0.f;
    {
        float acc[16][4];
#pragma unroll
        for (int i = 0; i < 16; i++)
#pragma unroll
            for (int q = 0; q < 4; q++) acc[i][q] = 0.f;

        for (int t0 = 0; t0 < 16; t0 += 3) {
            // issue next batch (tiles t0+3 .. t0+5, capped at 16)
#pragma unroll
            for (int i = 3; i < 6; i++)
                if (t0 + i < 16) issue_tile(t0 + i);
            cpcommit();

            // consume tiles t0 .. t0+2 (no waits/syncs between them)
#pragma unroll
            for (int ti = 0; ti < 3; ti++) {
                const int t = t0 + ti;
                if (t >= 16) break;
                const int slot = t % 6;
                const float* gsc = gs + slot * 32 * CGST;
                const uint32_t* hsc = hs + slot * 128 * CHSTU;

                // ---- score mma (tf32): S'[n16][m8] = (f*log2e)^T g ----
                uint32_t af[4][4];
#pragma unroll
                for (int half = 0; half < 2; half++) {
                    float sc[4][4];
#pragma unroll
                    for (int j2 = 0; j2 < 4; j2++)
#pragma unroll
                        for (int q = 0; q < 4; q++) sc[j2][q] = 0.f;
#pragma unroll
                    for (int ks = 0; ks < 4; ks++) {
                        const int k0 = ks * 8;
                        uint32_t a0 = __float_as_uint(fs[(k0 + c) * CFST2 + nq0 + r]);
                        uint32_t a1 = __float_as_uint(fs[(k0 + c) * CFST2 + nq0 + r + 8]);
                        uint32_t a2 = __float_as_uint(fs[(k0 + c + 4) * CFST2 + nq0 + r]);
                        uint32_t a3 = __float_as_uint(fs[(k0 + c + 4) * CFST2 + nq0 + r + 8]);
#pragma unroll
                        for (int j2 = 0; j2 < 4; j2++) {
                            const int mof = half * 32 + j2 * 8;
                            uint32_t b0 = __float_as_uint(gsc[(k0 + c) * CGST + mof + r]);
                            uint32_t b1 = __float_as_uint(gsc[(k0 + c + 4) * CGST + mof + r]);
                            mma8(sc[j2][0], sc[j2][1], sc[j2][2], sc[j2][3],
                                 a0, a1, a2, a3, b0, b1);
                        }
                    }
#pragma unroll
                    for (int mo2 = 0; mo2 < 2; mo2++) {
                        float e00 = ex2f(sc[2 * mo2][0]),     e01 = ex2f(sc[2 * mo2][1]);
                        float e02 = ex2f(sc[2 * mo2][2]),     e03 = ex2f(sc[2 * mo2][3]);
                        float e10 = ex2f(sc[2 * mo2 + 1][0]), e11 = ex2f(sc[2 * mo2 + 1][1]);
                        float e12 = ex2f(sc[2 * mo2 + 1][2]), e13 = ex2f(sc[2 * mo2 + 1][3]);
                        __nv_bfloat162 p0 = __floats2bfloat162_rn(e00, e01);
                        __nv_bfloat162 p1 = __floats2bfloat162_rn(e02, e03);
                        __nv_bfloat162 p2 = __floats2bfloat162_rn(e10, e11);
                        __nv_bfloat162 p3 = __floats2bfloat162_rn(e12, e13);
                        const int mo = half * 2 + mo2;
                        af[mo][0] = *(uint32_t*)&p0;
                        af[mo][1] = *(uint32_t*)&p1;
                        af[mo][2] = *(uint32_t*)&p2;
                        af[mo][3] = *(uint32_t*)&p3;
                        rs0 += (e00 + e01) + (e10 + e11);
                        rs1 += (e02 + e03) + (e12 + e13);
                    }
                }

                // ---- o-mma (bf16 k16): o^T[n16][c128] += P * h ----
                {
                    const uint32_t hs_sb = (uint32_t)__cvta_generic_to_shared(hsc);
#pragma unroll
                    for (int mo = 0; mo < 4; mo++) {
#pragma unroll
                        for (int cg = 0; cg < 8; cg++) {
                            uint32_t b0, b1, b2, b3;
                            ldm4(b0, b1, b2, b3,
                                 hs_sb + (uint32_t)(((cg * 16 + s4 * 8 + i7) * CHSTU + s2 * 4 + mo * 8) * 4));
                            mma16b(acc[2 * cg][0], acc[2 * cg][1], acc[2 * cg][2], acc[2 * cg][3],
                                   af[mo][0], af[mo][1], af[mo][2], af[mo][3], b0, b1);
                            mma16b(acc[2 * cg + 1][0], acc[2 * cg + 1][1], acc[2 * cg + 1][2], acc[2 * cg + 1][3],
                                   af[mo][0], af[mo][1], af[mo][2], af[mo][3], b2, b3);
                        }
                    }
                }
            }
            cpwait0();
            __syncthreads();   // next batch resident; this batch's slots reusable
        }

        // ---- rowsum: warp-local xor reduce over the 4 c-lanes ----
#pragma unroll
        for (int off = 1; off < 4; off <<= 1) {
            rs0 += __shfl_xor_sync(0xffffffffu, rs0, off);
            rs1 += __shfl_xor_sync(0xffffffffu, rs1, off);
        }
        const float inv0 = 1.f / rs0, inv1 = 1.f / rs1;

        // ---- normalize + store o^T bf16 [n][c] into SMEM (os) ----
#pragma unroll
        for (int tt = 0; tt < 16; tt++) {
            __nv_bfloat162 v0 = __floats2bfloat162_rn(acc[tt][0] * inv0, acc[tt][1] * inv0);
            __nv_bfloat162 v1 = __floats2bfloat162_rn(acc[tt][2] * inv1, acc[tt][3] * inv1);
            os[(nq0 + r) * OST2 + tt * 4 + c]     = *(uint32_t*)&v0;
            os[(nq0 + r + 8) * OST2 + tt * 4 + c] = *(uint32_t*)&v1;
        }
    }

    // ================= fused kD phase (Wb double-buffered) =================
    const float gamma = *gptr;
    const int ms = (w & 3) * 16, nh = w >> 2;   // nh 0..3: n-quarter of 256
    const uint32_t o_sb = (uint32_t)__cvta_generic_to_shared(os);
    const uint32_t wb_sb = (uint32_t)__cvta_generic_to_shared(Wb);
    const uint32_t a_off = (uint32_t)((ms + s2 * 8 + i7) * WKST + s4 * 4);
    const uint32_t b_off = (uint32_t)((nh * 64 + s4 * 8 + i7) * OST2 + s2 * 4);
    const float* xb = x + (size_t)b * CC * NPOS;
    float* outb = out + (size_t)b * CC * NPOS;

    // convert Wo slice for pass 0 into Wb[0]
#pragma unroll
    for (int p = 0; p < 4; p++) {
        int idx = tid + p * 512; int row = idx >> 5, cc = idx & 31;
        float4 v = *(const float4*)&Wo[(size_t)row * CHD + cc * 4];
        __nv_bfloat162 lo = __floats2bfloat162_rn(v.x, v.y);
        __nv_bfloat162 hi = __floats2bfloat162_rn(v.z, v.w);
        Wb[row * WKST + cc * 2]     = *(uint32_t*)&lo;
        Wb[row * WKST + cc * 2 + 1] = *(uint32_t*)&hi;
    }
    __syncthreads();   // os + Wb[0] visible

    for (int pass = 0; pass < 4; pass++) {
        const uint32_t w_sb = wb_sb + (uint32_t)((pass & 1) * 64 * WKST * 4);
        float acc[8][4];
#pragma unroll
        for (int j = 0; j < 8; j++)
#pragma unroll
            for (int q = 0; q < 4; q++) acc[j][q] = 0.f;

#pragma unroll
        for (int s = 0; s < 8; s++) {
            uint32_t a0, a1, a2, a3;
            ldm4(a0, a1, a2, a3, w_sb + (a_off + s * 8) * 4);
#pragma unroll
            for (int jp = 0; jp < 4; jp++) {
                uint32_t b0, b1, b2, b3;
                ldm4(b0, b1, b2, b3, o_sb + (b_off + jp * 16 * OST2 + s * 8) * 4);
                mma16b(acc[2 * jp][0], acc[2 * jp][1], acc[2 * jp][2], acc[2 * jp][3],
                       a0, a1, a2, a3, b0, b1);
                mma16b(acc[2 * jp + 1][0], acc[2 * jp + 1][1], acc[2 * jp + 1][2], acc[2 * jp + 1][3],
                       a0, a1, a2, a3, b2, b3);
            }
        }

        // convert next pass's Wo slice into the alternate buffer
        if (pass < 3) {
            uint32_t* Wn = Wb + ((pass + 1) & 1) * 64 * WKST;
#pragma unroll
            for (int p = 0; p < 4; p++) {
                int idx = tid + p * 512; int row = idx >> 5, cc = idx & 31;
                float4 v = *(const float4*)&Wo[(size_t)((pass + 1) * 64 + row) * CHD + cc * 4];
                __nv_bfloat162 lo = __floats2bfloat162_rn(v.x, v.y);
                __nv_bfloat162 hi = __floats2bfloat162_rn(v.z, v.w);
                Wn[row * WKST + cc * 2]     = *(uint32_t*)&lo;
                Wn[row * WKST + cc * 2 + 1] = *(uint32_t*)&hi;
            }
        }

        // epilogue: out = gamma * acc + x
        const int oc0 = pass * 64 + ms + r;
#pragma unroll
        for (int j = 0; j < 8; j++) {
            const int n = n0 + nh * 64 + j * 8 + 2 * c;
            size_t p0 = (size_t)oc0 * NPOS + n;
            size_t p1 = (size_t)(oc0 + 8) * NPOS + n;
            float2 x0 = *(const float2*)&xb[p0];
            float2 x1 = *(const float2*)&xb[p1];
            *(float2*)&outb[p0] = make_float2(fmaf(gamma, acc[j][0], x0.x),
                                              fmaf(gamma, acc[j][1], x0.y));
            *(float2*)&outb[p1] = make_float2(fmaf(gamma, acc[j][2], x1.x),
                                              fmaf(gamma, acc[j][3], x1.y));
        }

        if (pass < 3) __syncthreads();
    }
}

// ============================================================
extern "C" void kernel_launch(void* const* d_in, const int* in_sizes, int n_in,
                              void* d_out, int out_size) {
    const float* x     = (const float*)d_in[0];
    const float* Wf    = (const float*)d_in[1];
    const float* Wg    = (const float*)d_in[2];
    const float* Wh    = (const float*)d_in[3];
    const float* Wo    = (const float*)d_in[4];
    const float* gamma = (const float*)d_in[5];
    float* out = (float*)d_out;

    cudaFuncSetAttribute(kA, cudaFuncAttributeMaxDynamicSharedMemorySize, SMEM_A_BYTES);
    cudaFuncSetAttribute(kC2, cudaFuncAttributeMaxDynamicSharedMemorySize, SMEM_C_BYTES);

    kA<<<dim3(32, 3, 8), 256, SMEM_A_BYTES>>>(x, Wf, Wg, Wh);
    kC2<<<dim3(16, 8), 512, SMEM_C_BYTES>>>(x, Wo, gamma, out);
}

// round 17
// speedup vs baseline: 6.1558x; 1.0674x over previous
#include <cuda_runtime.h>
#include <cuda_bf16.h>
#include <cuda_fp16.h>
#include <cstdint>

#define BB 8
#define CC 256
#define NPOS 4096   // 64*64
#define MPOS 1024   // 32*32
#define CF 32       // C/8
#define CHD 128     // C/2

// ---- scratch (static device globals; no allocation) ----
__device__ __align__(16) __half g_f16[(size_t)BB * NPOS * 32];   // f*log2e, [b][n][k] fp16
__device__ __align__(16) __half g_g16[(size_t)BB * MPOS * 32];   // pooled g, [b][m][k] fp16
__device__ __align__(16) __nv_bfloat16 g_hp[(size_t)BB * CHD * MPOS];   // pooled h (bf16)

// ---- helpers ----
__device__ __forceinline__ void cpa16(void* s, const void* g) {
    unsigned sa = (unsigned)__cvta_generic_to_shared(s);
    asm volatile("cp.async.ca.shared.global [%0], [%1], 16;\n" :: "r"(sa), "l"(g));
}
__device__ __forceinline__ void cpcommit() { asm volatile("cp.async.commit_group;\n" ::); }
__device__ __forceinline__ void cpwait0()  { asm volatile("cp.async.wait_group 0;\n" ::); }

__device__ __forceinline__ float ex2f(float x) {
    float y;
    asm("ex2.approx.f32 %0, %1;" : "=f"(y) : "f"(x));
    return y;
}

__device__ __forceinline__ void mma8(float& c0, float& c1, float& c2, float& c3,
                                     uint32_t a0, uint32_t a1, uint32_t a2, uint32_t a3,
                                     uint32_t b0, uint32_t b1) {
    asm volatile("mma.sync.aligned.m16n8k8.row.col.f32.tf32.tf32.f32 "
                 "{%0,%1,%2,%3}, {%4,%5,%6,%7}, {%8,%9}, {%0,%1,%2,%3};"
                 : "+f"(c0), "+f"(c1), "+f"(c2), "+f"(c3)
                 : "r"(a0), "r"(a1), "r"(a2), "r"(a3), "r"(b0), "r"(b1));
}

__device__ __forceinline__ void mma16b(float& c0, float& c1, float& c2, float& c3,
                                       uint32_t a0, uint32_t a1, uint32_t a2, uint32_t a3,
                                       uint32_t b0, uint32_t b1) {
    asm volatile("mma.sync.aligned.m16n8k16.row.col.f32.bf16.bf16.f32 "
                 "{%0,%1,%2,%3}, {%4,%5,%6,%7}, {%8,%9}, {%0,%1,%2,%3};"
                 : "+f"(c0), "+f"(c1), "+f"(c2), "+f"(c3)
                 : "r"(a0), "r"(a1), "r"(a2), "r"(a3), "r"(b0), "r"(b1));
}

__device__ __forceinline__ void mma16f(float& c0, float& c1, float& c2, float& c3,
                                       uint32_t a0, uint32_t a1, uint32_t a2, uint32_t a3,
                                       uint32_t b0, uint32_t b1) {
    asm volatile("mma.sync.aligned.m16n8k16.row.col.f32.f16.f16.f32 "
                 "{%0,%1,%2,%3}, {%4,%5,%6,%7}, {%8,%9}, {%0,%1,%2,%3};"
                 : "+f"(c0), "+f"(c1), "+f"(c2), "+f"(c3)
                 : "r"(a0), "r"(a1), "r"(a2), "r"(a3), "r"(b0), "r"(b1));
}

__device__ __forceinline__ void ldm4(uint32_t& r0, uint32_t& r1, uint32_t& r2, uint32_t& r3,
                                     uint32_t saddr) {
    asm volatile("ldmatrix.sync.aligned.m8n8.x4.shared.b16 {%0,%1,%2,%3}, [%4];"
                 : "=r"(r0), "=r"(r1), "=r"(r2), "=r"(r3) : "r"(saddr));
}

extern __shared__ float smc[];

// ============================================================
// Kernel A: [f;g;h] = Wcat @ x via tf32 mma (proven mainloop).
// Epilogue: f -> fp16 [n][k] (pre-scaled log2e), g -> fp16 [m][k],
// h -> bf16 [c][m].
// grid (32 n-tiles of 128, 3 oc-tiles of 64, 8 b), 256 thr = 8 warps.
// ============================================================
#define WST 36
#define AXST 136
#define KA_WS 0
#define KA_XS (2 * 64 * WST)
#define SMEM_A_BYTES ((KA_XS + 2 * 32 * AXST) * 4)
#define LOG2E 1.4426950408889634f

__global__ __launch_bounds__(256, 3) void kA(const float* __restrict__ x,
                                             const float* __restrict__ Wf,
                                             const float* __restrict__ Wg,
                                             const float* __restrict__ Wh) {
    float* Ws = smc + KA_WS;   // 2 x [64][36]
    float* xs = smc + KA_XS;   // 2 x [32][136]
    const int b = blockIdx.z, ocb = blockIdx.y;
    const int n0 = blockIdx.x * 128;
    const int tid = threadIdx.x;
    const int w = tid >> 5, lane = tid & 31;
    const int r = lane >> 2, c = lane & 3;
    const int ms = (w & 3) * 16, nh = w >> 2;
    const float* xb = x + (size_t)b * CC * NPOS;

    float acc[8][4];
#pragma unroll
    for (int j = 0; j < 8; j++)
#pragma unroll
        for (int q = 0; q < 4; q++) acc[j][q] = 0.f;

    auto wrow = [&](int row) -> const float* {
        if (ocb == 0) return (row < 32) ? Wf + (size_t)row * 256 : Wg + (size_t)(row - 32) * 256;
        return Wh + (size_t)((ocb - 1) * 64 + row) * 256;
    };

#pragma unroll
    for (int p = 0; p < 2; p++) {
        int idx = tid + p * 256; int row = idx >> 3, cc = idx & 7;
        cpa16(&Ws[row * WST + cc * 4], wrow(row) + cc * 4);
    }
#pragma unroll
    for (int p = 0; p < 4; p++) {
        int idx = tid + p * 256; int kk = idx >> 5, cc = idx & 31;
        cpa16(&xs[kk * AXST + cc * 4], &xb[(size_t)kk * NPOS + n0 + cc * 4]);
    }
    cpcommit();
    cpwait0(); __syncthreads();

    for (int it = 0; it < 8; it++) {
        const int cur = it & 1;
        if (it + 1 < 8) {
            const int nxt = cur ^ 1, k0g = (it + 1) * 32;
            float* Wd = Ws + nxt * 64 * WST;
            float* xd = xs + nxt * 32 * AXST;
#pragma unroll
            for (int p = 0; p < 2; p++) {
                int idx = tid + p * 256; int row = idx >> 3, cc = idx & 7;
                cpa16(&Wd[row * WST + cc * 4], wrow(row) + k0g + cc * 4);
            }
#pragma unroll
            for (int p = 0; p < 4; p++) {
                int idx = tid + p * 256; int kk = idx >> 5, cc = idx & 31;
                cpa16(&xd[kk * AXST + cc * 4], &xb[(size_t)(k0g + kk) * NPOS + n0 + cc * 4]);
            }
        }
        cpcommit();

        const float* Wc = Ws + cur * 64 * WST;
        const float* xc = xs + cur * 32 * AXST;
#pragma unroll
        for (int ks = 0; ks < 4; ks++) {
            const int k0 = ks * 8;
            uint32_t a0 = __float_as_uint(Wc[(ms + r) * WST + k0 + c]);
            uint32_t a1 = __float_as_uint(Wc[(ms + r + 8) * WST + k0 + c]);
            uint32_t a2 = __float_as_uint(Wc[(ms + r) * WST + k0 + c + 4]);
            uint32_t a3 = __float_as_uint(Wc[(ms + r + 8) * WST + k0 + c + 4]);
#pragma unroll
            for (int j = 0; j < 8; j++) {
                const int nn = nh * 32 + (j & 3) * 8 + (j >> 2) * 64;
                uint32_t b0 = __float_as_uint(xc[(k0 + c) * AXST + nn + r]);
                uint32_t b1 = __float_as_uint(xc[(k0 + c + 4) * AXST + nn + r]);
                mma8(acc[j][0], acc[j][1], acc[j][2], acc[j][3], a0, a1, a2, a3, b0, b1);
            }
        }
        cpwait0(); __syncthreads();
    }

    // epilogue
    if (ocb == 0 && ms < 32) {
        // f rows: k = ms+r / ms+r+8; store fp16 [n][k], pre-scaled
        __half* fb = g_f16 + (size_t)b * NPOS * 32;
#pragma unroll
        for (int j = 0; j < 8; j++) {
            const int nn = nh * 32 + (j & 3) * 8 + (j >> 2) * 64;
            const int n = n0 + nn + 2 * c;
            fb[(size_t)n * 32 + ms + r]           = __float2half(acc[j][0] * LOG2E);
            fb[(size_t)(n + 1) * 32 + ms + r]     = __float2half(acc[j][1] * LOG2E);
            fb[(size_t)n * 32 + ms + r + 8]       = __float2half(acc[j][2] * LOG2E);
            fb[(size_t)(n + 1) * 32 + ms + r + 8] = __float2half(acc[j][3] * LOG2E);
        }
    } else {
        const int oc0 = ocb * 64 + ms + r;
#pragma unroll
        for (int j = 0; j < 4; j++) {
            float vlo = fmaxf(fmaxf(acc[j][0], acc[j][1]), fmaxf(acc[j + 4][0], acc[j + 4][1]));
            float vhi = fmaxf(fmaxf(acc[j][2], acc[j][3]), fmaxf(acc[j + 4][2], acc[j + 4][3]));
            const int pm = blockIdx.x * 32 + nh * 16 + j * 4 + c;
            if (ocb == 0) {
                // g rows: k = oc0-32; store fp16 [m][k]
                __half* gb = g_g16 + (size_t)b * MPOS * 32;
                gb[(size_t)pm * 32 + (oc0 - 32)]     = __float2half(vlo);
                gb[(size_t)pm * 32 + (oc0 - 32) + 8] = __float2half(vhi);
            } else {
                __nv_bfloat16* dst = g_hp + ((size_t)b * CHD + (oc0 - 64)) * MPOS;
                dst[pm] = __float2bfloat16(vlo);
                dst[8 * MPOS + pm] = __float2bfloat16(vhi);
            }
        }
    }
}

// ============================================================
// Kernel C2: FA2 attention + fused kD. 512 threads, n-tile 256,
// grid (16,8) = 128 blocks = 1/SM. Score via fp16 m16n8k16 with
// register-resident f A-frags; 6-slot g/h ring, 3-tile batches.
// ============================================================
#define FSTU 20    // u32 stride, fs16 rows (16 data + 4 pad)
#define GSTU16 20  // u32 stride, gs16 rows
#define CHSTU 36
#define KC_F16 0                       // fs16: 256*20  = 5120 u32
#define KC_G16 5120                    // gs16: 6*64*20 = 7680 u32
#define KC_HS16 12800                  // hs:   6*128*36 = 27648 u32
#define SMEM_C_U32 (KC_HS16 + 6 * 128 * CHSTU)   // 40448
#define SMEM_C_BYTES (SMEM_C_U32 * 4)             // 161792
#define KC_WB_U32 17408    // Wb overlays hs slots 1-2 (os = [0,17408))
#define OST2 68
#define WKST 68

__global__ __launch_bounds__(512, 1) void kC2(const float* __restrict__ x,
                                              const float* __restrict__ Wo,
                                              const float* __restrict__ gptr,
                                              float* __restrict__ out) {
    uint32_t* fs16 = (uint32_t*)smc + KC_F16;   // [256][20]
    uint32_t* gs16 = (uint32_t*)smc + KC_G16;   // 6 x [64][20]
    uint32_t* hs   = (uint32_t*)smc + KC_HS16;  // 6 x [128][36]
    uint32_t* os   = (uint32_t*)smc;            // [256][68] (kD phase)
    uint32_t* Wb   = (uint32_t*)smc + KC_WB_U32;// 2 x [64][68] (kD phase)

    const int b = blockIdx.y;
    const int n0 = blockIdx.x * 256;
    const int tid = threadIdx.x;
    const int w = tid >> 5, lane = tid & 31;
    const int r = lane >> 2, c = lane & 3;
    const int nq0 = w * 16;
    const __half* f16p = g_f16 + ((size_t)b * NPOS + n0) * 32;
    const __half* g16p = g_g16 + (size_t)b * MPOS * 32;
    const __nv_bfloat16* hp = g_hp + (size_t)b * CHD * MPOS;

    auto issue_tile = [&](int t) {
        const int slot = t % 6;
        const int m0 = t * 64;
        if (tid < 256) {
            int rr = tid >> 2, cc = tid & 3;
            cpa16(&gs16[slot * 64 * GSTU16 + rr * GSTU16 + cc * 4],
                  g16p + (size_t)(m0 + rr) * 32 + cc * 8);
        }
#pragma unroll
        for (int p = 0; p < 2; p++) {
            int idx = tid + p * 512; int rr = idx >> 3, cc = idx & 7;
            cpa16(&hs[slot * 128 * CHSTU + rr * CHSTU + cc * 4],
                  hp + (size_t)rr * MPOS + m0 + cc * 8);
        }
    };

    // prologue: fs16 (256 rows x 32 halfs) + batch 0 (tiles 0..2)
#pragma unroll
    for (int p = 0; p < 2; p++) {
        int idx = tid + p * 512; int rr = idx >> 2, cc = idx & 3;
        cpa16(&fs16[rr * FSTU + cc * 4], f16p + (size_t)rr * 32 + cc * 8);
    }
    issue_tile(0); issue_tile(1); issue_tile(2);
    cpcommit(); cpwait0(); __syncthreads();

    const int i7 = lane & 7, s2 = (lane >> 3) & 1, s4 = lane >> 4;

    // hoist f A-frags (constant across all tiles): A[n16][k32] = 2 k16 chunks
    uint32_t afA[2][4];
#pragma unroll
    for (int s = 0; s < 2; s++) {
        afA[s][0] = fs16[(nq0 + r) * FSTU + s * 8 + c];
        afA[s][1] = fs16[(nq0 + r + 8) * FSTU + s * 8 + c];
        afA[s][2] = fs16[(nq0 + r) * FSTU + s * 8 + c + 4];
        afA[s][3] = fs16[(nq0 + r + 8) * FSTU + s * 8 + c + 4];
    }

    float rs0 = 0.f, rs1 = 0.f;
    {
        float acc[16][4];
#pragma unroll
        for (int i = 0; i < 16; i++)
#pragma unroll
            for (int q = 0; q < 4; q++) acc[i][q] = 0.f;

        for (int t0 = 0; t0 < 16; t0 += 3) {
#pragma unroll
            for (int i = 3; i < 6; i++)
                if (t0 + i < 16) issue_tile(t0 + i);
            cpcommit();

#pragma unroll
            for (int ti = 0; ti < 3; ti++) {
                const int t = t0 + ti;
                if (t >= 16) break;
                const int slot = t % 6;
                const uint32_t* gsc = gs16 + slot * 64 * GSTU16;
                const uint32_t* hsc = hs + slot * 128 * CHSTU;

                // ---- score mma (fp16 k16): S'[n16][m8-groups] ----
                uint32_t af[4][4];
#pragma unroll
                for (int half = 0; half < 2; half++) {
                    float sc[4][4];
#pragma unroll
                    for (int j2 = 0; j2 < 4; j2++)
#pragma unroll
                        for (int q = 0; q < 4; q++) sc[j2][q] = 0.f;
#pragma unroll
                    for (int s = 0; s < 2; s++) {
#pragma unroll
                        for (int j2 = 0; j2 < 4; j2++) {
                            const int mof = half * 32 + j2 * 8;
                            uint32_t b0 = gsc[(mof + r) * GSTU16 + s * 8 + c];
                            uint32_t b1 = gsc[(mof + r) * GSTU16 + s * 8 + c + 4];
                            mma16f(sc[j2][0], sc[j2][1], sc[j2][2], sc[j2][3],
                                   afA[s][0], afA[s][1], afA[s][2], afA[s][3], b0, b1);
                        }
                    }
#pragma unroll
                    for (int mo2 = 0; mo2 < 2; mo2++) {
                        float e00 = ex2f(sc[2 * mo2][0]),     e01 = ex2f(sc[2 * mo2][1]);
                        float e02 = ex2f(sc[2 * mo2][2]),     e03 = ex2f(sc[2 * mo2][3]);
                        float e10 = ex2f(sc[2 * mo2 + 1][0]), e11 = ex2f(sc[2 * mo2 + 1][1]);
                        float e12 = ex2f(sc[2 * mo2 + 1][2]), e13 = ex2f(sc[2 * mo2 + 1][3]);
                        __nv_bfloat162 p0 = __floats2bfloat162_rn(e00, e01);
                        __nv_bfloat162 p1 = __floats2bfloat162_rn(e02, e03);
                        __nv_bfloat162 p2 = __floats2bfloat162_rn(e10, e11);
                        __nv_bfloat162 p3 = __floats2bfloat162_rn(e12, e13);
                        const int mo = half * 2 + mo2;
                        af[mo][0] = *(uint32_t*)&p0;
                        af[mo][1] = *(uint32_t*)&p1;
                        af[mo][2] = *(uint32_t*)&p2;
                        af[mo][3] = *(uint32_t*)&p3;
                        rs0 += (e00 + e01) + (e10 + e11);
                        rs1 += (e02 + e03) + (e12 + e13);
                    }
                }

                // ---- o-mma (bf16 k16): o^T[n16][c128] += P * h ----
                {
                    const uint32_t hs_sb = (uint32_t)__cvta_generic_to_shared(hsc);
#pragma unroll
                    for (int mo = 0; mo < 4; mo++) {
#pragma unroll
                        for (int cg = 0; cg < 8; cg++) {
                            uint32_t b0, b1, b2, b3;
                            ldm4(b0, b1, b2, b3,
                                 hs_sb + (uint32_t)(((cg * 16 + s4 * 8 + i7) * CHSTU + s2 * 4 + mo * 8) * 4));
                            mma16b(acc[2 * cg][0], acc[2 * cg][1], acc[2 * cg][2], acc[2 * cg][3],
                                   af[mo][0], af[mo][1], af[mo][2], af[mo][3], b0, b1);
                            mma16b(acc[2 * cg + 1][0], acc[2 * cg + 1][1], acc[2 * cg + 1][2], acc[2 * cg + 1][3],
                                   af[mo][0], af[mo][1], af[mo][2], af[mo][3], b2, b3);
                        }
                    }
                }
            }
            cpwait0();
            __syncthreads();
        }

        // ---- rowsum: warp-local xor reduce over the 4 c-lanes ----
#pragma unroll
        for (int off = 1; off < 4; off <<= 1) {
            rs0 += __shfl_xor_sync(0xffffffffu, rs0, off);
            rs1 += __shfl_xor_sync(0xffffffffu, rs1, off);
        }
        const float inv0 = 1.f / rs0, inv1 = 1.f / rs1;

        // ---- normalize + store o^T bf16 [n][c] into SMEM (os) ----
#pragma unroll
        for (int tt = 0; tt < 16; tt++) {
            __nv_bfloat162 v0 = __floats2bfloat162_rn(acc[tt][0] * inv0, acc[tt][1] * inv0);
            __nv_bfloat162 v1 = __floats2bfloat162_rn(acc[tt][2] * inv1, acc[tt][3] * inv1);
            os[(nq0 + r) * OST2 + tt * 4 + c]     = *(uint32_t*)&v0;
            os[(nq0 + r + 8) * OST2 + tt * 4 + c] = *(uint32_t*)&v1;
        }
    }

    // ================= fused kD phase (Wb double-buffered) =================
    const float gamma = *gptr;
    const int ms = (w & 3) * 16, nh = w >> 2;
    const uint32_t o_sb = (uint32_t)__cvta_generic_to_shared(os);
    const uint32_t wb_sb = (uint32_t)__cvta_generic_to_shared(Wb);
    const uint32_t a_off = (uint32_t)((ms + s2 * 8 + i7) * WKST + s4 * 4);
    const uint32_t b_off = (uint32_t)((nh * 64 + s4 * 8 + i7) * OST2 + s2 * 4);
    const float* xb = x + (size_t)b * CC * NPOS;
    float* outb = out + (size_t)b * CC * NPOS;

#pragma unroll
    for (int p = 0; p < 4; p++) {
        int idx = tid + p * 512; int row = idx >> 5, cc = idx & 31;
        float4 v = *(const float4*)&Wo[(size_t)row * CHD + cc * 4];
        __nv_bfloat162 lo = __floats2bfloat162_rn(v.x, v.y);
        __nv_bfloat162 hi = __floats2bfloat162_rn(v.z, v.w);
        Wb[row * WKST + cc * 2]     = *(uint32_t*)&lo;
        Wb[row * WKST + cc * 2 + 1] = *(uint32_t*)&hi;
    }
    __syncthreads();   // os + Wb[0] visible

    for (int pass = 0; pass < 4; pass++) {
        const uint32_t w_sb = wb_sb + (uint32_t)((pass & 1) * 64 * WKST * 4);
        float acc[8][4];
#pragma unroll
        for (int j = 0; j < 8; j++)
#pragma unroll
            for (int q = 0; q < 4; q++) acc[j][q] = 0.f;

#pragma unroll
        for (int s = 0; s < 8; s++) {
            uint32_t a0, a1, a2, a3;
            ldm4(a0, a1, a2, a3, w_sb + (a_off + s * 8) * 4);
#pragma unroll
            for (int jp = 0; jp < 4; jp++) {
                uint32_t b0, b1, b2, b3;
                ldm4(b0, b1, b2, b3, o_sb + (b_off + jp * 16 * OST2 + s * 8) * 4);
                mma16b(acc[2 * jp][0], acc[2 * jp][1], acc[2 * jp][2], acc[2 * jp][3],
                       a0, a1, a2, a3, b0, b1);
                mma16b(acc[2 * jp + 1][0], acc[2 * jp + 1][1], acc[2 * jp + 1][2], acc[2 * jp + 1][3],
                       a0, a1, a2, a3, b2, b3);
            }
        }

        if (pass < 3) {
            uint32_t* Wn = Wb + ((pass + 1) & 1) * 64 * WKST;
#pragma unroll
            for (int p = 0; p < 4; p++) {
                int idx = tid + p * 512; int row = idx >> 5, cc = idx & 31;
                float4 v = *(const float4*)&Wo[(size_t)((pass + 1) * 64 + row) * CHD + cc * 4];
                __nv_bfloat162 lo = __floats2bfloat162_rn(v.x, v.y);
                __nv_bfloat162 hi = __floats2bfloat162_rn(v.z, v.w);
                Wn[row * WKST + cc * 2]     = *(uint32_t*)&lo;
                Wn[row * WKST + cc * 2 + 1] = *(uint32_t*)&hi;
            }
        }

        const int oc0 = pass * 64 + ms + r;
#pragma unroll
        for (int j = 0; j < 8; j++) {
            const int n = n0 + nh * 64 + j * 8 + 2 * c;
            size_t p0 = (size_t)oc0 * NPOS + n;
            size_t p1 = (size_t)(oc0 + 8) * NPOS + n;
            float2 x0 = *(const float2*)&xb[p0];
            float2 x1 = *(const float2*)&xb[p1];
            *(float2*)&outb[p0] = make_float2(fmaf(gamma, acc[j][0], x0.x),
                                              fmaf(gamma, acc[j][1], x0.y));
            *(float2*)&outb[p1] = make_float2(fmaf(gamma, acc[j][2], x1.x),
                                              fmaf(gamma, acc[j][3], x1.y));
        }

        if (pass < 3) __syncthreads();
    }
}

// ============================================================
extern "C" void kernel_launch(void* const* d_in, const int* in_sizes, int n_in,
                              void* d_out, int out_size) {
    const float* x     = (const float*)d_in[0];
    const float* Wf    = (const float*)d_in[1];
    const float* Wg    = (const float*)d_in[2];
    const float* Wh    = (const float*)d_in[3];
    const float* Wo    = (const float*)d_in[4];
    const float* gamma = (const float*)d_in[5];
    float* out = (float*)d_out;

    cudaFuncSetAttribute(kA, cudaFuncAttributeMaxDynamicSharedMemorySize, SMEM_A_BYTES);
    cudaFuncSetAttribute(kC2, cudaFuncAttributeMaxDynamicSharedMemorySize, SMEM_C_BYTES);

    kA<<<dim3(32, 3, 8), 256, SMEM_A_BYTES>>>(x, Wf, Wg, Wh);
    kC2<<<dim3(16, 8), 512, SMEM_C_BYTES>>>(x, Wo, gamma, out);
}